// round 10
// baseline (speedup 1.0000x reference)
#include <cuda_runtime.h>
#include <math.h>

#define NB 8
#define NC 64
#define NG 4
#define CG 16
#define NH 128
#define NW 128
#define HW (NH*NW)
#define IMG (NB*NC*HW)
#define NROW (NB*NH)

typedef unsigned long long u64;

__device__ __forceinline__ u64 f2dup(float v) {
  u64 r; asm("mov.b64 %0, {%1, %1};" : "=l"(r) : "f"(v)); return r;
}
__device__ __forceinline__ u64 f2pk(float a, float b) {
  u64 r; asm("mov.b64 %0, {%1, %2};" : "=l"(r) : "f"(a), "f"(b)); return r;
}
__device__ __forceinline__ void fma2(u64& d, u64 a, u64 b) {
  asm("fma.rn.f32x2 %0, %1, %2, %0;" : "+l"(d) : "l"(a), "l"(b));
}
__device__ __forceinline__ float2 f2up(u64 v) {
  float2 f; asm("mov.b64 {%0, %1}, %2;" : "=f"(f.x), "=f"(f.y) : "l"(v)); return f;
}
__device__ __forceinline__ unsigned cvt_tf32(float x) {
  unsigned r; asm("cvt.rna.tf32.f32 %0, %1;" : "=r"(r) : "f"(x)); return r;
}
__device__ __forceinline__ void mma_tf32(
    float& d0, float& d1, float& d2, float& d3,
    unsigned a0, unsigned a1, unsigned a2, unsigned a3,
    unsigned b0, unsigned b1) {
  asm volatile(
    "mma.sync.aligned.m16n8k8.row.col.f32.tf32.tf32.f32 "
    "{%0,%1,%2,%3}, {%4,%5,%6,%7}, {%8,%9}, {%0,%1,%2,%3};"
    : "+f"(d0), "+f"(d1), "+f"(d2), "+f"(d3)
    : "r"(a0), "r"(a1), "r"(a2), "r"(a3), "r"(b0), "r"(b1));
}

// ---------------- scratch ----------------------------------------------------
__device__ float g_t1[2*(size_t)IMG];
__device__ float g_t2[2*(size_t)IMG];
__device__ float g_bnA[2][NC];
__device__ float g_bnB[2][NC];
__device__ __align__(16) float g_wt[2][NG*CG*CG*9];

// ---------------- BN statistics ----------------------------------------------
__global__ __launch_bounds__(256) void bn_stats_kernel(
    const float* __restrict__ xl, const float* __restrict__ xr,
    const float* __restrict__ gamma, const float* __restrict__ beta) {
  int c = blockIdx.x & 63;
  int img = blockIdx.x >> 6;
  const float4* x = (const float4*)(img ? xr : xl);
  int t = threadIdx.x;
  float s = 0.f, s2 = 0.f;
  for (int b = 0; b < NB; b++) {
    const float4* p = x + (size_t)(b*NC + c)*(HW/4);
    for (int i = t; i < HW/4; i += 256) {
      float4 v = p[i];
      s  += v.x + v.y + v.z + v.w;
      s2 += v.x*v.x + v.y*v.y + v.z*v.z + v.w*v.w;
    }
  }
  __shared__ float sh[256], sh2[256];
  sh[t] = s; sh2[t] = s2; __syncthreads();
  for (int off = 128; off; off >>= 1) {
    if (t < off) { sh[t] += sh[t+off]; sh2[t] += sh2[t+off]; }
    __syncthreads();
  }
  if (t == 0) {
    const float inv = 1.f / (float)(NB*HW);
    float mean = sh[0] * inv;
    float var  = sh2[0] * inv - mean*mean;
    float a = gamma[c] * rsqrtf(var + 1e-5f);
    g_bnA[img][c] = a;
    g_bnB[img][c] = beta[c] - mean * a;
  }
}

// ---------------- weight transpose -------------------------------------------
__global__ __launch_bounds__(256) void wtrans_kernel(
    const float* __restrict__ w1, const float* __restrict__ w2) {
  int i = blockIdx.x * 256 + threadIdx.x;
  if (i >= 2*NG*CG*CG*9) return;
  int layer = i >= NG*CG*CG*9;
  int j = layer ? i - NG*CG*CG*9 : i;
  int g = j / (CG*CG*9);
  int r = j - g*(CG*CG*9);
  int oc = r & 15;
  int rest = r >> 4;
  const float* src = layer ? w2 : w1;
  g_wt[layer][j] = src[g*CG*CG*9 + oc*CG*9 + rest];
}

// ---------------- grouped 3x3 conv (R9, kept) --------------------------------
#define IN_ST 132
#define CONV_SMEM (CG*6*IN_ST*4)

template<bool FIRST>
__global__ __launch_bounds__(256, 4) void conv3x3_kernel(
    const float* __restrict__ xL, const float* __restrict__ xR,
    float* __restrict__ t1, float* __restrict__ t2,
    const float* __restrict__ wt, const float* __restrict__ bias) {
  extern __shared__ float sm[];
  float* in_s = sm;
  int t = threadIdx.x;
  int img = blockIdx.z;
  int b = blockIdx.y >> 2, g = blockIdx.y & 3;
  int h0 = blockIdx.x * 4;
  const float* xorig = img ? xR : xL;
  const float* xin = FIRST ? xorig : (t1 + (size_t)img*IMG);
  float* out = (FIRST ? t1 : t2) + (size_t)img*IMG;

  for (int i = t; i < CG*6*IN_ST; i += 256) {
    int ic  = i / (6*IN_ST);
    int rem = i - ic*(6*IN_ST);
    int r   = rem / IN_ST;
    int wc  = rem - r*IN_ST;
    int hh  = h0 - 1 + r;
    int ww  = wc - 1;
    float v = 0.f;
    if ((unsigned)hh < (unsigned)NH && (unsigned)ww < (unsigned)NW) {
      v = xin[((size_t)(b*NC + g*CG + ic)*NH + hh)*NW + ww];
      if (FIRST) v = g_bnA[img][g*CG+ic]*v + g_bnB[img][g*CG+ic];
    }
    in_s[i] = v;
  }
  __syncthreads();

  int wseg = t & 31, hh2 = (t >> 5) & 3, ocq = t >> 7;
  int w0 = wseg * 4, oc0 = ocq * 8;
  const float* wg = wt + g*(CG*CG*9) + oc0;

  u64 acc2[4][4];
  #pragma unroll
  for (int p = 0; p < 4; p++) {
    u64 bz = f2pk(bias[g*CG+oc0+2*p], bias[g*CG+oc0+2*p+1]);
    #pragma unroll
    for (int j = 0; j < 4; j++) acc2[p][j] = bz;
  }

  for (int ic = 0; ic < CG; ic++) {
    #pragma unroll
    for (int kh = 0; kh < 3; kh++) {
      const float* row = in_s + (ic*6 + hh2 + kh)*IN_ST + w0;
      float4 A  = *(const float4*)row;
      float2 C2 = *(const float2*)(row + 4);
      u64 ind[6];
      ind[0]=f2dup(A.x); ind[1]=f2dup(A.y); ind[2]=f2dup(A.z);
      ind[3]=f2dup(A.w); ind[4]=f2dup(C2.x); ind[5]=f2dup(C2.y);
      const float* wb0 = wg + (ic*3 + kh)*48;
      #pragma unroll
      for (int kw = 0; kw < 3; kw++) {
        ulonglong2 wA = __ldg((const ulonglong2*)(wb0 + kw*16));
        ulonglong2 wB = __ldg((const ulonglong2*)(wb0 + kw*16 + 4));
        #pragma unroll
        for (int j = 0; j < 4; j++) {
          fma2(acc2[0][j], ind[kw+j], wA.x);
          fma2(acc2[1][j], ind[kw+j], wA.y);
          fma2(acc2[2][j], ind[kw+j], wB.x);
          fma2(acc2[3][j], ind[kw+j], wB.y);
        }
      }
    }
  }

  int hout = h0 + hh2;
  #pragma unroll
  for (int o = 0; o < 8; o++) {
    int ch = g*CG + oc0 + o;
    size_t idx = ((size_t)(b*NC + ch)*NH + hout)*NW + w0;
    float r[4];
    #pragma unroll
    for (int j = 0; j < 4; j++) {
      float2 f = f2up(acc2[o>>1][j]);
      r[j] = (o & 1) ? f.y : f.x;
    }
    if (FIRST) {
      #pragma unroll
      for (int j = 0; j < 4; j++) r[j] = r[j] > 0.f ? r[j] : 0.1f*r[j];
    } else {
      float ra = g_bnA[img][ch], rb = g_bnB[img][ch];
      float4 x0 = *(const float4*)&xorig[idx];
      float xs[4] = {x0.x,x0.y,x0.z,x0.w};
      #pragma unroll
      for (int j = 0; j < 4; j++) r[j] = r[j] + ra*xs[j] + rb;
    }
    *(float4*)&out[idx] = make_float4(r[0],r[1],r[2],r[3]);
  }
}

// ---------------- fused attention: tf32 mma GEMM1 ----------------------------
#define ST 128     // A' stride
#define AST 132    // hi/lo stride
#define SST 132    // S stride
#define XST 68
#define OFF_AHI  0
#define OFF_ALO  16896
#define OFF_T2   16896
#define OFF_S    33792
#define OFF_WS   33792
#define OFF_BS2  35840
#define OFF_XLS  16896
#define OFF_XRS  25600
#define OFF_HP   51200
#define OFF_DH   52736
#define OFF_PART 53120
#define OFF_RMAX 55168
#define OFF_RSC  55296
#define OFF_CMAX 55424
#define OFF_GCC  55552
#define OFF_VL   55680
#define OFF_VR   55808
#define OFF_FR   55936
#define OFF_GC   56064
#define OFF_MG   56192
#define ATTN_SMEM ((56192 + 32)*4)   // 224896 B

__global__ __launch_bounds__(1024, 1) void attn_kernel(
    const float* __restrict__ t2, const float* __restrict__ xL,
    const float* __restrict__ xR,
    const float* __restrict__ qw, const float* __restrict__ qb,
    const float* __restrict__ kw_, const float* __restrict__ kb,
    float* __restrict__ outL, float* __restrict__ outR) {
  extern __shared__ float sm[];
  float* Qf    = sm + OFF_AHI;     // fp32 Q/K -> hi (tf32) -> A'
  float* Lo    = sm + OFF_ALO;     // lo (tf32)
  float* t2s   = sm + OFF_T2;
  float* Sb    = sm + OFF_S;
  float* ws    = sm + OFF_WS;
  float* bs    = sm + OFF_BS2;
  float* xls   = sm + OFF_XLS;
  float* xrs   = sm + OFF_XRS;
  float* HP    = sm + OFF_HP;
  float* Dh    = sm + OFF_DH;
  float* part  = sm + OFF_PART;
  float* rmax  = sm + OFF_RMAX;
  float* rsc   = sm + OFF_RSC;
  float* cmax  = sm + OFF_CMAX;
  float* gcc   = sm + OFF_GCC;
  float* Vl    = sm + OFF_VL;
  float* Vr    = sm + OFF_VR;
  float* fr    = sm + OFF_FR;
  float* gc    = sm + OFF_GC;
  float* Mg    = sm + OFF_MG;
  int n = blockIdx.x, b = n >> 7, h = n & 127;
  int t = threadIdx.x, warp = t >> 5, lane = t & 31;

  // 1. stage weights/bias (S region, dead now) + t2 rows (Lo region)
  for (int i = t; i < 2048; i += 1024) ws[i] = (i < 1024) ? qw[i] : kw_[i-1024];
  if (t < 128) bs[t] = (t < 64) ? qb[t] : kb[t-64];
  for (int i = t; i < 16384; i += 1024) {
    int c = i >> 7, u = i & 127;
    size_t gi = ((c >= 64) ? (size_t)IMG : 0) +
                ((size_t)(b*NC + (c & 63))*NH + h)*NW + u;
    t2s[c*128 + u] = t2[gi];
  }
  __syncthreads();

  // 2. 1x1 grouped conv: Qf[k][u] fp32, stride 132
  for (int i = t; i < 8192; i += 1024) {
    int k = i >> 6, up = (i & 63)*2;
    int cb = (k >> 4) * 16;
    float bzv = bs[k];
    u64 a = f2pk(bzv, bzv);
    #pragma unroll
    for (int ic = 0; ic < 16; ic++) {
      u64 w2 = f2dup(ws[k*16 + ic]);
      u64 xp = *(const u64*)&t2s[(cb + ic)*128 + up];
      fma2(a, w2, xp);
    }
    *(u64*)&Qf[k*AST + up] = a;
  }
  __syncthreads();

  // 3. row-mean subtract
  for (int r = warp; r < 128; r += 32) {
    float s = 0.f;
    for (int u = lane; u < 128; u += 32) s += Qf[r*AST + u];
    #pragma unroll
    for (int off = 16; off; off >>= 1) s += __shfl_xor_sync(0xffffffffu, s, off);
    float mean = s * (1.f/128.f);
    for (int u = lane; u < 128; u += 32) Qf[r*AST + u] -= mean;
  }
  __syncthreads();

  // 4. split hi/lo (tf32)
  for (int i = t; i < 16384; i += 1024) {
    int r = i >> 7, c = i & 127;
    int idx = r*AST + c;
    float x = Qf[idx];
    unsigned hbits = cvt_tf32(x);
    float lof = x - __uint_as_float(hbits);
    unsigned lbits = cvt_tf32(lof);
    ((unsigned*)Qf)[idx] = hbits;
    ((unsigned*)Lo)[idx] = lbits;
  }
  __syncthreads();

  // 5. GEMM1 via 3xTF32 mma: S[u][v] = sum_k Q[k][u]K[k][v]
  {
    int g = lane >> 2, tig = lane & 3;
    int u0 = (warp >> 2) * 16;
    int v0 = (warp & 3) * 32;
    const unsigned* Hu = (const unsigned*)Qf;
    const unsigned* Lu = (const unsigned*)Lo;
    float d[4][4];
    #pragma unroll
    for (int nt = 0; nt < 4; nt++)
      d[nt][0] = d[nt][1] = d[nt][2] = d[nt][3] = 0.f;
    #pragma unroll
    for (int ks = 0; ks < 8; ks++) {
      int rowA = (ks*8 + tig)*AST;
      unsigned ah0 = Hu[rowA + u0 + g];
      unsigned ah1 = Hu[rowA + u0 + g + 8];
      unsigned ah2 = Hu[rowA + 4*AST + u0 + g];
      unsigned ah3 = Hu[rowA + 4*AST + u0 + g + 8];
      unsigned al0 = Lu[rowA + u0 + g];
      unsigned al1 = Lu[rowA + u0 + g + 8];
      unsigned al2 = Lu[rowA + 4*AST + u0 + g];
      unsigned al3 = Lu[rowA + 4*AST + u0 + g + 8];
      int rowB = rowA + 64*AST;
      #pragma unroll
      for (int nt = 0; nt < 4; nt++) {
        int vc = v0 + nt*8 + g;
        unsigned bh0 = Hu[rowB + vc];
        unsigned bh1 = Hu[rowB + 4*AST + vc];
        unsigned bl0 = Lu[rowB + vc];
        unsigned bl1 = Lu[rowB + 4*AST + vc];
        mma_tf32(d[nt][0],d[nt][1],d[nt][2],d[nt][3], al0,al1,al2,al3, bh0,bh1);
        mma_tf32(d[nt][0],d[nt][1],d[nt][2],d[nt][3], ah0,ah1,ah2,ah3, bl0,bl1);
        mma_tf32(d[nt][0],d[nt][1],d[nt][2],d[nt][3], ah0,ah1,ah2,ah3, bh0,bh1);
      }
    }
    #pragma unroll
    for (int nt = 0; nt < 4; nt++) {
      int col = v0 + nt*8 + 2*tig;
      *(float2*)&Sb[(u0+g)*SST + col]     = make_float2(d[nt][0], d[nt][1]);
      *(float2*)&Sb[(u0+g+8)*SST + col]   = make_float2(d[nt][2], d[nt][3]);
    }
  }
  __syncthreads();

  // 6. max scans on S
  if (warp < 16) {
    for (int r = warp*8; r < warp*8 + 8; r++) {
      float m = -1e30f;
      #pragma unroll
      for (int j = 0; j < 4; j++) m = fmaxf(m, Sb[r*SST + lane + j*32]);
      #pragma unroll
      for (int off = 16; off; off >>= 1) m = fmaxf(m, __shfl_xor_sync(0xffffffffu, m, off));
      if (lane == 0) rmax[r] = m;
    }
  } else {
    int j = warp - 16;
    int c = (j & 3)*32 + lane;
    int r0 = (j >> 2)*32;
    float m = -1e30f;
    for (int r = r0; r < r0 + 32; r++) m = fmaxf(m, Sb[r*SST + c]);
    part[(j >> 2)*128 + c] = m;
  }
  __syncthreads();

  // 7. cmax combine + global max + factors
  if (t < 128) {
    cmax[t] = fmaxf(fmaxf(part[t], part[128+t]), fmaxf(part[256+t], part[384+t]));
  } else if (t < 160) {
    int l = t - 128;
    float m = fmaxf(fmaxf(rmax[l], rmax[l+32]), fmaxf(rmax[l+64], rmax[l+96]));
    #pragma unroll
    for (int off = 16; off; off >>= 1) m = fmaxf(m, __shfl_xor_sync(0xffffffffu, m, off));
    if (l == 0) Mg[0] = m;
  }
  __syncthreads();
  if (t < 128) {
    float M = Mg[0];
    fr[t] = __expf(rmax[t] - M);
    gc[t] = __expf(M - cmax[t]);
  }
  __syncthreads();

  // 8. exp (warps 0-15): A'[r*128+c] = exp(S-M); warps 16-31: stage xls
  if (warp < 16) {
    float gcv[4];
    #pragma unroll
    for (int k = 0; k < 4; k++) gcv[k] = gc[lane + k*32];
    float csump[4] = {0.f, 0.f, 0.f, 0.f};
    for (int rr = 0; rr < 8; rr++) {
      int r = warp*8 + rr;
      float rm = rmax[r];
      float frv = fr[r];
      float rs = 0.f;
      #pragma unroll
      for (int k = 0; k < 4; k++) {
        int c = lane + k*32;
        float e = __expf(Sb[r*SST + c] - rm);
        float ap = e * frv;
        Qf[r*ST + c] = ap;           // A'
        rs += e;
        csump[k] += ap * gcv[k];
      }
      #pragma unroll
      for (int off = 16; off; off >>= 1) rs += __shfl_xor_sync(0xffffffffu, rs, off);
      if (lane == 0) rsc[r] = 1.f / rs;
    }
    #pragma unroll
    for (int k = 0; k < 4; k++) part[warp*128 + k*32 + lane] = csump[k];
  } else {
    for (int i = t - 512; i < 8192; i += 512) {
      int c = i >> 7, v = i & 127;
      xls[v*XST + c] = xL[((size_t)(b*NC + c)*NH + h)*NW + v];
    }
  }
  __syncthreads();

  // 9. csum combine
  if (t < 128) {
    float s = 0.f;
    #pragma unroll
    for (int w = 0; w < 16; w++) s += part[w*128 + t];
    gcc[t] = gc[t] / s;
    rsc[t] = __fdividef(rsc[t], fr[t]);
  }
  __syncthreads();

  // 10. stage xrs (S dead) + banded Grams of A'
  for (int i = t; i < 8192; i += 1024) {
    int c = i >> 7, v = i & 127;
    xrs[v*XST + c] = xR[((size_t)(b*NC + c)*NH + h)*NW + v];
  }
  if (warp < 16) {                    // G bands -> part[0..383]
    int a0 = warp * 8;
    float acc0[8], acc1[8], acc2g[8];
    #pragma unroll
    for (int i = 0; i < 8; i++) { acc0[i]=0.f; acc1[i]=0.f; acc2g[i]=0.f; }
    #pragma unroll
    for (int vj = 0; vj < 4; vj++) {
      int v = lane + vj*32;
      float w = gcc[v];
      float e[10];
      #pragma unroll
      for (int i = 0; i < 10; i++) e[i] = (a0+i < 128) ? Qf[(a0+i)*ST + v] : 0.f;
      #pragma unroll
      for (int i = 0; i < 8; i++) {
        float ew = e[i]*w;
        acc0[i] += ew*e[i];
        acc1[i] += ew*e[i+1];
        acc2g[i] += ew*e[i+2];
      }
    }
    #pragma unroll
    for (int i = 0; i < 8; i++) {
      #pragma unroll
      for (int off = 16; off; off >>= 1) {
        acc0[i]  += __shfl_xor_sync(0xffffffffu, acc0[i],  off);
        acc1[i]  += __shfl_xor_sync(0xffffffffu, acc1[i],  off);
        acc2g[i] += __shfl_xor_sync(0xffffffffu, acc2g[i], off);
      }
      if (lane == 0) {
        part[a0+i]       = acc0[i];
        part[128 + a0+i] = acc1[i];
        part[256 + a0+i] = acc2g[i];
      }
    }
  } else {                            // H bands -> HP
    int idx = warp - 16, cb = idx & 3, vc = idx >> 2;
    int c = cb*32 + lane;
    float h0 = 0.f, h1 = 0.f, h2 = 0.f;
    for (int v = vc*32; v < vc*32 + 32; v++) {
      float e = Qf[v*ST + c];
      float e1 = __shfl_down_sync(0xffffffffu, e, 1);
      float e2 = __shfl_down_sync(0xffffffffu, e, 2);
      if (lane >= 30) e2 = (c+2 < 128) ? Qf[v*ST + c + 2] : 0.f;
      if (lane == 31) e1 = (c+1 < 128) ? Qf[v*ST + c + 1] : 0.f;
      float ew = e * rsc[v];
      h0 += ew*e; h1 += ew*e1; h2 += ew*e2;
    }
    HP[vc*384 + c]       = h0;
    HP[vc*384 + 128 + c] = h1;
    HP[vc*384 + 256 + c] = h2;
  }
  __syncthreads();

  // 11. Dh combine + V_left
  if (t < 384) {
    Dh[t] = HP[t] + HP[384+t] + HP[768+t] + HP[1152+t];
  } else if (t >= 512 && t < 640) {
    int u = t - 512;
    float accL = rsc[u]*part[u];
    if (u+1 < 128) accL += rsc[u+1]*part[128+u];
    if (u+2 < 128) accL += rsc[u+2]*part[256+u];
    if (u >= 1)    accL += rsc[u-1]*part[128+u-1];
    if (u >= 2)    accL += rsc[u-2]*part[256+u-2];
    Vl[u] = tanhf(5.f*accL);
  }
  __syncthreads();
  if (t < 128) {
    int u = t;
    float accR = gcc[u]*Dh[u];
    if (u+1 < 128) accR += gcc[u+1]*Dh[128+u];
    if (u+2 < 128) accR += gcc[u+2]*Dh[256+u];
    if (u >= 1)    accR += gcc[u-1]*Dh[128+u-1];
    if (u >= 2)    accR += gcc[u-2]*Dh[256+u-2];
    Vr[u] = tanhf(5.f*accR);
  }

  // 12. GEMM2 (g0): xlT = rsc[u]*A'[u][:]*xr; GEMM3 (g1): xrT = gcc[u]*A'[:,u]*xl
  int group = t >> 9;
  int tid = t & 511;
  int c0 = (tid & 15)*4, u0 = (tid >> 4)*4;
  u64 acc2[4][2];
  #pragma unroll
  for (int i = 0; i < 4; i++) { acc2[i][0] = 0ull; acc2[i][1] = 0ull; }

  if (group == 0) {
    for (int v0g = 0; v0g < 128; v0g += 4) {
      ulonglong2 x0 = *(const ulonglong2*)&xrs[(v0g+0)*XST + c0];
      ulonglong2 x1 = *(const ulonglong2*)&xrs[(v0g+1)*XST + c0];
      ulonglong2 x2 = *(const ulonglong2*)&xrs[(v0g+2)*XST + c0];
      ulonglong2 x3 = *(const ulonglong2*)&xrs[(v0g+3)*XST + c0];
      #pragma unroll
      for (int i = 0; i < 4; i++) {
        float4 m = *(const float4*)&Qf[(u0+i)*ST + v0g];
        u64 m0 = f2dup(m.x), m1 = f2dup(m.y), m2 = f2dup(m.z), m3 = f2dup(m.w);
        fma2(acc2[i][0], m0, x0.x); fma2(acc2[i][1], m0, x0.y);
        fma2(acc2[i][0], m1, x1.x); fma2(acc2[i][1], m1, x1.y);
        fma2(acc2[i][0], m2, x2.x); fma2(acc2[i][1], m2, x2.y);
        fma2(acc2[i][0], m3, x3.x); fma2(acc2[i][1], m3, x3.y);
      }
    }
  } else {
    for (int v = 0; v < 128; v++) {
      ulonglong2 xp = *(const ulonglong2*)&xls[v*XST + c0];
      float4 b0 = *(const float4*)&Qf[v*ST + u0];
      u64 b0d = f2dup(b0.x), b1d = f2dup(b0.y), b2d = f2dup(b0.z), b3d = f2dup(b0.w);
      fma2(acc2[0][0], b0d, xp.x); fma2(acc2[0][1], b0d, xp.y);
      fma2(acc2[1][0], b1d, xp.x); fma2(acc2[1][1], b1d, xp.y);
      fma2(acc2[2][0], b2d, xp.x); fma2(acc2[2][1], b2d, xp.y);
      fma2(acc2[3][0], b3d, xp.x); fma2(acc2[3][1], b3d, xp.y);
    }
  }
  __syncthreads();

  // 13. blend in place
  if (group == 0) {
    #pragma unroll
    for (int i = 0; i < 4; i++) {
      int u = u0 + i;
      float vl = Vl[u];
      float gsc = vl * rsc[u];
      float2 f0 = f2up(acc2[i][0]), f1 = f2up(acc2[i][1]);
      float xt[4] = {f0.x, f0.y, f1.x, f1.y};
      #pragma unroll
      for (int cc = 0; cc < 4; cc++) {
        int x = u*XST + c0 + cc;
        xls[x] = xls[x]*(1.f - vl) + xt[cc]*gsc;
      }
    }
  } else {
    #pragma unroll
    for (int i = 0; i < 4; i++) {
      int u = u0 + i;
      float vr = Vr[u];
      float gsc = vr * gcc[u];
      float2 f0 = f2up(acc2[i][0]), f1 = f2up(acc2[i][1]);
      float xt[4] = {f0.x, f0.y, f1.x, f1.y};
      #pragma unroll
      for (int cc = 0; cc < 4; cc++) {
        int x = u*XST + c0 + cc;
        xrs[x] = xrs[x]*(1.f - vr) + xt[cc]*gsc;
      }
    }
  }
  __syncthreads();

  // 14. output
  for (int i = t; i < 8192; i += 1024) {
    int c = i >> 7, u = i & 127;
    size_t gi = ((size_t)(b*NC + c)*NH + h)*NW + u;
    outL[gi] = xls[u*XST + c];
    outR[gi] = xrs[u*XST + c];
  }
}

// ---------------- host ------------------------------------------------------
extern "C" void kernel_launch(void* const* d_in, const int* in_sizes, int n_in,
                              void* d_out, int out_size) {
  const float* xL    = (const float*)d_in[0];
  const float* xR    = (const float*)d_in[1];
  const float* gamma = (const float*)d_in[2];
  const float* beta  = (const float*)d_in[3];
  const float* w1    = (const float*)d_in[4];
  const float* b1    = (const float*)d_in[5];
  const float* w2    = (const float*)d_in[6];
  const float* b2    = (const float*)d_in[7];
  const float* qw    = (const float*)d_in[8];
  const float* qb    = (const float*)d_in[9];
  const float* kw    = (const float*)d_in[10];
  const float* kb    = (const float*)d_in[11];
  float* outL = (float*)d_out;
  float* outR = outL + (size_t)IMG;

  float *t1, *t2, *wt;
  cudaGetSymbolAddress((void**)&t1, g_t1);
  cudaGetSymbolAddress((void**)&t2, g_t2);
  cudaGetSymbolAddress((void**)&wt, g_wt);

  cudaFuncSetAttribute(conv3x3_kernel<true>,  cudaFuncAttributeMaxDynamicSharedMemorySize, CONV_SMEM);
  cudaFuncSetAttribute(conv3x3_kernel<false>, cudaFuncAttributeMaxDynamicSharedMemorySize, CONV_SMEM);
  cudaFuncSetAttribute(attn_kernel, cudaFuncAttributeMaxDynamicSharedMemorySize, ATTN_SMEM);

  bn_stats_kernel<<<128, 256>>>(xL, xR, gamma, beta);
  wtrans_kernel<<<(2*NG*CG*CG*9 + 255)/256, 256>>>(w1, w2);

  dim3 cgrid(NH/4, NB*NG, 2);
  conv3x3_kernel<true ><<<cgrid, 256, CONV_SMEM>>>(xL, xR, t1, t2, wt, b1);
  conv3x3_kernel<false><<<cgrid, 256, CONV_SMEM>>>(xL, xR, t1, t2, wt + NG*CG*CG*9, b2);

  attn_kernel<<<NROW, 1024, ATTN_SMEM>>>(t2, xL, xR, qw, qb, kw, kb, outL, outR);
}

// round 11
// speedup vs baseline: 1.0713x; 1.0713x over previous
#include <cuda_runtime.h>
#include <math.h>

#define NB 8
#define NC 64
#define NG 4
#define CG 16
#define NH 128
#define NW 128
#define HW (NH*NW)
#define IMG (NB*NC*HW)
#define NROW (NB*NH)

typedef unsigned long long u64;

__device__ __forceinline__ u64 f2dup(float v) {
  u64 r; asm("mov.b64 %0, {%1, %1};" : "=l"(r) : "f"(v)); return r;
}
__device__ __forceinline__ u64 f2pk(float a, float b) {
  u64 r; asm("mov.b64 %0, {%1, %2};" : "=l"(r) : "f"(a), "f"(b)); return r;
}
__device__ __forceinline__ void fma2(u64& d, u64 a, u64 b) {
  asm("fma.rn.f32x2 %0, %1, %2, %0;" : "+l"(d) : "l"(a), "l"(b));
}
__device__ __forceinline__ float2 f2up(u64 v) {
  float2 f; asm("mov.b64 {%0, %1}, %2;" : "=f"(f.x), "=f"(f.y) : "l"(v)); return f;
}
__device__ __forceinline__ unsigned cvt_tf32(float x) {
  unsigned r; asm("cvt.rna.tf32.f32 %0, %1;" : "=r"(r) : "f"(x)); return r;
}
__device__ __forceinline__ void mma_tf32(
    float& d0, float& d1, float& d2, float& d3,
    unsigned a0, unsigned a1, unsigned a2, unsigned a3,
    unsigned b0, unsigned b1) {
  asm volatile(
    "mma.sync.aligned.m16n8k8.row.col.f32.tf32.tf32.f32 "
    "{%0,%1,%2,%3}, {%4,%5,%6,%7}, {%8,%9}, {%0,%1,%2,%3};"
    : "+f"(d0), "+f"(d1), "+f"(d2), "+f"(d3)
    : "r"(a0), "r"(a1), "r"(a2), "r"(a3), "r"(b0), "r"(b1));
}

// ---------------- scratch ----------------------------------------------------
__device__ float g_t1[2*(size_t)IMG];
__device__ float g_t2[2*(size_t)IMG];
__device__ float g_bnA[2][NC];
__device__ float g_bnB[2][NC];
__device__ __align__(16) unsigned g_wth[2][NG*9*256];  // [layer][g][khkw][ic][oc] hi
__device__ __align__(16) unsigned g_wtl[2][NG*9*256];  // lo

// ---------------- BN statistics ----------------------------------------------
__global__ __launch_bounds__(256) void bn_stats_kernel(
    const float* __restrict__ xl, const float* __restrict__ xr,
    const float* __restrict__ gamma, const float* __restrict__ beta) {
  int c = blockIdx.x & 63;
  int img = blockIdx.x >> 6;
  const float4* x = (const float4*)(img ? xr : xl);
  int t = threadIdx.x;
  float s = 0.f, s2 = 0.f;
  for (int b = 0; b < NB; b++) {
    const float4* p = x + (size_t)(b*NC + c)*(HW/4);
    for (int i = t; i < HW/4; i += 256) {
      float4 v = p[i];
      s  += v.x + v.y + v.z + v.w;
      s2 += v.x*v.x + v.y*v.y + v.z*v.z + v.w*v.w;
    }
  }
  __shared__ float sh[256], sh2[256];
  sh[t] = s; sh2[t] = s2; __syncthreads();
  for (int off = 128; off; off >>= 1) {
    if (t < off) { sh[t] += sh[t+off]; sh2[t] += sh2[t+off]; }
    __syncthreads();
  }
  if (t == 0) {
    const float inv = 1.f / (float)(NB*HW);
    float mean = sh[0] * inv;
    float var  = sh2[0] * inv - mean*mean;
    float a = gamma[c] * rsqrtf(var + 1e-5f);
    g_bnA[img][c] = a;
    g_bnB[img][c] = beta[c] - mean * a;
  }
}

// ---------------- weight transpose + tf32 hi/lo split -------------------------
// dst[layer][g][khkw][ic][oc] from src[g][oc][ic][kh][kw]
__global__ __launch_bounds__(256) void wtrans_kernel(
    const float* __restrict__ w1, const float* __restrict__ w2) {
  int i = blockIdx.x * 256 + threadIdx.x;       // 2*4*9*256 = 18432
  if (i >= 2*NG*9*256) return;
  int layer = i / (NG*9*256);
  int j = i - layer*(NG*9*256);
  int g = j / (9*256);
  int r = j - g*(9*256);
  int khkw = r >> 8;
  int q = r & 255;
  int ic = q >> 4, oc = q & 15;
  const float* src = layer ? w2 : w1;
  float v = src[g*(CG*CG*9) + oc*(CG*9) + ic*9 + khkw];
  unsigned hb = cvt_tf32(v);
  g_wth[layer][j] = hb;
  g_wtl[layer][j] = cvt_tf32(v - __uint_as_float(hb));
}

// ---------------- grouped 3x3 conv as 9x implicit tf32 GEMM ------------------
#define CIN_ST 132
#define CIN_ROW (6*CIN_ST)   // 792
#define CONV_SMEM (2*CG*CIN_ROW*4)   // 101376 B -> 2 CTAs/SM

template<bool FIRST>
__global__ __launch_bounds__(256, 2) void conv3x3_kernel(
    const float* __restrict__ xL, const float* __restrict__ xR,
    float* __restrict__ t1, float* __restrict__ t2,
    const unsigned* __restrict__ wth, const unsigned* __restrict__ wtl,
    const float* __restrict__ bias) {
  extern __shared__ unsigned smu[];
  unsigned* in_hi = smu;                    // [16ic][6r][132]
  unsigned* in_lo = smu + CG*CIN_ROW;
  int t = threadIdx.x;
  int img = blockIdx.z;
  int b = blockIdx.y >> 2, grp = blockIdx.y & 3;
  int h0 = blockIdx.x * 4;
  const float* xorig = img ? xR : xL;
  const float* xin = FIRST ? xorig : (t1 + (size_t)img*IMG);
  float* out = (FIRST ? t1 : t2) + (size_t)img*IMG;

  // stage + BN + tf32 hi/lo split
  for (int i = t; i < CG*CIN_ROW; i += 256) {
    int ic  = i / CIN_ROW;
    int rem = i - ic*CIN_ROW;
    int r   = rem / CIN_ST;
    int wc  = rem - r*CIN_ST;
    int hh  = h0 - 1 + r;
    int ww  = wc - 1;
    float v = 0.f;
    if ((unsigned)hh < (unsigned)NH && (unsigned)ww < (unsigned)NW) {
      v = xin[((size_t)(b*NC + grp*CG + ic)*NH + hh)*NW + ww];
      if (FIRST) v = g_bnA[img][grp*CG+ic]*v + g_bnB[img][grp*CG+ic];
    }
    unsigned hb = cvt_tf32(v);
    in_hi[i] = hb;
    in_lo[i] = cvt_tf32(v - __uint_as_float(hb));
  }
  __syncthreads();

  int warp = t >> 5, lane = t & 31;
  int gr = lane >> 2, tig = lane & 3;
  int hh = warp >> 1;                  // output row within tile
  int wbase = (warp & 1) * 64;

  const unsigned* whi = wth + grp*(9*256);
  const unsigned* wlo = wtl + grp*(9*256);

  float d[8][4];
  #pragma unroll
  for (int nt = 0; nt < 8; nt++)
    d[nt][0] = d[nt][1] = d[nt][2] = d[nt][3] = 0.f;

  #pragma unroll
  for (int khkw = 0; khkw < 9; khkw++) {
    const int kh = khkw / 3, kw = khkw % 3;
    const unsigned* wh = whi + khkw*256;
    const unsigned* wl = wlo + khkw*256;
    unsigned ah[2][4], al[2][4];
    #pragma unroll
    for (int ks = 0; ks < 2; ks++) {
      int ic0 = ks*8 + tig;
      ah[ks][0] = __ldg(wh + ic0*16 + gr);
      ah[ks][1] = __ldg(wh + ic0*16 + gr + 8);
      ah[ks][2] = __ldg(wh + (ic0+4)*16 + gr);
      ah[ks][3] = __ldg(wh + (ic0+4)*16 + gr + 8);
      al[ks][0] = __ldg(wl + ic0*16 + gr);
      al[ks][1] = __ldg(wl + ic0*16 + gr + 8);
      al[ks][2] = __ldg(wl + (ic0+4)*16 + gr);
      al[ks][3] = __ldg(wl + (ic0+4)*16 + gr + 8);
    }
    int base_in = (hh + kh)*CIN_ST + wbase + kw + gr;
    #pragma unroll
    for (int nt = 0; nt < 8; nt++) {
      int coln = base_in + nt*8;
      #pragma unroll
      for (int ks = 0; ks < 2; ks++) {
        int icr = ks*8 + tig;
        unsigned bh0 = in_hi[icr*CIN_ROW + coln];
        unsigned bh1 = in_hi[(icr+4)*CIN_ROW + coln];
        unsigned bl0 = in_lo[icr*CIN_ROW + coln];
        unsigned bl1 = in_lo[(icr+4)*CIN_ROW + coln];
        mma_tf32(d[nt][0],d[nt][1],d[nt][2],d[nt][3],
                 al[ks][0],al[ks][1],al[ks][2],al[ks][3], bh0,bh1);
        mma_tf32(d[nt][0],d[nt][1],d[nt][2],d[nt][3],
                 ah[ks][0],ah[ks][1],ah[ks][2],ah[ks][3], bl0,bl1);
        mma_tf32(d[nt][0],d[nt][1],d[nt][2],d[nt][3],
                 ah[ks][0],ah[ks][1],ah[ks][2],ah[ks][3], bh0,bh1);
      }
    }
  }

  // epilogue: thread (gr,tig) owns D[oc=gr][n=nt*8+2tig..+1] and D[oc=gr+8][...]
  int hout = h0 + hh;
  int ch0 = grp*CG + gr;
  int ch1 = ch0 + 8;
  float bz0 = bias[ch0], bz1 = bias[ch1];
  float ra0 = 0.f, rb0 = 0.f, ra1 = 0.f, rb1 = 0.f;
  if (!FIRST) {
    ra0 = g_bnA[img][ch0]; rb0 = g_bnB[img][ch0];
    ra1 = g_bnA[img][ch1]; rb1 = g_bnB[img][ch1];
  }
  size_t base0 = ((size_t)(b*NC + ch0)*NH + hout)*NW;
  size_t base1 = ((size_t)(b*NC + ch1)*NH + hout)*NW;
  #pragma unroll
  for (int nt = 0; nt < 8; nt++) {
    int w2c = wbase + nt*8 + 2*tig;
    float v0 = d[nt][0] + bz0, v1 = d[nt][1] + bz0;
    float v2 = d[nt][2] + bz1, v3 = d[nt][3] + bz1;
    if (FIRST) {
      v0 = v0 > 0.f ? v0 : 0.1f*v0;
      v1 = v1 > 0.f ? v1 : 0.1f*v1;
      v2 = v2 > 0.f ? v2 : 0.1f*v2;
      v3 = v3 > 0.f ? v3 : 0.1f*v3;
    } else {
      float2 x0 = *(const float2*)&xorig[base0 + w2c];
      float2 x1 = *(const float2*)&xorig[base1 + w2c];
      v0 += ra0*x0.x + rb0;  v1 += ra0*x0.y + rb0;
      v2 += ra1*x1.x + rb1;  v3 += ra1*x1.y + rb1;
    }
    *(float2*)&out[base0 + w2c] = make_float2(v0, v1);
    *(float2*)&out[base1 + w2c] = make_float2(v2, v3);
  }
}

// ---------------- fused attention (R9 version, measured 345us) ---------------
#define ST 128
#define XST 68
#define OFF_BM    16384
#define OFF_XLS   32768
#define OFF_XRS   41472
#define OFF_WS    50176
#define OFF_BS    52224
#define OFF_RMAX  52352
#define OFF_RSC   52480
#define OFF_CMAX  52608
#define OFF_GCC   52736
#define OFF_VL    52864
#define OFF_VR    52992
#define OFF_PART  53120
#define OFF_FR    55168
#define OFF_GC    55296
#define OFF_MG    55424
#define ATTN_SMEM ((55424 + 32)*4)

__global__ __launch_bounds__(1024, 1) void attn_kernel(
    const float* __restrict__ t2, const float* __restrict__ xL,
    const float* __restrict__ xR,
    const float* __restrict__ qw, const float* __restrict__ qb,
    const float* __restrict__ kw_, const float* __restrict__ kb,
    float* __restrict__ outL, float* __restrict__ outR) {
  extern __shared__ float sm[];
  float* Am    = sm;
  float* Bm    = sm + OFF_BM;
  float* xls   = sm + OFF_XLS;
  float* xrs   = sm + OFF_XRS;
  float* ws    = sm + OFF_WS;
  float* bs    = sm + OFF_BS;
  float* rmax  = sm + OFF_RMAX;
  float* rsc   = sm + OFF_RSC;
  float* cmax  = sm + OFF_CMAX;
  float* gcc   = sm + OFF_GCC;
  float* Vl    = sm + OFF_VL;
  float* Vr    = sm + OFF_VR;
  float* part  = sm + OFF_PART;
  float* fr    = sm + OFF_FR;
  float* gc    = sm + OFF_GC;
  float* Mg    = sm + OFF_MG;
  int n = blockIdx.x, b = n >> 7, h = n & 127;
  int t = threadIdx.x, warp = t >> 5, lane = t & 31;

  for (int i = t; i < 2048; i += 1024) ws[i] = (i < 1024) ? qw[i] : kw_[i-1024];
  if (t < 128) bs[t] = (t < 64) ? qb[t] : kb[t-64];
  for (int i = t; i < 16384; i += 1024) {
    int c = i >> 7, u = i & 127;
    size_t gi = ((c >= 64) ? (size_t)IMG : 0) +
                ((size_t)(b*NC + (c & 63))*NH + h)*NW + u;
    Am[c*ST + u] = t2[gi];
  }
  __syncthreads();

  for (int i = t; i < 8192; i += 1024) {
    int k = i >> 6, up = (i & 63)*2;
    int cb = (k >> 4) * 16;
    float bzv = bs[k];
    u64 a = f2pk(bzv, bzv);
    #pragma unroll
    for (int ic = 0; ic < 16; ic++) {
      u64 w2 = f2dup(ws[k*16 + ic]);
      u64 xp = *(const u64*)&Am[(cb + ic)*ST + up];
      fma2(a, w2, xp);
    }
    *(u64*)&Bm[k*ST + up] = a;
  }
  __syncthreads();

  for (int r = warp; r < 128; r += 32) {
    float s = 0.f;
    for (int u = lane; u < 128; u += 32) s += Bm[r*ST + u];
    #pragma unroll
    for (int off = 16; off; off >>= 1) s += __shfl_xor_sync(0xffffffffu, s, off);
    float mean = s * (1.f/128.f);
    for (int u = lane; u < 128; u += 32) Bm[r*ST + u] -= mean;
  }
  __syncthreads();

  int g1u0 = warp * 4, g1v0 = lane * 4;
  float cmv[4] = {-1e30f, -1e30f, -1e30f, -1e30f};
  {
    u64 acc2[4][2];
    #pragma unroll
    for (int i = 0; i < 4; i++) { acc2[i][0] = 0ull; acc2[i][1] = 0ull; }
    for (int k = 0; k < 64; k++) {
      float4 qv = *(const float4*)&Bm[k*ST + g1u0];
      ulonglong2 kv = *(const ulonglong2*)&Bm[(64+k)*ST + g1v0];
      u64 q0 = f2dup(qv.x), q1 = f2dup(qv.y), q2 = f2dup(qv.z), q3 = f2dup(qv.w);
      fma2(acc2[0][0], q0, kv.x); fma2(acc2[0][1], q0, kv.y);
      fma2(acc2[1][0], q1, kv.x); fma2(acc2[1][1], q1, kv.y);
      fma2(acc2[2][0], q2, kv.x); fma2(acc2[2][1], q2, kv.y);
      fma2(acc2[3][0], q3, kv.x); fma2(acc2[3][1], q3, kv.y);
    }
    #pragma unroll
    for (int i = 0; i < 4; i++) {
      float2 a = f2up(acc2[i][0]), c2 = f2up(acc2[i][1]);
      *(float4*)&Am[(g1u0+i)*ST + g1v0] = make_float4(a.x,a.y,c2.x,c2.y);
      float rm = fmaxf(fmaxf(a.x, a.y), fmaxf(c2.x, c2.y));
      #pragma unroll
      for (int off = 16; off; off >>= 1) rm = fmaxf(rm, __shfl_xor_sync(0xffffffffu, rm, off));
      if (lane == 0) rmax[g1u0+i] = rm;
      cmv[0] = fmaxf(cmv[0], a.x);  cmv[1] = fmaxf(cmv[1], a.y);
      cmv[2] = fmaxf(cmv[2], c2.x); cmv[3] = fmaxf(cmv[3], c2.y);
    }
    if (warp < 16)
      *(float4*)&part[warp*128 + g1v0] = make_float4(cmv[0],cmv[1],cmv[2],cmv[3]);
  }
  __syncthreads();

  if (warp >= 16) {
    float4 old = *(const float4*)&part[(warp-16)*128 + g1v0];
    old.x = fmaxf(old.x, cmv[0]); old.y = fmaxf(old.y, cmv[1]);
    old.z = fmaxf(old.z, cmv[2]); old.w = fmaxf(old.w, cmv[3]);
    *(float4*)&part[(warp-16)*128 + g1v0] = old;
  }
  for (int i = t; i < 8192; i += 1024) {
    int c = i >> 7, v = i & 127;
    size_t gi = ((size_t)(b*NC + c)*NH + h)*NW + v;
    xls[v*XST + c] = xL[gi];
    xrs[v*XST + c] = xR[gi];
  }
  __syncthreads();

  if (t < 128) {
    float m = -1e30f;
    #pragma unroll
    for (int k2 = 0; k2 < 16; k2++) m = fmaxf(m, part[k2*128 + t]);
    cmax[t] = m;
  } else if (t < 160) {
    int l = t - 128;
    float m = fmaxf(fmaxf(rmax[l], rmax[l+32]), fmaxf(rmax[l+64], rmax[l+96]));
    #pragma unroll
    for (int off = 16; off; off >>= 1) m = fmaxf(m, __shfl_xor_sync(0xffffffffu, m, off));
    if (l == 0) Mg[0] = m;
  }
  __syncthreads();
  if (t < 128) {
    float M = Mg[0];
    fr[t] = __expf(rmax[t] - M);
    gc[t] = __expf(M - cmax[t]);
  }
  __syncthreads();

  if (warp < 16) {
    float gcv[4];
    #pragma unroll
    for (int k = 0; k < 4; k++) gcv[k] = gc[lane + k*32];
    float csump[4] = {0.f, 0.f, 0.f, 0.f};
    for (int rr = 0; rr < 8; rr++) {
      int r = warp*8 + rr;
      float rm = rmax[r];
      float frv = fr[r];
      float rs = 0.f;
      #pragma unroll
      for (int k = 0; k < 4; k++) {
        int c = lane + k*32;
        float e = __expf(Am[r*ST + c] - rm);
        float ap = e * frv;
        Am[r*ST + c] = ap;
        rs += e;
        csump[k] += ap * gcv[k];
      }
      #pragma unroll
      for (int off = 16; off; off >>= 1) rs += __shfl_xor_sync(0xffffffffu, rs, off);
      if (lane == 0) rsc[r] = 1.f / rs;
    }
    #pragma unroll
    for (int k = 0; k < 4; k++) part[warp*128 + k*32 + lane] = csump[k];
  }
  __syncthreads();
  if (t < 128) {
    float s = 0.f;
    #pragma unroll
    for (int w = 0; w < 16; w++) s += part[w*128 + t];
    gcc[t] = gc[t] / s;
    rsc[t] = __fdividef(rsc[t], fr[t]);
  }
  __syncthreads();

  if (warp < 16) {
    int a0 = warp * 8;
    float acc0[8], acc1[8], acc2g[8];
    #pragma unroll
    for (int i = 0; i < 8; i++) { acc0[i]=0.f; acc1[i]=0.f; acc2g[i]=0.f; }
    #pragma unroll
    for (int vj = 0; vj < 4; vj++) {
      int v = lane + vj*32;
      float w = gcc[v];
      float e[10];
      #pragma unroll
      for (int i = 0; i < 10; i++) e[i] = (a0+i < 128) ? Am[(a0+i)*ST + v] : 0.f;
      #pragma unroll
      for (int i = 0; i < 8; i++) {
        float ew = e[i]*w;
        acc0[i] += ew*e[i];
        acc1[i] += ew*e[i+1];
        acc2g[i] += ew*e[i+2];
      }
    }
    #pragma unroll
    for (int i = 0; i < 8; i++) {
      #pragma unroll
      for (int off = 16; off; off >>= 1) {
        acc0[i]  += __shfl_xor_sync(0xffffffffu, acc0[i],  off);
        acc1[i]  += __shfl_xor_sync(0xffffffffu, acc1[i],  off);
        acc2g[i] += __shfl_xor_sync(0xffffffffu, acc2g[i], off);
      }
      if (lane == 0) {
        part[a0+i]       = acc0[i];
        part[128 + a0+i] = acc1[i];
        part[256 + a0+i] = acc2g[i];
      }
    }
  } else {
    int idx = warp - 16, cb = idx & 3, vc = idx >> 2;
    int c = cb*32 + lane;
    float h0 = 0.f, h1 = 0.f, h2 = 0.f;
    for (int v = vc*32; v < vc*32 + 32; v++) {
      float e = Am[v*ST + c];
      float e1 = __shfl_down_sync(0xffffffffu, e, 1);
      float e2 = __shfl_down_sync(0xffffffffu, e, 2);
      if (lane >= 30) e2 = (c+2 < 128) ? Am[v*ST + c + 2] : 0.f;
      if (lane == 31) e1 = (c+1 < 128) ? Am[v*ST + c + 1] : 0.f;
      float ew = e * rsc[v];
      h0 += ew*e; h1 += ew*e1; h2 += ew*e2;
    }
    ws[vc*384 + c]       = h0;
    ws[vc*384 + 128 + c] = h1;
    ws[vc*384 + 256 + c] = h2;
  }
  __syncthreads();

  if (t < 384) {
    part[384 + t] = ws[t] + ws[384+t] + ws[768+t] + ws[1152+t];
  } else if (t >= 512 && t < 640) {
    int u = t - 512;
    float accL = rsc[u]*part[u];
    if (u+1 < 128) accL += rsc[u+1]*part[128+u];
    if (u+2 < 128) accL += rsc[u+2]*part[256+u];
    if (u >= 1)    accL += rsc[u-1]*part[128+u-1];
    if (u >= 2)    accL += rsc[u-2]*part[256+u-2];
    Vl[u] = tanhf(5.f*accL);
  }
  __syncthreads();
  if (t < 128) {
    int u = t;
    float accR = gcc[u]*part[384+u];
    if (u+1 < 128) accR += gcc[u+1]*part[512+u];
    if (u+2 < 128) accR += gcc[u+2]*part[640+u];
    if (u >= 1)    accR += gcc[u-1]*part[512+u-1];
    if (u >= 2)    accR += gcc[u-2]*part[640+u-2];
    Vr[u] = tanhf(5.f*accR);
  }

  int group = t >> 9;
  int tid = t & 511;
  int c0 = (tid & 15)*4, u0 = (tid >> 4)*4;
  u64 acc2[4][2];
  #pragma unroll
  for (int i = 0; i < 4; i++) { acc2[i][0] = 0ull; acc2[i][1] = 0ull; }

  if (group == 0) {
    for (int v0g = 0; v0g < 128; v0g += 4) {
      ulonglong2 x0 = *(const ulonglong2*)&xrs[(v0g+0)*XST + c0];
      ulonglong2 x1 = *(const ulonglong2*)&xrs[(v0g+1)*XST + c0];
      ulonglong2 x2 = *(const ulonglong2*)&xrs[(v0g+2)*XST + c0];
      ulonglong2 x3 = *(const ulonglong2*)&xrs[(v0g+3)*XST + c0];
      #pragma unroll
      for (int i = 0; i < 4; i++) {
        float4 m = *(const float4*)&Am[(u0+i)*ST + v0g];
        u64 m0 = f2dup(m.x), m1 = f2dup(m.y), m2 = f2dup(m.z), m3 = f2dup(m.w);
        fma2(acc2[i][0], m0, x0.x); fma2(acc2[i][1], m0, x0.y);
        fma2(acc2[i][0], m1, x1.x); fma2(acc2[i][1], m1, x1.y);
        fma2(acc2[i][0], m2, x2.x); fma2(acc2[i][1], m2, x2.y);
        fma2(acc2[i][0], m3, x3.x); fma2(acc2[i][1], m3, x3.y);
      }
    }
  } else {
    for (int v = 0; v < 128; v++) {
      ulonglong2 xp = *(const ulonglong2*)&xls[v*XST + c0];
      float4 b0 = *(const float4*)&Am[v*ST + u0];
      u64 b0d = f2dup(b0.x), b1d = f2dup(b0.y), b2d = f2dup(b0.z), b3d = f2dup(b0.w);
      fma2(acc2[0][0], b0d, xp.x); fma2(acc2[0][1], b0d, xp.y);
      fma2(acc2[1][0], b1d, xp.x); fma2(acc2[1][1], b1d, xp.y);
      fma2(acc2[2][0], b2d, xp.x); fma2(acc2[2][1], b2d, xp.y);
      fma2(acc2[3][0], b3d, xp.x); fma2(acc2[3][1], b3d, xp.y);
    }
  }
  __syncthreads();

  if (group == 0) {
    #pragma unroll
    for (int i = 0; i < 4; i++) {
      int u = u0 + i;
      float vl = Vl[u];
      float gsc = vl * rsc[u];
      float2 f0 = f2up(acc2[i][0]), f1 = f2up(acc2[i][1]);
      float xt[4] = {f0.x, f0.y, f1.x, f1.y};
      #pragma unroll
      for (int cc = 0; cc < 4; cc++) {
        int x = u*XST + c0 + cc;
        xls[x] = xls[x]*(1.f - vl) + xt[cc]*gsc;
      }
    }
  } else {
    #pragma unroll
    for (int i = 0; i < 4; i++) {
      int u = u0 + i;
      float vr = Vr[u];
      float gsc = vr * gcc[u];
      float2 f0 = f2up(acc2[i][0]), f1 = f2up(acc2[i][1]);
      float xt[4] = {f0.x, f0.y, f1.x, f1.y};
      #pragma unroll
      for (int cc = 0; cc < 4; cc++) {
        int x = u*XST + c0 + cc;
        xrs[x] = xrs[x]*(1.f - vr) + xt[cc]*gsc;
      }
    }
  }
  __syncthreads();

  for (int i = t; i < 8192; i += 1024) {
    int c = i >> 7, u = i & 127;
    size_t gi = ((size_t)(b*NC + c)*NH + h)*NW + u;
    outL[gi] = xls[u*XST + c];
    outR[gi] = xrs[u*XST + c];
  }
}

// ---------------- host ------------------------------------------------------
extern "C" void kernel_launch(void* const* d_in, const int* in_sizes, int n_in,
                              void* d_out, int out_size) {
  const float* xL    = (const float*)d_in[0];
  const float* xR    = (const float*)d_in[1];
  const float* gamma = (const float*)d_in[2];
  const float* beta  = (const float*)d_in[3];
  const float* w1    = (const float*)d_in[4];
  const float* b1    = (const float*)d_in[5];
  const float* w2    = (const float*)d_in[6];
  const float* b2    = (const float*)d_in[7];
  const float* qw    = (const float*)d_in[8];
  const float* qb    = (const float*)d_in[9];
  const float* kw    = (const float*)d_in[10];
  const float* kb    = (const float*)d_in[11];
  float* outL = (float*)d_out;
  float* outR = outL + (size_t)IMG;

  float *t1, *t2;
  unsigned *wth, *wtl;
  cudaGetSymbolAddress((void**)&t1, g_t1);
  cudaGetSymbolAddress((void**)&t2, g_t2);
  cudaGetSymbolAddress((void**)&wth, g_wth);
  cudaGetSymbolAddress((void**)&wtl, g_wtl);

  cudaFuncSetAttribute(conv3x3_kernel<true>,  cudaFuncAttributeMaxDynamicSharedMemorySize, CONV_SMEM);
  cudaFuncSetAttribute(conv3x3_kernel<false>, cudaFuncAttributeMaxDynamicSharedMemorySize, CONV_SMEM);
  cudaFuncSetAttribute(attn_kernel, cudaFuncAttributeMaxDynamicSharedMemorySize, ATTN_SMEM);

  bn_stats_kernel<<<128, 256>>>(xL, xR, gamma, beta);
  wtrans_kernel<<<(2*NG*9*256 + 255)/256, 256>>>(w1, w2);

  dim3 cgrid(NH/4, NB*NG, 2);
  conv3x3_kernel<true ><<<cgrid, 256, CONV_SMEM>>>(
      xL, xR, t1, t2, wth, wtl, b1);
  conv3x3_kernel<false><<<cgrid, 256, CONV_SMEM>>>(
      xL, xR, t1, t2, wth + NG*9*256, wtl + NG*9*256, b2);

  attn_kernel<<<NROW, 1024, ATTN_SMEM>>>(t2, xL, xR, qw, qb, kw, kb, outL, outR);
}

// round 12
// speedup vs baseline: 1.3467x; 1.2571x over previous
#include <cuda_runtime.h>
#include <cuda_bf16.h>
#include <math.h>

#define NB 8
#define NC 64
#define NG 4
#define CG 16
#define NH 128
#define NW 128
#define HW (NH*NW)
#define IMG (NB*NC*HW)
#define NROW (NB*NH)

typedef unsigned long long u64;

__device__ __forceinline__ u64 f2dup(float v) {
  u64 r; asm("mov.b64 %0, {%1, %1};" : "=l"(r) : "f"(v)); return r;
}
__device__ __forceinline__ u64 f2pk(float a, float b) {
  u64 r; asm("mov.b64 %0, {%1, %2};" : "=l"(r) : "f"(a), "f"(b)); return r;
}
__device__ __forceinline__ void fma2(u64& d, u64 a, u64 b) {
  asm("fma.rn.f32x2 %0, %1, %2, %0;" : "+l"(d) : "l"(a), "l"(b));
}
__device__ __forceinline__ float2 f2up(u64 v) {
  float2 f; asm("mov.b64 {%0, %1}, %2;" : "=f"(f.x), "=f"(f.y) : "l"(v)); return f;
}
__device__ __forceinline__ void mma_bf16(
    float& d0, float& d1, float& d2, float& d3,
    unsigned a0, unsigned a1, unsigned a2, unsigned a3,
    unsigned b0, unsigned b1) {
  asm volatile(
    "mma.sync.aligned.m16n8k16.row.col.f32.bf16.bf16.f32 "
    "{%0,%1,%2,%3}, {%4,%5,%6,%7}, {%8,%9}, {%0,%1,%2,%3};"
    : "+f"(d0), "+f"(d1), "+f"(d2), "+f"(d3)
    : "r"(a0), "r"(a1), "r"(a2), "r"(a3), "r"(b0), "r"(b1));
}
__device__ __forceinline__ unsigned bfpk(__nv_bfloat16 a, __nv_bfloat16 b) {
  __nv_bfloat162 h = __halves2bfloat162(a, b);
  return *(unsigned*)&h;
}

// ---------------- scratch ----------------------------------------------------
__device__ float g_t1[2*(size_t)IMG];
__device__ float g_t2[2*(size_t)IMG];
__device__ float g_bnA[2][NC];
__device__ float g_bnB[2][NC];
__device__ __align__(16) unsigned g_wth[2][NG*9*16*8];  // [layer][g][khkw][oc][icpair]
__device__ __align__(16) unsigned g_wtl[2][NG*9*16*8];

// ---------------- BN statistics ----------------------------------------------
__global__ __launch_bounds__(256) void bn_stats_kernel(
    const float* __restrict__ xl, const float* __restrict__ xr,
    const float* __restrict__ gamma, const float* __restrict__ beta) {
  int c = blockIdx.x & 63;
  int img = blockIdx.x >> 6;
  const float4* x = (const float4*)(img ? xr : xl);
  int t = threadIdx.x;
  float s = 0.f, s2 = 0.f;
  for (int b = 0; b < NB; b++) {
    const float4* p = x + (size_t)(b*NC + c)*(HW/4);
    for (int i = t; i < HW/4; i += 256) {
      float4 v = p[i];
      s  += v.x + v.y + v.z + v.w;
      s2 += v.x*v.x + v.y*v.y + v.z*v.z + v.w*v.w;
    }
  }
  __shared__ float sh[256], sh2[256];
  sh[t] = s; sh2[t] = s2; __syncthreads();
  for (int off = 128; off; off >>= 1) {
    if (t < off) { sh[t] += sh[t+off]; sh2[t] += sh2[t+off]; }
    __syncthreads();
  }
  if (t == 0) {
    const float inv = 1.f / (float)(NB*HW);
    float mean = sh[0] * inv;
    float var  = sh2[0] * inv - mean*mean;
    float a = gamma[c] * rsqrtf(var + 1e-5f);
    g_bnA[img][c] = a;
    g_bnB[img][c] = beta[c] - mean * a;
  }
}

// ---------------- weight prep: bf16 hi/lo, [g][khkw][oc][icpair] -------------
__global__ __launch_bounds__(256) void wtrans_kernel(
    const float* __restrict__ w1, const float* __restrict__ w2) {
  int i = blockIdx.x * 256 + threadIdx.x;   // 2*4608
  if (i >= 2*NG*9*16*8) return;
  int layer = i / 4608;
  int j = i - layer*4608;
  int g = j / 1152;
  int r = j - g*1152;
  int khkw = r >> 7;
  int q = r & 127;
  int oc = q >> 3, p = q & 7;
  const float* src = layer ? w2 : w1;
  int base = g*(CG*CG*9) + oc*(CG*9) + (2*p)*9 + khkw;
  float w0 = src[base], w1v = src[base + 9];
  __nv_bfloat16 h0 = __float2bfloat16(w0);
  __nv_bfloat16 h1 = __float2bfloat16(w1v);
  g_wth[layer][j] = bfpk(h0, h1);
  g_wtl[layer][j] = bfpk(__float2bfloat16(w0 - __bfloat162float(h0)),
                         __float2bfloat16(w1v - __bfloat162float(h1)));
}

// ---------------- grouped 3x3 conv: bf16 m16n8k16 implicit GEMM --------------
#define PRST 136            // pair stride (136 % 32 == 8 -> conflict-free)
#define ROWST (8*PRST)      // 1088
#define CIN_U32 (6*ROWST)   // 6528 u32 per buffer
#define CONV_SMEM (2*CIN_U32*4)   // 52224 B -> 3 CTAs/SM

template<bool FIRST>
__global__ __launch_bounds__(256, 3) void conv3x3_kernel(
    const float* __restrict__ xL, const float* __restrict__ xR,
    float* __restrict__ t1, float* __restrict__ t2,
    const unsigned* __restrict__ wth, const unsigned* __restrict__ wtl,
    const float* __restrict__ bias) {
  extern __shared__ unsigned smu[];
  unsigned* in_hi = smu;             // [row(6)][pair(8)][col(136)]
  unsigned* in_lo = smu + CIN_U32;
  int t = threadIdx.x;
  int img = blockIdx.z;
  int b = blockIdx.y >> 2, grp = blockIdx.y & 3;
  int h0 = blockIdx.x * 4;
  const float* xorig = img ? xR : xL;
  const float* xin = FIRST ? xorig : (t1 + (size_t)img*IMG);
  float* out = (FIRST ? t1 : t2) + (size_t)img*IMG;

  // stage + (BN) + bf16 hi/lo split, channel pairs packed
  for (int i = t; i < CIN_U32; i += 256) {
    int col  = i % PRST;
    int rest = i / PRST;
    int pair = rest & 7;
    int row  = rest >> 3;
    int hh = h0 - 1 + row;
    int ww = col - 1;
    float v0 = 0.f, v1 = 0.f;
    if ((unsigned)hh < (unsigned)NH && (unsigned)ww < (unsigned)NW) {
      int ch = grp*CG + 2*pair;
      size_t gidx = ((size_t)(b*NC + ch)*NH + hh)*NW + ww;
      v0 = xin[gidx];
      v1 = xin[gidx + HW];
      if (FIRST) {
        v0 = g_bnA[img][ch]*v0 + g_bnB[img][ch];
        v1 = g_bnA[img][ch+1]*v1 + g_bnB[img][ch+1];
      }
    }
    __nv_bfloat16 h0b = __float2bfloat16(v0);
    __nv_bfloat16 h1b = __float2bfloat16(v1);
    in_hi[i] = bfpk(h0b, h1b);
    in_lo[i] = bfpk(__float2bfloat16(v0 - __bfloat162float(h0b)),
                    __float2bfloat16(v1 - __bfloat162float(h1b)));
  }
  __syncthreads();

  int warp = t >> 5, lane = t & 31;
  int gr = lane >> 2, tig = lane & 3;
  int hh = warp >> 1;
  int wbase = (warp & 1) * 64;

  const unsigned* whg = wth + grp*(9*128);
  const unsigned* wlg = wtl + grp*(9*128);

  float d[8][4];
  #pragma unroll
  for (int nt = 0; nt < 8; nt++)
    d[nt][0] = d[nt][1] = d[nt][2] = d[nt][3] = 0.f;

  #pragma unroll
  for (int khkw = 0; khkw < 9; khkw++) {
    const int kh = khkw / 3, kw = khkw % 3;
    const unsigned* wh = whg + khkw*128;
    const unsigned* wl = wlg + khkw*128;
    unsigned ah0 = __ldg(wh + gr*8 + tig);
    unsigned ah1 = __ldg(wh + gr*8 + tig + 64);
    unsigned ah2 = __ldg(wh + gr*8 + tig + 4);
    unsigned ah3 = __ldg(wh + gr*8 + tig + 68);
    unsigned al0 = __ldg(wl + gr*8 + tig);
    unsigned al1 = __ldg(wl + gr*8 + tig + 64);
    unsigned al2 = __ldg(wl + gr*8 + tig + 4);
    unsigned al3 = __ldg(wl + gr*8 + tig + 68);
    int base_in = (hh + kh)*ROWST + tig*PRST + wbase + kw + gr;
    #pragma unroll
    for (int nt = 0; nt < 8; nt++) {
      int coln = base_in + nt*8;
      unsigned bh0 = in_hi[coln];
      unsigned bh1 = in_hi[coln + 4*PRST];
      unsigned bl0 = in_lo[coln];
      unsigned bl1 = in_lo[coln + 4*PRST];
      mma_bf16(d[nt][0],d[nt][1],d[nt][2],d[nt][3], al0,al1,al2,al3, bh0,bh1);
      mma_bf16(d[nt][0],d[nt][1],d[nt][2],d[nt][3], ah0,ah1,ah2,ah3, bl0,bl1);
      mma_bf16(d[nt][0],d[nt][1],d[nt][2],d[nt][3], ah0,ah1,ah2,ah3, bh0,bh1);
    }
  }

  // epilogue: thread (gr,tig) owns D[oc=gr][2tig,2tig+1] and D[oc=gr+8][...]
  int hout = h0 + hh;
  int ch0 = grp*CG + gr;
  int ch1 = ch0 + 8;
  float bz0 = bias[ch0], bz1 = bias[ch1];
  float ra0 = 0.f, rb0 = 0.f, ra1 = 0.f, rb1 = 0.f;
  if (!FIRST) {
    ra0 = g_bnA[img][ch0]; rb0 = g_bnB[img][ch0];
    ra1 = g_bnA[img][ch1]; rb1 = g_bnB[img][ch1];
  }
  size_t base0 = ((size_t)(b*NC + ch0)*NH + hout)*NW;
  size_t base1 = ((size_t)(b*NC + ch1)*NH + hout)*NW;
  #pragma unroll
  for (int nt = 0; nt < 8; nt++) {
    int w2c = wbase + nt*8 + 2*tig;
    float v0 = d[nt][0] + bz0, v1 = d[nt][1] + bz0;
    float v2 = d[nt][2] + bz1, v3 = d[nt][3] + bz1;
    if (FIRST) {
      v0 = v0 > 0.f ? v0 : 0.1f*v0;
      v1 = v1 > 0.f ? v1 : 0.1f*v1;
      v2 = v2 > 0.f ? v2 : 0.1f*v2;
      v3 = v3 > 0.f ? v3 : 0.1f*v3;
    } else {
      float2 x0 = *(const float2*)&xorig[base0 + w2c];
      float2 x1 = *(const float2*)&xorig[base1 + w2c];
      v0 += ra0*x0.x + rb0;  v1 += ra0*x0.y + rb0;
      v2 += ra1*x1.x + rb1;  v3 += ra1*x1.y + rb1;
    }
    *(float2*)&out[base0 + w2c] = make_float2(v0, v1);
    *(float2*)&out[base1 + w2c] = make_float2(v2, v3);
  }
}

// ---------------- fused attention (R9 version, measured 345us) ---------------
#define ST 128
#define XST 68
#define OFF_BM    16384
#define OFF_XLS   32768
#define OFF_XRS   41472
#define OFF_WS    50176
#define OFF_BS    52224
#define OFF_RMAX  52352
#define OFF_RSC   52480
#define OFF_CMAX  52608
#define OFF_GCC   52736
#define OFF_VL    52864
#define OFF_VR    52992
#define OFF_PART  53120
#define OFF_FR    55168
#define OFF_GC    55296
#define OFF_MG    55424
#define ATTN_SMEM ((55424 + 32)*4)

__global__ __launch_bounds__(1024, 1) void attn_kernel(
    const float* __restrict__ t2, const float* __restrict__ xL,
    const float* __restrict__ xR,
    const float* __restrict__ qw, const float* __restrict__ qb,
    const float* __restrict__ kw_, const float* __restrict__ kb,
    float* __restrict__ outL, float* __restrict__ outR) {
  extern __shared__ float sm[];
  float* Am    = sm;
  float* Bm    = sm + OFF_BM;
  float* xls   = sm + OFF_XLS;
  float* xrs   = sm + OFF_XRS;
  float* ws    = sm + OFF_WS;
  float* bs    = sm + OFF_BS;
  float* rmax  = sm + OFF_RMAX;
  float* rsc   = sm + OFF_RSC;
  float* cmax  = sm + OFF_CMAX;
  float* gcc   = sm + OFF_GCC;
  float* Vl    = sm + OFF_VL;
  float* Vr    = sm + OFF_VR;
  float* part  = sm + OFF_PART;
  float* fr    = sm + OFF_FR;
  float* gc    = sm + OFF_GC;
  float* Mg    = sm + OFF_MG;
  int n = blockIdx.x, b = n >> 7, h = n & 127;
  int t = threadIdx.x, warp = t >> 5, lane = t & 31;

  for (int i = t; i < 2048; i += 1024) ws[i] = (i < 1024) ? qw[i] : kw_[i-1024];
  if (t < 128) bs[t] = (t < 64) ? qb[t] : kb[t-64];
  for (int i = t; i < 16384; i += 1024) {
    int c = i >> 7, u = i & 127;
    size_t gi = ((c >= 64) ? (size_t)IMG : 0) +
                ((size_t)(b*NC + (c & 63))*NH + h)*NW + u;
    Am[c*ST + u] = t2[gi];
  }
  __syncthreads();

  for (int i = t; i < 8192; i += 1024) {
    int k = i >> 6, up = (i & 63)*2;
    int cb = (k >> 4) * 16;
    float bzv = bs[k];
    u64 a = f2pk(bzv, bzv);
    #pragma unroll
    for (int ic = 0; ic < 16; ic++) {
      u64 w2 = f2dup(ws[k*16 + ic]);
      u64 xp = *(const u64*)&Am[(cb + ic)*ST + up];
      fma2(a, w2, xp);
    }
    *(u64*)&Bm[k*ST + up] = a;
  }
  __syncthreads();

  for (int r = warp; r < 128; r += 32) {
    float s = 0.f;
    for (int u = lane; u < 128; u += 32) s += Bm[r*ST + u];
    #pragma unroll
    for (int off = 16; off; off >>= 1) s += __shfl_xor_sync(0xffffffffu, s, off);
    float mean = s * (1.f/128.f);
    for (int u = lane; u < 128; u += 32) Bm[r*ST + u] -= mean;
  }
  __syncthreads();

  int g1u0 = warp * 4, g1v0 = lane * 4;
  float cmv[4] = {-1e30f, -1e30f, -1e30f, -1e30f};
  {
    u64 acc2[4][2];
    #pragma unroll
    for (int i = 0; i < 4; i++) { acc2[i][0] = 0ull; acc2[i][1] = 0ull; }
    for (int k = 0; k < 64; k++) {
      float4 qv = *(const float4*)&Bm[k*ST + g1u0];
      ulonglong2 kv = *(const ulonglong2*)&Bm[(64+k)*ST + g1v0];
      u64 q0 = f2dup(qv.x), q1 = f2dup(qv.y), q2 = f2dup(qv.z), q3 = f2dup(qv.w);
      fma2(acc2[0][0], q0, kv.x); fma2(acc2[0][1], q0, kv.y);
      fma2(acc2[1][0], q1, kv.x); fma2(acc2[1][1], q1, kv.y);
      fma2(acc2[2][0], q2, kv.x); fma2(acc2[2][1], q2, kv.y);
      fma2(acc2[3][0], q3, kv.x); fma2(acc2[3][1], q3, kv.y);
    }
    #pragma unroll
    for (int i = 0; i < 4; i++) {
      float2 a = f2up(acc2[i][0]), c2 = f2up(acc2[i][1]);
      *(float4*)&Am[(g1u0+i)*ST + g1v0] = make_float4(a.x,a.y,c2.x,c2.y);
      float rm = fmaxf(fmaxf(a.x, a.y), fmaxf(c2.x, c2.y));
      #pragma unroll
      for (int off = 16; off; off >>= 1) rm = fmaxf(rm, __shfl_xor_sync(0xffffffffu, rm, off));
      if (lane == 0) rmax[g1u0+i] = rm;
      cmv[0] = fmaxf(cmv[0], a.x);  cmv[1] = fmaxf(cmv[1], a.y);
      cmv[2] = fmaxf(cmv[2], c2.x); cmv[3] = fmaxf(cmv[3], c2.y);
    }
    if (warp < 16)
      *(float4*)&part[warp*128 + g1v0] = make_float4(cmv[0],cmv[1],cmv[2],cmv[3]);
  }
  __syncthreads();

  if (warp >= 16) {
    float4 old = *(const float4*)&part[(warp-16)*128 + g1v0];
    old.x = fmaxf(old.x, cmv[0]); old.y = fmaxf(old.y, cmv[1]);
    old.z = fmaxf(old.z, cmv[2]); old.w = fmaxf(old.w, cmv[3]);
    *(float4*)&part[(warp-16)*128 + g1v0] = old;
  }
  for (int i = t; i < 8192; i += 1024) {
    int c = i >> 7, v = i & 127;
    size_t gi = ((size_t)(b*NC + c)*NH + h)*NW + v;
    xls[v*XST + c] = xL[gi];
    xrs[v*XST + c] = xR[gi];
  }
  __syncthreads();

  if (t < 128) {
    float m = -1e30f;
    #pragma unroll
    for (int k2 = 0; k2 < 16; k2++) m = fmaxf(m, part[k2*128 + t]);
    cmax[t] = m;
  } else if (t < 160) {
    int l = t - 128;
    float m = fmaxf(fmaxf(rmax[l], rmax[l+32]), fmaxf(rmax[l+64], rmax[l+96]));
    #pragma unroll
    for (int off = 16; off; off >>= 1) m = fmaxf(m, __shfl_xor_sync(0xffffffffu, m, off));
    if (l == 0) Mg[0] = m;
  }
  __syncthreads();
  if (t < 128) {
    float M = Mg[0];
    fr[t] = __expf(rmax[t] - M);
    gc[t] = __expf(M - cmax[t]);
  }
  __syncthreads();

  if (warp < 16) {
    float gcv[4];
    #pragma unroll
    for (int k = 0; k < 4; k++) gcv[k] = gc[lane + k*32];
    float csump[4] = {0.f, 0.f, 0.f, 0.f};
    for (int rr = 0; rr < 8; rr++) {
      int r = warp*8 + rr;
      float rm = rmax[r];
      float frv = fr[r];
      float rs = 0.f;
      #pragma unroll
      for (int k = 0; k < 4; k++) {
        int c = lane + k*32;
        float e = __expf(Am[r*ST + c] - rm);
        float ap = e * frv;
        Am[r*ST + c] = ap;
        rs += e;
        csump[k] += ap * gcv[k];
      }
      #pragma unroll
      for (int off = 16; off; off >>= 1) rs += __shfl_xor_sync(0xffffffffu, rs, off);
      if (lane == 0) rsc[r] = 1.f / rs;
    }
    #pragma unroll
    for (int k = 0; k < 4; k++) part[warp*128 + k*32 + lane] = csump[k];
  }
  __syncthreads();
  if (t < 128) {
    float s = 0.f;
    #pragma unroll
    for (int w = 0; w < 16; w++) s += part[w*128 + t];
    gcc[t] = gc[t] / s;
    rsc[t] = __fdividef(rsc[t], fr[t]);
  }
  __syncthreads();

  if (warp < 16) {
    int a0 = warp * 8;
    float acc0[8], acc1[8], acc2g[8];
    #pragma unroll
    for (int i = 0; i < 8; i++) { acc0[i]=0.f; acc1[i]=0.f; acc2g[i]=0.f; }
    #pragma unroll
    for (int vj = 0; vj < 4; vj++) {
      int v = lane + vj*32;
      float w = gcc[v];
      float e[10];
      #pragma unroll
      for (int i = 0; i < 10; i++) e[i] = (a0+i < 128) ? Am[(a0+i)*ST + v] : 0.f;
      #pragma unroll
      for (int i = 0; i < 8; i++) {
        float ew = e[i]*w;
        acc0[i] += ew*e[i];
        acc1[i] += ew*e[i+1];
        acc2g[i] += ew*e[i+2];
      }
    }
    #pragma unroll
    for (int i = 0; i < 8; i++) {
      #pragma unroll
      for (int off = 16; off; off >>= 1) {
        acc0[i]  += __shfl_xor_sync(0xffffffffu, acc0[i],  off);
        acc1[i]  += __shfl_xor_sync(0xffffffffu, acc1[i],  off);
        acc2g[i] += __shfl_xor_sync(0xffffffffu, acc2g[i], off);
      }
      if (lane == 0) {
        part[a0+i]       = acc0[i];
        part[128 + a0+i] = acc1[i];
        part[256 + a0+i] = acc2g[i];
      }
    }
  } else {
    int idx = warp - 16, cb = idx & 3, vc = idx >> 2;
    int c = cb*32 + lane;
    float h0 = 0.f, h1 = 0.f, h2 = 0.f;
    for (int v = vc*32; v < vc*32 + 32; v++) {
      float e = Am[v*ST + c];
      float e1 = __shfl_down_sync(0xffffffffu, e, 1);
      float e2 = __shfl_down_sync(0xffffffffu, e, 2);
      if (lane >= 30) e2 = (c+2 < 128) ? Am[v*ST + c + 2] : 0.f;
      if (lane == 31) e1 = (c+1 < 128) ? Am[v*ST + c + 1] : 0.f;
      float ew = e * rsc[v];
      h0 += ew*e; h1 += ew*e1; h2 += ew*e2;
    }
    ws[vc*384 + c]       = h0;
    ws[vc*384 + 128 + c] = h1;
    ws[vc*384 + 256 + c] = h2;
  }
  __syncthreads();

  if (t < 384) {
    part[384 + t] = ws[t] + ws[384+t] + ws[768+t] + ws[1152+t];
  } else if (t >= 512 && t < 640) {
    int u = t - 512;
    float accL = rsc[u]*part[u];
    if (u+1 < 128) accL += rsc[u+1]*part[128+u];
    if (u+2 < 128) accL += rsc[u+2]*part[256+u];
    if (u >= 1)    accL += rsc[u-1]*part[128+u-1];
    if (u >= 2)    accL += rsc[u-2]*part[256+u-2];
    Vl[u] = tanhf(5.f*accL);
  }
  __syncthreads();
  if (t < 128) {
    int u = t;
    float accR = gcc[u]*part[384+u];
    if (u+1 < 128) accR += gcc[u+1]*part[512+u];
    if (u+2 < 128) accR += gcc[u+2]*part[640+u];
    if (u >= 1)    accR += gcc[u-1]*part[512+u-1];
    if (u >= 2)    accR += gcc[u-2]*part[640+u-2];
    Vr[u] = tanhf(5.f*accR);
  }

  int group = t >> 9;
  int tid = t & 511;
  int c0 = (tid & 15)*4, u0 = (tid >> 4)*4;
  u64 acc2[4][2];
  #pragma unroll
  for (int i = 0; i < 4; i++) { acc2[i][0] = 0ull; acc2[i][1] = 0ull; }

  if (group == 0) {
    for (int v0g = 0; v0g < 128; v0g += 4) {
      ulonglong2 x0 = *(const ulonglong2*)&xrs[(v0g+0)*XST + c0];
      ulonglong2 x1 = *(const ulonglong2*)&xrs[(v0g+1)*XST + c0];
      ulonglong2 x2 = *(const ulonglong2*)&xrs[(v0g+2)*XST + c0];
      ulonglong2 x3 = *(const ulonglong2*)&xrs[(v0g+3)*XST + c0];
      #pragma unroll
      for (int i = 0; i < 4; i++) {
        float4 m = *(const float4*)&Am[(u0+i)*ST + v0g];
        u64 m0 = f2dup(m.x), m1 = f2dup(m.y), m2 = f2dup(m.z), m3 = f2dup(m.w);
        fma2(acc2[i][0], m0, x0.x); fma2(acc2[i][1], m0, x0.y);
        fma2(acc2[i][0], m1, x1.x); fma2(acc2[i][1], m1, x1.y);
        fma2(acc2[i][0], m2, x2.x); fma2(acc2[i][1], m2, x2.y);
        fma2(acc2[i][0], m3, x3.x); fma2(acc2[i][1], m3, x3.y);
      }
    }
  } else {
    for (int v = 0; v < 128; v++) {
      ulonglong2 xp = *(const ulonglong2*)&xls[v*XST + c0];
      float4 b0 = *(const float4*)&Am[v*ST + u0];
      u64 b0d = f2dup(b0.x), b1d = f2dup(b0.y), b2d = f2dup(b0.z), b3d = f2dup(b0.w);
      fma2(acc2[0][0], b0d, xp.x); fma2(acc2[0][1], b0d, xp.y);
      fma2(acc2[1][0], b1d, xp.x); fma2(acc2[1][1], b1d, xp.y);
      fma2(acc2[2][0], b2d, xp.x); fma2(acc2[2][1], b2d, xp.y);
      fma2(acc2[3][0], b3d, xp.x); fma2(acc2[3][1], b3d, xp.y);
    }
  }
  __syncthreads();

  if (group == 0) {
    #pragma unroll
    for (int i = 0; i < 4; i++) {
      int u = u0 + i;
      float vl = Vl[u];
      float gsc = vl * rsc[u];
      float2 f0 = f2up(acc2[i][0]), f1 = f2up(acc2[i][1]);
      float xt[4] = {f0.x, f0.y, f1.x, f1.y};
      #pragma unroll
      for (int cc = 0; cc < 4; cc++) {
        int x = u*XST + c0 + cc;
        xls[x] = xls[x]*(1.f - vl) + xt[cc]*gsc;
      }
    }
  } else {
    #pragma unroll
    for (int i = 0; i < 4; i++) {
      int u = u0 + i;
      float vr = Vr[u];
      float gsc = vr * gcc[u];
      float2 f0 = f2up(acc2[i][0]), f1 = f2up(acc2[i][1]);
      float xt[4] = {f0.x, f0.y, f1.x, f1.y};
      #pragma unroll
      for (int cc = 0; cc < 4; cc++) {
        int x = u*XST + c0 + cc;
        xrs[x] = xrs[x]*(1.f - vr) + xt[cc]*gsc;
      }
    }
  }
  __syncthreads();

  for (int i = t; i < 8192; i += 1024) {
    int c = i >> 7, u = i & 127;
    size_t gi = ((size_t)(b*NC + c)*NH + h)*NW + u;
    outL[gi] = xls[u*XST + c];
    outR[gi] = xrs[u*XST + c];
  }
}

// ---------------- host ------------------------------------------------------
extern "C" void kernel_launch(void* const* d_in, const int* in_sizes, int n_in,
                              void* d_out, int out_size) {
  const float* xL    = (const float*)d_in[0];
  const float* xR    = (const float*)d_in[1];
  const float* gamma = (const float*)d_in[2];
  const float* beta  = (const float*)d_in[3];
  const float* w1    = (const float*)d_in[4];
  const float* b1    = (const float*)d_in[5];
  const float* w2    = (const float*)d_in[6];
  const float* b2    = (const float*)d_in[7];
  const float* qw    = (const float*)d_in[8];
  const float* qb    = (const float*)d_in[9];
  const float* kw    = (const float*)d_in[10];
  const float* kb    = (const float*)d_in[11];
  float* outL = (float*)d_out;
  float* outR = outL + (size_t)IMG;

  float *t1, *t2;
  unsigned *wth, *wtl;
  cudaGetSymbolAddress((void**)&t1, g_t1);
  cudaGetSymbolAddress((void**)&t2, g_t2);
  cudaGetSymbolAddress((void**)&wth, g_wth);
  cudaGetSymbolAddress((void**)&wtl, g_wtl);

  cudaFuncSetAttribute(conv3x3_kernel<true>,  cudaFuncAttributeMaxDynamicSharedMemorySize, CONV_SMEM);
  cudaFuncSetAttribute(conv3x3_kernel<false>, cudaFuncAttributeMaxDynamicSharedMemorySize, CONV_SMEM);
  cudaFuncSetAttribute(attn_kernel, cudaFuncAttributeMaxDynamicSharedMemorySize, ATTN_SMEM);

  bn_stats_kernel<<<128, 256>>>(xL, xR, gamma, beta);
  wtrans_kernel<<<(2*NG*9*16*8 + 255)/256, 256>>>(w1, w2);

  dim3 cgrid(NH/4, NB*NG, 2);
  conv3x3_kernel<true ><<<cgrid, 256, CONV_SMEM>>>(
      xL, xR, t1, t2, wth, wtl, b1);
  conv3x3_kernel<false><<<cgrid, 256, CONV_SMEM>>>(
      xL, xR, t1, t2, wth + 4608, wtl + 4608, b2);

  attn_kernel<<<NROW, 1024, ATTN_SMEM>>>(t2, xL, xR, qw, qb, kw, kb, outL, outR);
}

// round 13
// speedup vs baseline: 1.4635x; 1.0868x over previous
#include <cuda_runtime.h>
#include <cuda_bf16.h>
#include <math.h>

#define NB 8
#define NC 64
#define NG 4
#define CG 16
#define NH 128
#define NW 128
#define HW (NH*NW)
#define IMG (NB*NC*HW)
#define NROW (NB*NH)

typedef unsigned long long u64;

__device__ __forceinline__ u64 f2dup(float v) {
  u64 r; asm("mov.b64 %0, {%1, %1};" : "=l"(r) : "f"(v)); return r;
}
__device__ __forceinline__ u64 f2pk(float a, float b) {
  u64 r; asm("mov.b64 %0, {%1, %2};" : "=l"(r) : "f"(a), "f"(b)); return r;
}
__device__ __forceinline__ void fma2(u64& d, u64 a, u64 b) {
  asm("fma.rn.f32x2 %0, %1, %2, %0;" : "+l"(d) : "l"(a), "l"(b));
}
__device__ __forceinline__ float2 f2up(u64 v) {
  float2 f; asm("mov.b64 {%0, %1}, %2;" : "=f"(f.x), "=f"(f.y) : "l"(v)); return f;
}
__device__ __forceinline__ void mma_bf16(
    float& d0, float& d1, float& d2, float& d3,
    unsigned a0, unsigned a1, unsigned a2, unsigned a3,
    unsigned b0, unsigned b1) {
  asm volatile(
    "mma.sync.aligned.m16n8k16.row.col.f32.bf16.bf16.f32 "
    "{%0,%1,%2,%3}, {%4,%5,%6,%7}, {%8,%9}, {%0,%1,%2,%3};"
    : "+f"(d0), "+f"(d1), "+f"(d2), "+f"(d3)
    : "r"(a0), "r"(a1), "r"(a2), "r"(a3), "r"(b0), "r"(b1));
}
__device__ __forceinline__ unsigned bfpk(__nv_bfloat16 a, __nv_bfloat16 b) {
  __nv_bfloat162 h = __halves2bfloat162(a, b);
  return *(unsigned*)&h;
}
__device__ __forceinline__ float2 upk(unsigned h, unsigned l) {
  __nv_bfloat162 hb = *(__nv_bfloat162*)&h;
  __nv_bfloat162 lb = *(__nv_bfloat162*)&l;
  return make_float2(__low2float(hb) + __low2float(lb),
                     __high2float(hb) + __high2float(lb));
}

// ---------------- scratch ----------------------------------------------------
__device__ float g_t1[2*(size_t)IMG];
__device__ float g_t2[2*(size_t)IMG];
__device__ float g_bnA[2][NC];
__device__ float g_bnB[2][NC];
__device__ __align__(16) unsigned g_wth[2][NG*9*16*8];
__device__ __align__(16) unsigned g_wtl[2][NG*9*16*8];

// ---------------- BN statistics ----------------------------------------------
__global__ __launch_bounds__(256) void bn_stats_kernel(
    const float* __restrict__ xl, const float* __restrict__ xr,
    const float* __restrict__ gamma, const float* __restrict__ beta) {
  int c = blockIdx.x & 63;
  int img = blockIdx.x >> 6;
  const float4* x = (const float4*)(img ? xr : xl);
  int t = threadIdx.x;
  float s = 0.f, s2 = 0.f;
  for (int b = 0; b < NB; b++) {
    const float4* p = x + (size_t)(b*NC + c)*(HW/4);
    for (int i = t; i < HW/4; i += 256) {
      float4 v = p[i];
      s  += v.x + v.y + v.z + v.w;
      s2 += v.x*v.x + v.y*v.y + v.z*v.z + v.w*v.w;
    }
  }
  __shared__ float sh[256], sh2[256];
  sh[t] = s; sh2[t] = s2; __syncthreads();
  for (int off = 128; off; off >>= 1) {
    if (t < off) { sh[t] += sh[t+off]; sh2[t] += sh2[t+off]; }
    __syncthreads();
  }
  if (t == 0) {
    const float inv = 1.f / (float)(NB*HW);
    float mean = sh[0] * inv;
    float var  = sh2[0] * inv - mean*mean;
    float a = gamma[c] * rsqrtf(var + 1e-5f);
    g_bnA[img][c] = a;
    g_bnB[img][c] = beta[c] - mean * a;
  }
}

// ---------------- weight prep (R12, kept) ------------------------------------
__global__ __launch_bounds__(256) void wtrans_kernel(
    const float* __restrict__ w1, const float* __restrict__ w2) {
  int i = blockIdx.x * 256 + threadIdx.x;
  if (i >= 2*NG*9*16*8) return;
  int layer = i / 4608;
  int j = i - layer*4608;
  int g = j / 1152;
  int r = j - g*1152;
  int khkw = r >> 7;
  int q = r & 127;
  int oc = q >> 3, p = q & 7;
  const float* src = layer ? w2 : w1;
  int base = g*(CG*CG*9) + oc*(CG*9) + (2*p)*9 + khkw;
  float w0 = src[base], w1v = src[base + 9];
  __nv_bfloat16 h0 = __float2bfloat16(w0);
  __nv_bfloat16 h1 = __float2bfloat16(w1v);
  g_wth[layer][j] = bfpk(h0, h1);
  g_wtl[layer][j] = bfpk(__float2bfloat16(w0 - __bfloat162float(h0)),
                         __float2bfloat16(w1v - __bfloat162float(h1)));
}

// ---------------- grouped 3x3 conv (R12, kept: 76.8us) -----------------------
#define PRST 136
#define ROWST (8*PRST)
#define CIN_U32 (6*ROWST)
#define CONV_SMEM (2*CIN_U32*4)

template<bool FIRST>
__global__ __launch_bounds__(256, 3) void conv3x3_kernel(
    const float* __restrict__ xL, const float* __restrict__ xR,
    float* __restrict__ t1, float* __restrict__ t2,
    const unsigned* __restrict__ wth, const unsigned* __restrict__ wtl,
    const float* __restrict__ bias) {
  extern __shared__ unsigned smu[];
  unsigned* in_hi = smu;
  unsigned* in_lo = smu + CIN_U32;
  int t = threadIdx.x;
  int img = blockIdx.z;
  int b = blockIdx.y >> 2, grp = blockIdx.y & 3;
  int h0 = blockIdx.x * 4;
  const float* xorig = img ? xR : xL;
  const float* xin = FIRST ? xorig : (t1 + (size_t)img*IMG);
  float* out = (FIRST ? t1 : t2) + (size_t)img*IMG;

  for (int i = t; i < CIN_U32; i += 256) {
    int col  = i % PRST;
    int rest = i / PRST;
    int pair = rest & 7;
    int row  = rest >> 3;
    int hh = h0 - 1 + row;
    int ww = col - 1;
    float v0 = 0.f, v1 = 0.f;
    if ((unsigned)hh < (unsigned)NH && (unsigned)ww < (unsigned)NW) {
      int ch = grp*CG + 2*pair;
      size_t gidx = ((size_t)(b*NC + ch)*NH + hh)*NW + ww;
      v0 = xin[gidx];
      v1 = xin[gidx + HW];
      if (FIRST) {
        v0 = g_bnA[img][ch]*v0 + g_bnB[img][ch];
        v1 = g_bnA[img][ch+1]*v1 + g_bnB[img][ch+1];
      }
    }
    __nv_bfloat16 h0b = __float2bfloat16(v0);
    __nv_bfloat16 h1b = __float2bfloat16(v1);
    in_hi[i] = bfpk(h0b, h1b);
    in_lo[i] = bfpk(__float2bfloat16(v0 - __bfloat162float(h0b)),
                    __float2bfloat16(v1 - __bfloat162float(h1b)));
  }
  __syncthreads();

  int warp = t >> 5, lane = t & 31;
  int gr = lane >> 2, tig = lane & 3;
  int hh = warp >> 1;
  int wbase = (warp & 1) * 64;

  const unsigned* whg = wth + grp*(9*128);
  const unsigned* wlg = wtl + grp*(9*128);

  float d[8][4];
  #pragma unroll
  for (int nt = 0; nt < 8; nt++)
    d[nt][0] = d[nt][1] = d[nt][2] = d[nt][3] = 0.f;

  #pragma unroll
  for (int khkw = 0; khkw < 9; khkw++) {
    const int kh = khkw / 3, kw = khkw % 3;
    const unsigned* wh = whg + khkw*128;
    const unsigned* wl = wlg + khkw*128;
    unsigned ah0 = __ldg(wh + gr*8 + tig);
    unsigned ah1 = __ldg(wh + gr*8 + tig + 64);
    unsigned ah2 = __ldg(wh + gr*8 + tig + 4);
    unsigned ah3 = __ldg(wh + gr*8 + tig + 68);
    unsigned al0 = __ldg(wl + gr*8 + tig);
    unsigned al1 = __ldg(wl + gr*8 + tig + 64);
    unsigned al2 = __ldg(wl + gr*8 + tig + 4);
    unsigned al3 = __ldg(wl + gr*8 + tig + 68);
    int base_in = (hh + kh)*ROWST + tig*PRST + wbase + kw + gr;
    #pragma unroll
    for (int nt = 0; nt < 8; nt++) {
      int coln = base_in + nt*8;
      unsigned bh0 = in_hi[coln];
      unsigned bh1 = in_hi[coln + 4*PRST];
      unsigned bl0 = in_lo[coln];
      unsigned bl1 = in_lo[coln + 4*PRST];
      mma_bf16(d[nt][0],d[nt][1],d[nt][2],d[nt][3], al0,al1,al2,al3, bh0,bh1);
      mma_bf16(d[nt][0],d[nt][1],d[nt][2],d[nt][3], ah0,ah1,ah2,ah3, bl0,bl1);
      mma_bf16(d[nt][0],d[nt][1],d[nt][2],d[nt][3], ah0,ah1,ah2,ah3, bh0,bh1);
    }
  }

  int hout = h0 + hh;
  int ch0 = grp*CG + gr;
  int ch1 = ch0 + 8;
  float bz0 = bias[ch0], bz1 = bias[ch1];
  float ra0 = 0.f, rb0 = 0.f, ra1 = 0.f, rb1 = 0.f;
  if (!FIRST) {
    ra0 = g_bnA[img][ch0]; rb0 = g_bnB[img][ch0];
    ra1 = g_bnA[img][ch1]; rb1 = g_bnB[img][ch1];
  }
  size_t base0 = ((size_t)(b*NC + ch0)*NH + hout)*NW;
  size_t base1 = ((size_t)(b*NC + ch1)*NH + hout)*NW;
  #pragma unroll
  for (int nt = 0; nt < 8; nt++) {
    int w2c = wbase + nt*8 + 2*tig;
    float v0 = d[nt][0] + bz0, v1 = d[nt][1] + bz0;
    float v2 = d[nt][2] + bz1, v3 = d[nt][3] + bz1;
    if (FIRST) {
      v0 = v0 > 0.f ? v0 : 0.1f*v0;
      v1 = v1 > 0.f ? v1 : 0.1f*v1;
      v2 = v2 > 0.f ? v2 : 0.1f*v2;
      v3 = v3 > 0.f ? v3 : 0.1f*v3;
    } else {
      float2 x0 = *(const float2*)&xorig[base0 + w2c];
      float2 x1 = *(const float2*)&xorig[base1 + w2c];
      v0 += ra0*x0.x + rb0;  v1 += ra0*x0.y + rb0;
      v2 += ra1*x1.x + rb1;  v3 += ra1*x1.y + rb1;
    }
    *(float2*)&out[base0 + w2c] = make_float2(v0, v1);
    *(float2*)&out[base1 + w2c] = make_float2(v2, v3);
  }
}

// ---------------- fused attention: bf16 mma GEMM2/3 --------------------------
#define ST 128
#define A2ST 66
#define ATST 66
#define XPST 66
#define OFF_XLP_H 0
#define OFF_XLP_L 4224
#define OFF_XRP_H 8448
#define OFF_XRP_L 12672
#define OFF_QK    16384
#define OFF_A2H   16896
#define OFF_A2L   25344
#define OFF_ATH   33792
#define OFF_ATL   42240
#define OFF_WS    50688
#define OFF_BS    52736
#define OFF_RMAX  52864
#define OFF_RSC   52992
#define OFF_CMAX  53120
#define OFF_GCC   53248
#define OFF_VL    53376
#define OFF_VR    53504
#define OFF_PART  53632
#define OFF_FR    55680
#define OFF_GC    55808
#define OFF_MG    55936
#define ATTN_SMEM ((55936 + 32)*4)   // 223872 B

__global__ __launch_bounds__(1024, 1) void attn_kernel(
    const float* __restrict__ t2, const float* __restrict__ xL,
    const float* __restrict__ xR,
    const float* __restrict__ qw, const float* __restrict__ qb,
    const float* __restrict__ kw_, const float* __restrict__ kb,
    float* __restrict__ outL, float* __restrict__ outR) {
  extern __shared__ float sm[];
  float* Sb    = sm;                 // t2 stage -> S
  float* qk    = sm + OFF_QK;
  unsigned* A2h = (unsigned*)(sm + OFF_A2H);
  unsigned* A2l = (unsigned*)(sm + OFF_A2L);
  unsigned* Ath = (unsigned*)(sm + OFF_ATH);
  unsigned* Atl = (unsigned*)(sm + OFF_ATL);
  float* ws    = sm + OFF_WS;
  float* bs    = sm + OFF_BS;
  float* rmax  = sm + OFF_RMAX;
  float* rsc   = sm + OFF_RSC;
  float* cmax  = sm + OFF_CMAX;
  float* gcc   = sm + OFF_GCC;
  float* Vl    = sm + OFF_VL;
  float* Vr    = sm + OFF_VR;
  float* part  = sm + OFF_PART;
  float* fr    = sm + OFF_FR;
  float* gc    = sm + OFF_GC;
  float* Mg    = sm + OFF_MG;
  int n = blockIdx.x, b = n >> 7, h = n & 127;
  int t = threadIdx.x, warp = t >> 5, lane = t & 31;
  int g = lane >> 2, tig = lane & 3;

  // 1. stage weights/bias + t2 rows
  for (int i = t; i < 2048; i += 1024) ws[i] = (i < 1024) ? qw[i] : kw_[i-1024];
  if (t < 128) bs[t] = (t < 64) ? qb[t] : kb[t-64];
  for (int i = t; i < 16384; i += 1024) {
    int c = i >> 7, u = i & 127;
    size_t gi = ((c >= 64) ? (size_t)IMG : 0) +
                ((size_t)(b*NC + (c & 63))*NH + h)*NW + u;
    Sb[c*ST + u] = t2[gi];
  }
  __syncthreads();

  // 2. 1x1 grouped conv: qk[k][u]
  for (int i = t; i < 8192; i += 1024) {
    int k = i >> 6, up = (i & 63)*2;
    int cb = (k >> 4) * 16;
    float bzv = bs[k];
    u64 a = f2pk(bzv, bzv);
    #pragma unroll
    for (int ic = 0; ic < 16; ic++) {
      u64 w2 = f2dup(ws[k*16 + ic]);
      u64 xp = *(const u64*)&Sb[(cb + ic)*ST + up];
      fma2(a, w2, xp);
    }
    *(u64*)&qk[k*ST + up] = a;
  }
  __syncthreads();

  // 3. row-mean subtract
  for (int r = warp; r < 128; r += 32) {
    float s = 0.f;
    for (int u = lane; u < 128; u += 32) s += qk[r*ST + u];
    #pragma unroll
    for (int off = 16; off; off >>= 1) s += __shfl_xor_sync(0xffffffffu, s, off);
    float mean = s * (1.f/128.f);
    for (int u = lane; u < 128; u += 32) qk[r*ST + u] -= mean;
  }
  __syncthreads();

  // 4. GEMM1 (f32x2) + fused maxes -> S in Sb
  int g1u0 = warp * 4, g1v0 = lane * 4;
  float cmv[4] = {-1e30f, -1e30f, -1e30f, -1e30f};
  {
    u64 acc2[4][2];
    #pragma unroll
    for (int i = 0; i < 4; i++) { acc2[i][0] = 0ull; acc2[i][1] = 0ull; }
    for (int k = 0; k < 64; k++) {
      float4 qv = *(const float4*)&qk[k*ST + g1u0];
      ulonglong2 kv = *(const ulonglong2*)&qk[(64+k)*ST + g1v0];
      u64 q0 = f2dup(qv.x), q1 = f2dup(qv.y), q2 = f2dup(qv.z), q3 = f2dup(qv.w);
      fma2(acc2[0][0], q0, kv.x); fma2(acc2[0][1], q0, kv.y);
      fma2(acc2[1][0], q1, kv.x); fma2(acc2[1][1], q1, kv.y);
      fma2(acc2[2][0], q2, kv.x); fma2(acc2[2][1], q2, kv.y);
      fma2(acc2[3][0], q3, kv.x); fma2(acc2[3][1], q3, kv.y);
    }
    #pragma unroll
    for (int i = 0; i < 4; i++) {
      float2 a = f2up(acc2[i][0]), c2 = f2up(acc2[i][1]);
      *(float4*)&Sb[(g1u0+i)*ST + g1v0] = make_float4(a.x,a.y,c2.x,c2.y);
      float rm = fmaxf(fmaxf(a.x, a.y), fmaxf(c2.x, c2.y));
      #pragma unroll
      for (int off = 16; off; off >>= 1) rm = fmaxf(rm, __shfl_xor_sync(0xffffffffu, rm, off));
      if (lane == 0) rmax[g1u0+i] = rm;
      cmv[0] = fmaxf(cmv[0], a.x);  cmv[1] = fmaxf(cmv[1], a.y);
      cmv[2] = fmaxf(cmv[2], c2.x); cmv[3] = fmaxf(cmv[3], c2.y);
    }
    if (warp < 16)
      *(float4*)&part[warp*128 + g1v0] = make_float4(cmv[0],cmv[1],cmv[2],cmv[3]);
  }
  __syncthreads();
  if (warp >= 16) {
    float4 old = *(const float4*)&part[(warp-16)*128 + g1v0];
    old.x = fmaxf(old.x, cmv[0]); old.y = fmaxf(old.y, cmv[1]);
    old.z = fmaxf(old.z, cmv[2]); old.w = fmaxf(old.w, cmv[3]);
    *(float4*)&part[(warp-16)*128 + g1v0] = old;
  }
  __syncthreads();

  // 5. cmax combine + global max + factors
  if (t < 128) {
    float m = -1e30f;
    #pragma unroll
    for (int k2 = 0; k2 < 16; k2++) m = fmaxf(m, part[k2*128 + t]);
    cmax[t] = m;
  } else if (t < 160) {
    int l = t - 128;
    float m = fmaxf(fmaxf(rmax[l], rmax[l+32]), fmaxf(rmax[l+64], rmax[l+96]));
    #pragma unroll
    for (int off = 16; off; off >>= 1) m = fmaxf(m, __shfl_xor_sync(0xffffffffu, m, off));
    if (l == 0) Mg[0] = m;
  }
  __syncthreads();
  if (t < 128) {
    float M = Mg[0];
    fr[t] = __expf(rmax[t] - M);
    gc[t] = __expf(M - cmax[t]);
  }
  __syncthreads();

  // 6. exp + A2/At bf16 hi/lo packing + row sums + col-sum partials
  if (warp < 16) {
    int cA = 2*lane, cB = cA + 64;
    float g0 = gc[cA], g1v = gc[cA+1], g2 = gc[cB], g3 = gc[cB+1];
    float cs0=0.f, cs1=0.f, cs2=0.f, cs3=0.f;
    float p0=0.f, p1=0.f, p2=0.f, p3=0.f;
    #pragma unroll
    for (int rr = 0; rr < 8; rr++) {
      int r = warp*8 + rr;
      float rm = rmax[r], frv = fr[r];
      float2 sA = *(const float2*)&Sb[r*ST + cA];
      float2 sB = *(const float2*)&Sb[r*ST + cB];
      float e0 = __expf(sA.x - rm), e1 = __expf(sA.y - rm);
      float e2 = __expf(sB.x - rm), e3 = __expf(sB.y - rm);
      float rs = e0 + e1 + e2 + e3;
      float a0 = e0*frv, a1 = e1*frv, a2 = e2*frv, a3 = e3*frv;
      cs0 += a0*g0; cs1 += a1*g1v; cs2 += a2*g2; cs3 += a3*g3;
      __nv_bfloat16 h0 = __float2bfloat16(a0), h1 = __float2bfloat16(a1);
      __nv_bfloat16 h2 = __float2bfloat16(a2), h3 = __float2bfloat16(a3);
      A2h[r*A2ST + lane]      = bfpk(h0, h1);
      A2l[r*A2ST + lane]      = bfpk(__float2bfloat16(a0 - __bfloat162float(h0)),
                                     __float2bfloat16(a1 - __bfloat162float(h1)));
      A2h[r*A2ST + lane + 32] = bfpk(h2, h3);
      A2l[r*A2ST + lane + 32] = bfpk(__float2bfloat16(a2 - __bfloat162float(h2)),
                                     __float2bfloat16(a3 - __bfloat162float(h3)));
      if (rr & 1) {
        int vp = warp*4 + (rr >> 1);
        __nv_bfloat16 q0 = __float2bfloat16(p0), q1 = __float2bfloat16(p1);
        __nv_bfloat16 q2 = __float2bfloat16(p2), q3 = __float2bfloat16(p3);
        Ath[cA*ATST + vp]     = bfpk(q0, h0);
        Atl[cA*ATST + vp]     = bfpk(__float2bfloat16(p0 - __bfloat162float(q0)),
                                     __float2bfloat16(a0 - __bfloat162float(h0)));
        Ath[(cA+1)*ATST + vp] = bfpk(q1, h1);
        Atl[(cA+1)*ATST + vp] = bfpk(__float2bfloat16(p1 - __bfloat162float(q1)),
                                     __float2bfloat16(a1 - __bfloat162float(h1)));
        Ath[cB*ATST + vp]     = bfpk(q2, h2);
        Atl[cB*ATST + vp]     = bfpk(__float2bfloat16(p2 - __bfloat162float(q2)),
                                     __float2bfloat16(a2 - __bfloat162float(h2)));
        Ath[(cB+1)*ATST + vp] = bfpk(q3, h3);
        Atl[(cB+1)*ATST + vp] = bfpk(__float2bfloat16(p3 - __bfloat162float(q3)),
                                     __float2bfloat16(a3 - __bfloat162float(h3)));
      } else { p0 = a0; p1 = a1; p2 = a2; p3 = a3; }
      #pragma unroll
      for (int off = 16; off; off >>= 1) rs += __shfl_xor_sync(0xffffffffu, rs, off);
      if (lane == 0) rsc[r] = 1.f / rs;
    }
    part[warp*128 + cA]   = cs0;
    part[warp*128 + cA+1] = cs1;
    part[warp*128 + cB]   = cs2;
    part[warp*128 + cB+1] = cs3;
  }
  __syncthreads();
  if (t < 128) {
    float s = 0.f;
    #pragma unroll
    for (int w = 0; w < 16; w++) s += part[w*128 + t];
    gcc[t] = gc[t] / s;
    rsc[t] = __fdividef(rsc[t], fr[t]);
  }
  __syncthreads();

  // 7. banded Grams: G from A2 (gcc weights), H from At (rsc weights)
  {
    bool isG = warp < 16;
    const unsigned* Ph = isG ? A2h : Ath;
    const unsigned* Pl = isG ? A2l : Atl;
    const float* wv = isG ? gcc : rsc;
    int stp = isG ? A2ST : ATST;
    int base = (warp & 15) * 8;
    float acc0[8], acc1[8], acc2g[8];
    #pragma unroll
    for (int i = 0; i < 8; i++) { acc0[i]=0.f; acc1[i]=0.f; acc2g[i]=0.f; }
    #pragma unroll
    for (int vj = 0; vj < 2; vj++) {
      int vp = vj*32 + lane;
      float w0 = wv[2*vp], w1 = wv[2*vp+1];
      float2 e0v = upk(Ph[base*stp + vp], Pl[base*stp + vp]);
      float2 e1v = upk(Ph[(base+1)*stp + vp], Pl[(base+1)*stp + vp]);
      #pragma unroll
      for (int i = 0; i < 8; i++) {
        int rn = base + i + 2;
        float2 e2v = (rn < 128) ? upk(Ph[rn*stp + vp], Pl[rn*stp + vp])
                                : make_float2(0.f, 0.f);
        acc0[i]  += e0v.x*w0*e0v.x + e0v.y*w1*e0v.y;
        acc1[i]  += e0v.x*w0*e1v.x + e0v.y*w1*e1v.y;
        acc2g[i] += e0v.x*w0*e2v.x + e0v.y*w1*e2v.y;
        e0v = e1v; e1v = e2v;
      }
    }
    int po = isG ? 0 : 384;
    #pragma unroll
    for (int i = 0; i < 8; i++) {
      #pragma unroll
      for (int off = 16; off; off >>= 1) {
        acc0[i]  += __shfl_xor_sync(0xffffffffu, acc0[i],  off);
        acc1[i]  += __shfl_xor_sync(0xffffffffu, acc1[i],  off);
        acc2g[i] += __shfl_xor_sync(0xffffffffu, acc2g[i], off);
      }
      if (lane == 0) {
        part[po + base+i]       = acc0[i];
        part[po + 128 + base+i] = acc1[i];
        part[po + 256 + base+i] = acc2g[i];
      }
    }
  }
  __syncthreads();

  // 8. x bf16 packing + V maps
  for (int i = t; i < 8192; i += 1024) {
    int img = i >> 12, j = i & 4095, c = j >> 6, vp = j & 63;
    const float* src = img ? xR : xL;
    float2 v = *(const float2*)&src[((size_t)(b*NC + c)*NH + h)*NW + 2*vp];
    unsigned* ph = (unsigned*)(sm + (img ? OFF_XRP_H : OFF_XLP_H));
    unsigned* pl = (unsigned*)(sm + (img ? OFF_XRP_L : OFF_XLP_L));
    __nv_bfloat16 h0 = __float2bfloat16(v.x), h1 = __float2bfloat16(v.y);
    ph[c*XPST + vp] = bfpk(h0, h1);
    pl[c*XPST + vp] = bfpk(__float2bfloat16(v.x - __bfloat162float(h0)),
                           __float2bfloat16(v.y - __bfloat162float(h1)));
  }
  if (t < 128) {
    int u = t;
    float accL = rsc[u]*part[u];
    if (u+1 < 128) accL += rsc[u+1]*part[128+u];
    if (u+2 < 128) accL += rsc[u+2]*part[256+u];
    if (u >= 1)    accL += rsc[u-1]*part[128+u-1];
    if (u >= 2)    accL += rsc[u-2]*part[256+u-2];
    Vl[u] = tanhf(5.f*accL);
  } else if (t < 256) {
    int u = t - 128;
    float accR = gcc[u]*part[384+u];
    if (u+1 < 128) accR += gcc[u+1]*part[512+u];
    if (u+2 < 128) accR += gcc[u+2]*part[640+u];
    if (u >= 1)    accR += gcc[u-1]*part[512+u-1];
    if (u >= 2)    accR += gcc[u-2]*part[640+u-2];
    Vr[u] = tanhf(5.f*accR);
  }
  __syncthreads();

  // 9. GEMM2 (warps 0-15, left) / GEMM3 (warps 16-31, right) via bf16 mma
  {
    bool left = warp < 16;
    int gw = warp & 15;
    int u0 = (gw >> 1) * 16, nb = (gw & 1) * 32;
    const unsigned* Ah = left ? A2h : Ath;
    const unsigned* Al = left ? A2l : Atl;
    const unsigned* Bh = (const unsigned*)(sm + (left ? OFF_XRP_H : OFF_XLP_H));
    const unsigned* Bl = (const unsigned*)(sm + (left ? OFF_XRP_L : OFF_XLP_L));
    float d[4][4];
    #pragma unroll
    for (int j = 0; j < 4; j++)
      d[j][0] = d[j][1] = d[j][2] = d[j][3] = 0.f;
    for (int ks = 0; ks < 8; ks++) {
      int vp = ks*8 + tig;
      int ra = (u0+g)*A2ST + vp, rb = (u0+g+8)*A2ST + vp;
      unsigned ah0 = Ah[ra],   ah1 = Ah[rb];
      unsigned ah2 = Ah[ra+4], ah3 = Ah[rb+4];
      unsigned al0 = Al[ra],   al1 = Al[rb];
      unsigned al2 = Al[ra+4], al3 = Al[rb+4];
      #pragma unroll
      for (int j = 0; j < 4; j++) {
        int ci = (nb + j*8 + g)*XPST + vp;
        unsigned bh0 = Bh[ci], bh1 = Bh[ci+4];
        unsigned bl0 = Bl[ci], bl1 = Bl[ci+4];
        mma_bf16(d[j][0],d[j][1],d[j][2],d[j][3], al0,al1,al2,al3, bh0,bh1);
        mma_bf16(d[j][0],d[j][1],d[j][2],d[j][3], ah0,ah1,ah2,ah3, bl0,bl1);
        mma_bf16(d[j][0],d[j][1],d[j][2],d[j][3], ah0,ah1,ah2,ah3, bh0,bh1);
      }
    }
    const float* xg = left ? xL : xR;
    float* og = left ? outL : outR;
    const float* Vv = left ? Vl : Vr;
    const float* scv = left ? rsc : gcc;
    int ua = u0 + g, ub = u0 + g + 8;
    float va = Vv[ua], vb = Vv[ub];
    float sa = scv[ua]*va, sb2 = scv[ub]*vb;
    float ia = 1.f - va, ib = 1.f - vb;
    #pragma unroll
    for (int j = 0; j < 4; j++) {
      int c = nb + j*8 + 2*tig;
      size_t b0i = ((size_t)(b*NC + c)*NH + h)*NW;
      size_t b1i = b0i + (size_t)HW;
      og[b0i + ua] = xg[b0i + ua]*ia + d[j][0]*sa;
      og[b1i + ua] = xg[b1i + ua]*ia + d[j][1]*sa;
      og[b0i + ub] = xg[b0i + ub]*ib + d[j][2]*sb2;
      og[b1i + ub] = xg[b1i + ub]*ib + d[j][3]*sb2;
    }
  }
}

// ---------------- host ------------------------------------------------------
extern "C" void kernel_launch(void* const* d_in, const int* in_sizes, int n_in,
                              void* d_out, int out_size) {
  const float* xL    = (const float*)d_in[0];
  const float* xR    = (const float*)d_in[1];
  const float* gamma = (const float*)d_in[2];
  const float* beta  = (const float*)d_in[3];
  const float* w1    = (const float*)d_in[4];
  const float* b1    = (const float*)d_in[5];
  const float* w2    = (const float*)d_in[6];
  const float* b2    = (const float*)d_in[7];
  const float* qw    = (const float*)d_in[8];
  const float* qb    = (const float*)d_in[9];
  const float* kw    = (const float*)d_in[10];
  const float* kb    = (const float*)d_in[11];
  float* outL = (float*)d_out;
  float* outR = outL + (size_t)IMG;

  float *t1, *t2;
  unsigned *wth, *wtl;
  cudaGetSymbolAddress((void**)&t1, g_t1);
  cudaGetSymbolAddress((void**)&t2, g_t2);
  cudaGetSymbolAddress((void**)&wth, g_wth);
  cudaGetSymbolAddress((void**)&wtl, g_wtl);

  cudaFuncSetAttribute(conv3x3_kernel<true>,  cudaFuncAttributeMaxDynamicSharedMemorySize, CONV_SMEM);
  cudaFuncSetAttribute(conv3x3_kernel<false>, cudaFuncAttributeMaxDynamicSharedMemorySize, CONV_SMEM);
  cudaFuncSetAttribute(attn_kernel, cudaFuncAttributeMaxDynamicSharedMemorySize, ATTN_SMEM);

  bn_stats_kernel<<<128, 256>>>(xL, xR, gamma, beta);
  wtrans_kernel<<<(2*NG*9*16*8 + 255)/256, 256>>>(w1, w2);

  dim3 cgrid(NH/4, NB*NG, 2);
  conv3x3_kernel<true ><<<cgrid, 256, CONV_SMEM>>>(
      xL, xR, t1, t2, wth, wtl, b1);
  conv3x3_kernel<false><<<cgrid, 256, CONV_SMEM>>>(
      xL, xR, t1, t2, wth + 4608, wtl + 4608, b2);

  attn_kernel<<<NROW, 1024, ATTN_SMEM>>>(t2, xL, xR, qw, qb, kw, kb, outL, outR);
}

// round 14
// speedup vs baseline: 1.4742x; 1.0073x over previous
#include <cuda_runtime.h>
#include <cuda_bf16.h>
#include <math.h>

#define NB 8
#define NC 64
#define NG 4
#define CG 16
#define NH 128
#define NW 128
#define HW (NH*NW)
#define IMG (NB*NC*HW)
#define NROW (NB*NH)

typedef unsigned long long u64;

__device__ __forceinline__ u64 f2dup(float v) {
  u64 r; asm("mov.b64 %0, {%1, %1};" : "=l"(r) : "f"(v)); return r;
}
__device__ __forceinline__ u64 f2pk(float a, float b) {
  u64 r; asm("mov.b64 %0, {%1, %2};" : "=l"(r) : "f"(a), "f"(b)); return r;
}
__device__ __forceinline__ void fma2(u64& d, u64 a, u64 b) {
  asm("fma.rn.f32x2 %0, %1, %2, %0;" : "+l"(d) : "l"(a), "l"(b));
}
__device__ __forceinline__ float2 f2up(u64 v) {
  float2 f; asm("mov.b64 {%0, %1}, %2;" : "=f"(f.x), "=f"(f.y) : "l"(v)); return f;
}
__device__ __forceinline__ void mma_bf16(
    float& d0, float& d1, float& d2, float& d3,
    unsigned a0, unsigned a1, unsigned a2, unsigned a3,
    unsigned b0, unsigned b1) {
  asm volatile(
    "mma.sync.aligned.m16n8k16.row.col.f32.bf16.bf16.f32 "
    "{%0,%1,%2,%3}, {%4,%5,%6,%7}, {%8,%9}, {%0,%1,%2,%3};"
    : "+f"(d0), "+f"(d1), "+f"(d2), "+f"(d3)
    : "r"(a0), "r"(a1), "r"(a2), "r"(a3), "r"(b0), "r"(b1));
}
__device__ __forceinline__ unsigned bfpk(__nv_bfloat16 a, __nv_bfloat16 b) {
  __nv_bfloat162 h = __halves2bfloat162(a, b);
  return *(unsigned*)&h;
}
__device__ __forceinline__ unsigned bfsplit(float a, float b, unsigned& lo) {
  __nv_bfloat16 ha = __float2bfloat16(a), hb = __float2bfloat16(b);
  lo = bfpk(__float2bfloat16(a - __bfloat162float(ha)),
            __float2bfloat16(b - __bfloat162float(hb)));
  return bfpk(ha, hb);
}
__device__ __forceinline__ float2 upk(unsigned h, unsigned l) {
  __nv_bfloat162 hb = *(__nv_bfloat162*)&h;
  __nv_bfloat162 lb = *(__nv_bfloat162*)&l;
  return make_float2(__low2float(hb) + __low2float(lb),
                     __high2float(hb) + __high2float(lb));
}

// ---------------- scratch ----------------------------------------------------
__device__ float g_t1[2*(size_t)IMG];
__device__ float g_t2[2*(size_t)IMG];
__device__ float g_bnA[2][NC];
__device__ float g_bnB[2][NC];
__device__ __align__(16) unsigned g_wth[2][NG*9*16*8];
__device__ __align__(16) unsigned g_wtl[2][NG*9*16*8];

// ---------------- BN statistics ----------------------------------------------
__global__ __launch_bounds__(256) void bn_stats_kernel(
    const float* __restrict__ xl, const float* __restrict__ xr,
    const float* __restrict__ gamma, const float* __restrict__ beta) {
  int c = blockIdx.x & 63;
  int img = blockIdx.x >> 6;
  const float4* x = (const float4*)(img ? xr : xl);
  int t = threadIdx.x;
  float s = 0.f, s2 = 0.f;
  for (int b = 0; b < NB; b++) {
    const float4* p = x + (size_t)(b*NC + c)*(HW/4);
    for (int i = t; i < HW/4; i += 256) {
      float4 v = p[i];
      s  += v.x + v.y + v.z + v.w;
      s2 += v.x*v.x + v.y*v.y + v.z*v.z + v.w*v.w;
    }
  }
  __shared__ float sh[256], sh2[256];
  sh[t] = s; sh2[t] = s2; __syncthreads();
  for (int off = 128; off; off >>= 1) {
    if (t < off) { sh[t] += sh[t+off]; sh2[t] += sh2[t+off]; }
    __syncthreads();
  }
  if (t == 0) {
    const float inv = 1.f / (float)(NB*HW);
    float mean = sh[0] * inv;
    float var  = sh2[0] * inv - mean*mean;
    float a = gamma[c] * rsqrtf(var + 1e-5f);
    g_bnA[img][c] = a;
    g_bnB[img][c] = beta[c] - mean * a;
  }
}

// ---------------- weight prep (kept) ------------------------------------------
__global__ __launch_bounds__(256) void wtrans_kernel(
    const float* __restrict__ w1, const float* __restrict__ w2) {
  int i = blockIdx.x * 256 + threadIdx.x;
  if (i >= 2*NG*9*16*8) return;
  int layer = i / 4608;
  int j = i - layer*4608;
  int g = j / 1152;
  int r = j - g*1152;
  int khkw = r >> 7;
  int q = r & 127;
  int oc = q >> 3, p = q & 7;
  const float* src = layer ? w2 : w1;
  int base = g*(CG*CG*9) + oc*(CG*9) + (2*p)*9 + khkw;
  float w0 = src[base], w1v = src[base + 9];
  unsigned lo;
  g_wth[layer][j] = bfsplit(w0, w1v, lo);
  g_wtl[layer][j] = lo;
}

// ---------------- grouped 3x3 conv (R12, kept: 76.8us) -----------------------
#define PRST 136
#define ROWST (8*PRST)
#define CIN_U32 (6*ROWST)
#define CONV_SMEM (2*CIN_U32*4)

template<bool FIRST>
__global__ __launch_bounds__(256, 3) void conv3x3_kernel(
    const float* __restrict__ xL, const float* __restrict__ xR,
    float* __restrict__ t1, float* __restrict__ t2,
    const unsigned* __restrict__ wth, const unsigned* __restrict__ wtl,
    const float* __restrict__ bias) {
  extern __shared__ unsigned smu[];
  unsigned* in_hi = smu;
  unsigned* in_lo = smu + CIN_U32;
  int t = threadIdx.x;
  int img = blockIdx.z;
  int b = blockIdx.y >> 2, grp = blockIdx.y & 3;
  int h0 = blockIdx.x * 4;
  const float* xorig = img ? xR : xL;
  const float* xin = FIRST ? xorig : (t1 + (size_t)img*IMG);
  float* out = (FIRST ? t1 : t2) + (size_t)img*IMG;

  for (int i = t; i < CIN_U32; i += 256) {
    int col  = i % PRST;
    int rest = i / PRST;
    int pair = rest & 7;
    int row  = rest >> 3;
    int hh = h0 - 1 + row;
    int ww = col - 1;
    float v0 = 0.f, v1 = 0.f;
    if ((unsigned)hh < (unsigned)NH && (unsigned)ww < (unsigned)NW) {
      int ch = grp*CG + 2*pair;
      size_t gidx = ((size_t)(b*NC + ch)*NH + hh)*NW + ww;
      v0 = xin[gidx];
      v1 = xin[gidx + HW];
      if (FIRST) {
        v0 = g_bnA[img][ch]*v0 + g_bnB[img][ch];
        v1 = g_bnA[img][ch+1]*v1 + g_bnB[img][ch+1];
      }
    }
    unsigned lo;
    in_hi[i] = bfsplit(v0, v1, lo);
    in_lo[i] = lo;
  }
  __syncthreads();

  int warp = t >> 5, lane = t & 31;
  int gr = lane >> 2, tig = lane & 3;
  int hh = warp >> 1;
  int wbase = (warp & 1) * 64;

  const unsigned* whg = wth + grp*(9*128);
  const unsigned* wlg = wtl + grp*(9*128);

  float d[8][4];
  #pragma unroll
  for (int nt = 0; nt < 8; nt++)
    d[nt][0] = d[nt][1] = d[nt][2] = d[nt][3] = 0.f;

  #pragma unroll
  for (int khkw = 0; khkw < 9; khkw++) {
    const int kh = khkw / 3, kw = khkw % 3;
    const unsigned* wh = whg + khkw*128;
    const unsigned* wl = wlg + khkw*128;
    unsigned ah0 = __ldg(wh + gr*8 + tig);
    unsigned ah1 = __ldg(wh + gr*8 + tig + 64);
    unsigned ah2 = __ldg(wh + gr*8 + tig + 4);
    unsigned ah3 = __ldg(wh + gr*8 + tig + 68);
    unsigned al0 = __ldg(wl + gr*8 + tig);
    unsigned al1 = __ldg(wl + gr*8 + tig + 64);
    unsigned al2 = __ldg(wl + gr*8 + tig + 4);
    unsigned al3 = __ldg(wl + gr*8 + tig + 68);
    int base_in = (hh + kh)*ROWST + tig*PRST + wbase + kw + gr;
    #pragma unroll
    for (int nt = 0; nt < 8; nt++) {
      int coln = base_in + nt*8;
      unsigned bh0 = in_hi[coln];
      unsigned bh1 = in_hi[coln + 4*PRST];
      unsigned bl0 = in_lo[coln];
      unsigned bl1 = in_lo[coln + 4*PRST];
      mma_bf16(d[nt][0],d[nt][1],d[nt][2],d[nt][3], al0,al1,al2,al3, bh0,bh1);
      mma_bf16(d[nt][0],d[nt][1],d[nt][2],d[nt][3], ah0,ah1,ah2,ah3, bl0,bl1);
      mma_bf16(d[nt][0],d[nt][1],d[nt][2],d[nt][3], ah0,ah1,ah2,ah3, bh0,bh1);
    }
  }

  int hout = h0 + hh;
  int ch0 = grp*CG + gr;
  int ch1 = ch0 + 8;
  float bz0 = bias[ch0], bz1 = bias[ch1];
  float ra0 = 0.f, rb0 = 0.f, ra1 = 0.f, rb1 = 0.f;
  if (!FIRST) {
    ra0 = g_bnA[img][ch0]; rb0 = g_bnB[img][ch0];
    ra1 = g_bnA[img][ch1]; rb1 = g_bnB[img][ch1];
  }
  size_t base0 = ((size_t)(b*NC + ch0)*NH + hout)*NW;
  size_t base1 = ((size_t)(b*NC + ch1)*NH + hout)*NW;
  #pragma unroll
  for (int nt = 0; nt < 8; nt++) {
    int w2c = wbase + nt*8 + 2*tig;
    float v0 = d[nt][0] + bz0, v1 = d[nt][1] + bz0;
    float v2 = d[nt][2] + bz1, v3 = d[nt][3] + bz1;
    if (FIRST) {
      v0 = v0 > 0.f ? v0 : 0.1f*v0;
      v1 = v1 > 0.f ? v1 : 0.1f*v1;
      v2 = v2 > 0.f ? v2 : 0.1f*v2;
      v3 = v3 > 0.f ? v3 : 0.1f*v3;
    } else {
      float2 x0 = *(const float2*)&xorig[base0 + w2c];
      float2 x1 = *(const float2*)&xorig[base1 + w2c];
      v0 += ra0*x0.x + rb0;  v1 += ra0*x0.y + rb0;
      v2 += ra1*x1.x + rb1;  v3 += ra1*x1.y + rb1;
    }
    *(float2*)&out[base0 + w2c] = make_float2(v0, v1);
    *(float2*)&out[base1 + w2c] = make_float2(v2, v3);
  }
}

// ---------------- fused attention: all-mma back-end --------------------------
#define SST 132
#define QPST 37
#define A2ST 66
#define ATST 66
#define XPST 66
#define OFF_XLP_H 0
#define OFF_XLP_L 4224
#define OFF_XRP_H 8448
#define OFF_XRP_L 12672
#define OFF_QKV   0        // qk fp32 [k][u] stride 128 (0..16384)
#define OFF_T2S   16896    // t2 staging stride 128 (16896..33280, dead after conv)
#define OFF_QPH   16896    // packed Q/K (over dead t2s): stride 37
#define OFF_QPL   21632
#define OFF_KPH   26368
#define OFF_KPL   31104    // ends 35840
#define OFF_A2H   16896    // written phase 6 (Qp dead)
#define OFF_A2L   25344
#define OFF_ATH   33792
#define OFF_ATL   42240
#define OFF_WS    50688
#define OFF_BS    52736
#define OFF_RMAX  52864
#define OFF_RSC   52992
#define OFF_CMAX  53120
#define OFF_GCC   53248
#define OFF_VL    53376
#define OFF_VR    53504
#define OFF_PART  53632
#define OFF_FR    55680
#define OFF_GC    55808
#define OFF_MG    55936
#define ATTN_SMEM ((55936 + 32)*4)   // 223872 B

__global__ __launch_bounds__(1024, 1) void attn_kernel(
    const float* __restrict__ t2, const float* __restrict__ xL,
    const float* __restrict__ xR,
    const float* __restrict__ qw, const float* __restrict__ qb,
    const float* __restrict__ kw_, const float* __restrict__ kb,
    float* __restrict__ outL, float* __restrict__ outR) {
  extern __shared__ float sm[];
  float* Sb    = sm;                 // qk -> S (stride 132)
  float* qkv   = sm + OFF_QKV;
  float* t2s   = sm + OFF_T2S;
  unsigned* Qph = (unsigned*)(sm + OFF_QPH);
  unsigned* Qpl = (unsigned*)(sm + OFF_QPL);
  unsigned* Kph = (unsigned*)(sm + OFF_KPH);
  unsigned* Kpl = (unsigned*)(sm + OFF_KPL);
  unsigned* A2h = (unsigned*)(sm + OFF_A2H);
  unsigned* A2l = (unsigned*)(sm + OFF_A2L);
  unsigned* Ath = (unsigned*)(sm + OFF_ATH);
  unsigned* Atl = (unsigned*)(sm + OFF_ATL);
  float* ws    = sm + OFF_WS;
  float* bs    = sm + OFF_BS;
  float* rmax  = sm + OFF_RMAX;
  float* rsc   = sm + OFF_RSC;
  float* cmax  = sm + OFF_CMAX;
  float* gcc   = sm + OFF_GCC;
  float* Vl    = sm + OFF_VL;
  float* Vr    = sm + OFF_VR;
  float* part  = sm + OFF_PART;
  float* fr    = sm + OFF_FR;
  float* gc    = sm + OFF_GC;
  float* Mg    = sm + OFF_MG;
  int n = blockIdx.x, b = n >> 7, h = n & 127;
  int t = threadIdx.x, warp = t >> 5, lane = t & 31;
  int g = lane >> 2, tig = lane & 3;

  // 1. stage weights/bias + t2 rows (into A2 region, dead before phase 6)
  for (int i = t; i < 2048; i += 1024) ws[i] = (i < 1024) ? qw[i] : kw_[i-1024];
  if (t < 128) bs[t] = (t < 64) ? qb[t] : kb[t-64];
  for (int i = t; i < 16384; i += 1024) {
    int c = i >> 7, u = i & 127;
    size_t gi = ((c >= 64) ? (size_t)IMG : 0) +
                ((size_t)(b*NC + (c & 63))*NH + h)*NW + u;
    t2s[c*128 + u] = t2[gi];
  }
  __syncthreads();

  // 2. 1x1 grouped conv: qkv[k][u] stride 128 (region 0)
  for (int i = t; i < 8192; i += 1024) {
    int k = i >> 6, up = (i & 63)*2;
    int cb = (k >> 4) * 16;
    float bzv = bs[k];
    u64 a = f2pk(bzv, bzv);
    #pragma unroll
    for (int ic = 0; ic < 16; ic++) {
      u64 w2 = f2dup(ws[k*16 + ic]);
      u64 xp = *(const u64*)&t2s[(cb + ic)*128 + up];
      fma2(a, w2, xp);
    }
    *(u64*)&qkv[k*128 + up] = a;
  }
  __syncthreads();

  // 3. row-mean subtract
  for (int r = warp; r < 128; r += 32) {
    float s = 0.f;
    for (int u = lane; u < 128; u += 32) s += qkv[r*128 + u];
    #pragma unroll
    for (int off = 16; off; off >>= 1) s += __shfl_xor_sync(0xffffffffu, s, off);
    float mean = s * (1.f/128.f);
    for (int u = lane; u < 128; u += 32) qkv[r*128 + u] -= mean;
  }
  __syncthreads();

  // 3.5 pack Q/K k-pairs bf16 hi/lo (stride 37; t2s dead)
  for (int loop = 0; loop < 8; loop++) {
    int u = t & 127;
    int kp = (t >> 7) + loop*8;
    float v0 = qkv[(2*kp)*128 + u];
    float v1 = qkv[(2*kp+1)*128 + u];
    unsigned lo;
    unsigned hi = bfsplit(v0, v1, lo);
    if (kp < 32) { Qph[u*QPST + kp] = hi;      Qpl[u*QPST + kp] = lo; }
    else         { Kph[u*QPST + kp-32] = hi;   Kpl[u*QPST + kp-32] = lo; }
  }
  __syncthreads();

  // 4. GEMM1 via bf16 mma: S[u][v] -> Sb stride 132 (qkv dead)
  {
    int u0 = (warp >> 2) * 16, v0 = (warp & 3) * 32;
    float d[4][4];
    #pragma unroll
    for (int j = 0; j < 4; j++)
      d[j][0] = d[j][1] = d[j][2] = d[j][3] = 0.f;
    #pragma unroll
    for (int ks = 0; ks < 4; ks++) {
      int kp = ks*8 + tig;
      int ra = (u0+g)*QPST + kp, rb = (u0+g+8)*QPST + kp;
      unsigned ah0 = Qph[ra],   ah1 = Qph[rb];
      unsigned ah2 = Qph[ra+4], ah3 = Qph[rb+4];
      unsigned al0 = Qpl[ra],   al1 = Qpl[rb];
      unsigned al2 = Qpl[ra+4], al3 = Qpl[rb+4];
      #pragma unroll
      for (int j = 0; j < 4; j++) {
        int ci = (v0 + j*8 + g)*QPST + kp;
        unsigned bh0 = Kph[ci], bh1 = Kph[ci+4];
        unsigned bl0 = Kpl[ci], bl1 = Kpl[ci+4];
        mma_bf16(d[j][0],d[j][1],d[j][2],d[j][3], al0,al1,al2,al3, bh0,bh1);
        mma_bf16(d[j][0],d[j][1],d[j][2],d[j][3], ah0,ah1,ah2,ah3, bl0,bl1);
        mma_bf16(d[j][0],d[j][1],d[j][2],d[j][3], ah0,ah1,ah2,ah3, bh0,bh1);
      }
    }
    #pragma unroll
    for (int j = 0; j < 4; j++) {
      int col = v0 + j*8 + 2*tig;
      *(float2*)&Sb[(u0+g)*SST + col]   = make_float2(d[j][0], d[j][1]);
      *(float2*)&Sb[(u0+g+8)*SST + col] = make_float2(d[j][2], d[j][3]);
    }
  }
  __syncthreads();

  // 5. max scans (R10-validated) + combine + factors
  if (warp < 16) {
    for (int r = warp*8; r < warp*8 + 8; r++) {
      float m = -1e30f;
      #pragma unroll
      for (int j = 0; j < 4; j++) m = fmaxf(m, Sb[r*SST + lane + j*32]);
      #pragma unroll
      for (int off = 16; off; off >>= 1) m = fmaxf(m, __shfl_xor_sync(0xffffffffu, m, off));
      if (lane == 0) rmax[r] = m;
    }
  } else {
    int j = warp - 16;
    int c = (j & 3)*32 + lane;
    int r0 = (j >> 2)*32;
    float m = -1e30f;
    for (int r = r0; r < r0 + 32; r++) m = fmaxf(m, Sb[r*SST + c]);
    part[(j >> 2)*128 + c] = m;
  }
  __syncthreads();
  if (t < 128) {
    cmax[t] = fmaxf(fmaxf(part[t], part[128+t]), fmaxf(part[256+t], part[384+t]));
  } else if (t < 160) {
    int l = t - 128;
    float m = fmaxf(fmaxf(rmax[l], rmax[l+32]), fmaxf(rmax[l+64], rmax[l+96]));
    #pragma unroll
    for (int off = 16; off; off >>= 1) m = fmaxf(m, __shfl_xor_sync(0xffffffffu, m, off));
    if (l == 0) Mg[0] = m;
  }
  __syncthreads();
  if (t < 128) {
    float M = Mg[0];
    fr[t] = __expf(rmax[t] - M);
    gc[t] = __expf(M - cmax[t]);
  }
  __syncthreads();

  // 6. exp + A2/At bf16 hi/lo packing + sums (Qp dead)
  if (warp < 16) {
    int cA = 2*lane, cB = cA + 64;
    float g0 = gc[cA], g1v = gc[cA+1], g2 = gc[cB], g3 = gc[cB+1];
    float cs0=0.f, cs1=0.f, cs2=0.f, cs3=0.f;
    float p0=0.f, p1=0.f, p2=0.f, p3=0.f;
    #pragma unroll
    for (int rr = 0; rr < 8; rr++) {
      int r = warp*8 + rr;
      float rm = rmax[r], frv = fr[r];
      float2 sA = *(const float2*)&Sb[r*SST + cA];
      float2 sB = *(const float2*)&Sb[r*SST + cB];
      float e0 = __expf(sA.x - rm), e1 = __expf(sA.y - rm);
      float e2 = __expf(sB.x - rm), e3 = __expf(sB.y - rm);
      float rs = e0 + e1 + e2 + e3;
      float a0 = e0*frv, a1 = e1*frv, a2 = e2*frv, a3 = e3*frv;
      cs0 += a0*g0; cs1 += a1*g1v; cs2 += a2*g2; cs3 += a3*g3;
      __nv_bfloat16 h0 = __float2bfloat16(a0), h1 = __float2bfloat16(a1);
      __nv_bfloat16 h2 = __float2bfloat16(a2), h3 = __float2bfloat16(a3);
      A2h[r*A2ST + lane]      = bfpk(h0, h1);
      A2l[r*A2ST + lane]      = bfpk(__float2bfloat16(a0 - __bfloat162float(h0)),
                                     __float2bfloat16(a1 - __bfloat162float(h1)));
      A2h[r*A2ST + lane + 32] = bfpk(h2, h3);
      A2l[r*A2ST + lane + 32] = bfpk(__float2bfloat16(a2 - __bfloat162float(h2)),
                                     __float2bfloat16(a3 - __bfloat162float(h3)));
      if (rr & 1) {
        int vp = warp*4 + (rr >> 1);
        __nv_bfloat16 q0 = __float2bfloat16(p0), q1 = __float2bfloat16(p1);
        __nv_bfloat16 q2 = __float2bfloat16(p2), q3 = __float2bfloat16(p3);
        Ath[cA*ATST + vp]     = bfpk(q0, h0);
        Atl[cA*ATST + vp]     = bfpk(__float2bfloat16(p0 - __bfloat162float(q0)),
                                     __float2bfloat16(a0 - __bfloat162float(h0)));
        Ath[(cA+1)*ATST + vp] = bfpk(q1, h1);
        Atl[(cA+1)*ATST + vp] = bfpk(__float2bfloat16(p1 - __bfloat162float(q1)),
                                     __float2bfloat16(a1 - __bfloat162float(h1)));
        Ath[cB*ATST + vp]     = bfpk(q2, h2);
        Atl[cB*ATST + vp]     = bfpk(__float2bfloat16(p2 - __bfloat162float(q2)),
                                     __float2bfloat16(a2 - __bfloat162float(h2)));
        Ath[(cB+1)*ATST + vp] = bfpk(q3, h3);
        Atl[(cB+1)*ATST + vp] = bfpk(__float2bfloat16(p3 - __bfloat162float(q3)),
                                     __float2bfloat16(a3 - __bfloat162float(h3)));
      } else { p0 = a0; p1 = a1; p2 = a2; p3 = a3; }
      #pragma unroll
      for (int off = 16; off; off >>= 1) rs += __shfl_xor_sync(0xffffffffu, rs, off);
      if (lane == 0) rsc[r] = 1.f / rs;
    }
    part[warp*128 + cA]   = cs0;
    part[warp*128 + cA+1] = cs1;
    part[warp*128 + cB]   = cs2;
    part[warp*128 + cB+1] = cs3;
  }
  __syncthreads();
  if (t < 128) {
    float s = 0.f;
    #pragma unroll
    for (int w = 0; w < 16; w++) s += part[w*128 + t];
    gcc[t] = gc[t] / s;
    rsc[t] = __fdividef(rsc[t], fr[t]);
  }
  __syncthreads();

  // 7. banded Grams
  {
    bool isG = warp < 16;
    const unsigned* Ph = isG ? A2h : Ath;
    const unsigned* Pl = isG ? A2l : Atl;
    const float* wv = isG ? gcc : rsc;
    int stp = isG ? A2ST : ATST;
    int base = (warp & 15) * 8;
    float acc0[8], acc1[8], acc2g[8];
    #pragma unroll
    for (int i = 0; i < 8; i++) { acc0[i]=0.f; acc1[i]=0.f; acc2g[i]=0.f; }
    #pragma unroll
    for (int vj = 0; vj < 2; vj++) {
      int vp = vj*32 + lane;
      float w0 = wv[2*vp], w1 = wv[2*vp+1];
      float2 e0v = upk(Ph[base*stp + vp], Pl[base*stp + vp]);
      float2 e1v = upk(Ph[(base+1)*stp + vp], Pl[(base+1)*stp + vp]);
      #pragma unroll
      for (int i = 0; i < 8; i++) {
        int rn = base + i + 2;
        float2 e2v = (rn < 128) ? upk(Ph[rn*stp + vp], Pl[rn*stp + vp])
                                : make_float2(0.f, 0.f);
        acc0[i]  += e0v.x*w0*e0v.x + e0v.y*w1*e0v.y;
        acc1[i]  += e0v.x*w0*e1v.x + e0v.y*w1*e1v.y;
        acc2g[i] += e0v.x*w0*e2v.x + e0v.y*w1*e2v.y;
        e0v = e1v; e1v = e2v;
      }
    }
    int po = isG ? 0 : 384;
    #pragma unroll
    for (int i = 0; i < 8; i++) {
      #pragma unroll
      for (int off = 16; off; off >>= 1) {
        acc0[i]  += __shfl_xor_sync(0xffffffffu, acc0[i],  off);
        acc1[i]  += __shfl_xor_sync(0xffffffffu, acc1[i],  off);
        acc2g[i] += __shfl_xor_sync(0xffffffffu, acc2g[i], off);
      }
      if (lane == 0) {
        part[po + base+i]       = acc0[i];
        part[po + 128 + base+i] = acc1[i];
        part[po + 256 + base+i] = acc2g[i];
      }
    }
  }
  __syncthreads();

  // 8. x bf16 packing + V maps
  for (int i = t; i < 8192; i += 1024) {
    int img = i >> 12, j = i & 4095, c = j >> 6, vp = j & 63;
    const float* src = img ? xR : xL;
    float2 v = *(const float2*)&src[((size_t)(b*NC + c)*NH + h)*NW + 2*vp];
    unsigned* ph = (unsigned*)(sm + (img ? OFF_XRP_H : OFF_XLP_H));
    unsigned* pl = (unsigned*)(sm + (img ? OFF_XRP_L : OFF_XLP_L));
    unsigned lo;
    ph[c*XPST + vp] = bfsplit(v.x, v.y, lo);
    pl[c*XPST + vp] = lo;
  }
  if (t < 128) {
    int u = t;
    float accL = rsc[u]*part[u];
    if (u+1 < 128) accL += rsc[u+1]*part[128+u];
    if (u+2 < 128) accL += rsc[u+2]*part[256+u];
    if (u >= 1)    accL += rsc[u-1]*part[128+u-1];
    if (u >= 2)    accL += rsc[u-2]*part[256+u-2];
    Vl[u] = tanhf(5.f*accL);
  } else if (t < 256) {
    int u = t - 128;
    float accR = gcc[u]*part[384+u];
    if (u+1 < 128) accR += gcc[u+1]*part[512+u];
    if (u+2 < 128) accR += gcc[u+2]*part[640+u];
    if (u >= 1)    accR += gcc[u-1]*part[512+u-1];
    if (u >= 2)    accR += gcc[u-2]*part[640+u-2];
    Vr[u] = tanhf(5.f*accR);
  }
  __syncthreads();

  // 9. GEMM2/3 via bf16 mma + blend epilogue
  {
    bool left = warp < 16;
    int gw = warp & 15;
    int u0 = (gw >> 1) * 16, nb = (gw & 1) * 32;
    const unsigned* Ah = left ? A2h : Ath;
    const unsigned* Al = left ? A2l : Atl;
    const unsigned* Bh = (const unsigned*)(sm + (left ? OFF_XRP_H : OFF_XLP_H));
    const unsigned* Bl = (const unsigned*)(sm + (left ? OFF_XRP_L : OFF_XLP_L));
    float d[4][4];
    #pragma unroll
    for (int j = 0; j < 4; j++)
      d[j][0] = d[j][1] = d[j][2] = d[j][3] = 0.f;
    for (int ks = 0; ks < 8; ks++) {
      int vp = ks*8 + tig;
      int ra = (u0+g)*A2ST + vp, rb = (u0+g+8)*A2ST + vp;
      unsigned ah0 = Ah[ra],   ah1 = Ah[rb];
      unsigned ah2 = Ah[ra+4], ah3 = Ah[rb+4];
      unsigned al0 = Al[ra],   al1 = Al[rb];
      unsigned al2 = Al[ra+4], al3 = Al[rb+4];
      #pragma unroll
      for (int j = 0; j < 4; j++) {
        int ci = (nb + j*8 + g)*XPST + vp;
        unsigned bh0 = Bh[ci], bh1 = Bh[ci+4];
        unsigned bl0 = Bl[ci], bl1 = Bl[ci+4];
        mma_bf16(d[j][0],d[j][1],d[j][2],d[j][3], al0,al1,al2,al3, bh0,bh1);
        mma_bf16(d[j][0],d[j][1],d[j][2],d[j][3], ah0,ah1,ah2,ah3, bl0,bl1);
        mma_bf16(d[j][0],d[j][1],d[j][2],d[j][3], ah0,ah1,ah2,ah3, bh0,bh1);
      }
    }
    const float* xg = left ? xL : xR;
    float* og = left ? outL : outR;
    const float* Vv = left ? Vl : Vr;
    const float* scv = left ? rsc : gcc;
    int ua = u0 + g, ub = u0 + g + 8;
    float va = Vv[ua], vb = Vv[ub];
    float sa = scv[ua]*va, sb2 = scv[ub]*vb;
    float ia = 1.f - va, ib = 1.f - vb;
    #pragma unroll
    for (int j = 0; j < 4; j++) {
      int c = nb + j*8 + 2*tig;
      size_t b0i = ((size_t)(b*NC + c)*NH + h)*NW;
      size_t b1i = b0i + (size_t)HW;
      og[b0i + ua] = xg[b0i + ua]*ia + d[j][0]*sa;
      og[b1i + ua] = xg[b1i + ua]*ia + d[j][1]*sa;
      og[b0i + ub] = xg[b0i + ub]*ib + d[j][2]*sb2;
      og[b1i + ub] = xg[b1i + ub]*ib + d[j][3]*sb2;
    }
  }
}

// ---------------- host ------------------------------------------------------
extern "C" void kernel_launch(void* const* d_in, const int* in_sizes, int n_in,
                              void* d_out, int out_size) {
  const float* xL    = (const float*)d_in[0];
  const float* xR    = (const float*)d_in[1];
  const float* gamma = (const float*)d_in[2];
  const float* beta  = (const float*)d_in[3];
  const float* w1    = (const float*)d_in[4];
  const float* b1    = (const float*)d_in[5];
  const float* w2    = (const float*)d_in[6];
  const float* b2    = (const float*)d_in[7];
  const float* qw    = (const float*)d_in[8];
  const float* qb    = (const float*)d_in[9];
  const float* kw    = (const float*)d_in[10];
  const float* kb    = (const float*)d_in[11];
  float* outL = (float*)d_out;
  float* outR = outL + (size_t)IMG;

  float *t1, *t2;
  unsigned *wth, *wtl;
  cudaGetSymbolAddress((void**)&t1, g_t1);
  cudaGetSymbolAddress((void**)&t2, g_t2);
  cudaGetSymbolAddress((void**)&wth, g_wth);
  cudaGetSymbolAddress((void**)&wtl, g_wtl);

  cudaFuncSetAttribute(conv3x3_kernel<true>,  cudaFuncAttributeMaxDynamicSharedMemorySize, CONV_SMEM);
  cudaFuncSetAttribute(conv3x3_kernel<false>, cudaFuncAttributeMaxDynamicSharedMemorySize, CONV_SMEM);
  cudaFuncSetAttribute(attn_kernel, cudaFuncAttributeMaxDynamicSharedMemorySize, ATTN_SMEM);

  bn_stats_kernel<<<128, 256>>>(xL, xR, gamma, beta);
  wtrans_kernel<<<(2*NG*9*16*8 + 255)/256, 256>>>(w1, w2);

  dim3 cgrid(NH/4, NB*NG, 2);
  conv3x3_kernel<true ><<<cgrid, 256, CONV_SMEM>>>(
      xL, xR, t1, t2, wth, wtl, b1);
  conv3x3_kernel<false><<<cgrid, 256, CONV_SMEM>>>(
      xL, xR, t1, t2, wth + 4608, wtl + 4608, b2);

  attn_kernel<<<NROW, 1024, ATTN_SMEM>>>(t2, xL, xR, qw, qb, kw, kb, outL, outR);
}

// round 16
// speedup vs baseline: 1.6634x; 1.1283x over previous
#include <cuda_runtime.h>
#include <cuda_bf16.h>
#include <math.h>

#define NB 8
#define NC 64
#define NG 4
#define CG 16
#define NH 128
#define NW 128
#define HW (NH*NW)
#define IMG (NB*NC*HW)
#define NROW (NB*NH)

typedef unsigned long long u64;

__device__ __forceinline__ u64 f2dup(float v) {
  u64 r; asm("mov.b64 %0, {%1, %1};" : "=l"(r) : "f"(v)); return r;
}
__device__ __forceinline__ u64 f2pk(float a, float b) {
  u64 r; asm("mov.b64 %0, {%1, %2};" : "=l"(r) : "f"(a), "f"(b)); return r;
}
__device__ __forceinline__ void fma2(u64& d, u64 a, u64 b) {
  asm("fma.rn.f32x2 %0, %1, %2, %0;" : "+l"(d) : "l"(a), "l"(b));
}
__device__ __forceinline__ float2 f2up(u64 v) {
  float2 f; asm("mov.b64 {%0, %1}, %2;" : "=f"(f.x), "=f"(f.y) : "l"(v)); return f;
}
__device__ __forceinline__ void mma_bf16(
    float& d0, float& d1, float& d2, float& d3,
    unsigned a0, unsigned a1, unsigned a2, unsigned a3,
    unsigned b0, unsigned b1) {
  asm volatile(
    "mma.sync.aligned.m16n8k16.row.col.f32.bf16.bf16.f32 "
    "{%0,%1,%2,%3}, {%4,%5,%6,%7}, {%8,%9}, {%0,%1,%2,%3};"
    : "+f"(d0), "+f"(d1), "+f"(d2), "+f"(d3)
    : "r"(a0), "r"(a1), "r"(a2), "r"(a3), "r"(b0), "r"(b1));
}
__device__ __forceinline__ unsigned bfpk(__nv_bfloat16 a, __nv_bfloat16 b) {
  __nv_bfloat162 h = __halves2bfloat162(a, b);
  return *(unsigned*)&h;
}
__device__ __forceinline__ unsigned bfsplit(float a, float b, unsigned& lo) {
  __nv_bfloat16 ha = __float2bfloat16(a), hb = __float2bfloat16(b);
  lo = bfpk(__float2bfloat16(a - __bfloat162float(ha)),
            __float2bfloat16(b - __bfloat162float(hb)));
  return bfpk(ha, hb);
}
__device__ __forceinline__ float2 upk(unsigned h, unsigned l) {
  __nv_bfloat162 hb = *(__nv_bfloat162*)&h;
  __nv_bfloat162 lb = *(__nv_bfloat162*)&l;
  return make_float2(__low2float(hb) + __low2float(lb),
                     __high2float(hb) + __high2float(lb));
}

// ---------------- scratch ----------------------------------------------------
__device__ float g_t1[2*(size_t)IMG];
__device__ float g_t2[2*(size_t)IMG];
__device__ float g_bnA[2][NC];
__device__ float g_bnB[2][NC];
__device__ __align__(16) unsigned g_wth[2][NG*9*16*8];
__device__ __align__(16) unsigned g_wtl[2][NG*9*16*8];

// ---------------- BN statistics ----------------------------------------------
__global__ __launch_bounds__(256) void bn_stats_kernel(
    const float* __restrict__ xl, const float* __restrict__ xr,
    const float* __restrict__ gamma, const float* __restrict__ beta) {
  int c = blockIdx.x & 63;
  int img = blockIdx.x >> 6;
  const float4* x = (const float4*)(img ? xr : xl);
  int t = threadIdx.x;
  float s = 0.f, s2 = 0.f;
  for (int b = 0; b < NB; b++) {
    const float4* p = x + (size_t)(b*NC + c)*(HW/4);
    for (int i = t; i < HW/4; i += 256) {
      float4 v = p[i];
      s  += v.x + v.y + v.z + v.w;
      s2 += v.x*v.x + v.y*v.y + v.z*v.z + v.w*v.w;
    }
  }
  __shared__ float sh[256], sh2[256];
  sh[t] = s; sh2[t] = s2; __syncthreads();
  for (int off = 128; off; off >>= 1) {
    if (t < off) { sh[t] += sh[t+off]; sh2[t] += sh2[t+off]; }
    __syncthreads();
  }
  if (t == 0) {
    const float inv = 1.f / (float)(NB*HW);
    float mean = sh[0] * inv;
    float var  = sh2[0] * inv - mean*mean;
    float a = gamma[c] * rsqrtf(var + 1e-5f);
    g_bnA[img][c] = a;
    g_bnB[img][c] = beta[c] - mean * a;
  }
}

// ---------------- weight prep (kept) ------------------------------------------
__global__ __launch_bounds__(256) void wtrans_kernel(
    const float* __restrict__ w1, const float* __restrict__ w2) {
  int i = blockIdx.x * 256 + threadIdx.x;
  if (i >= 2*NG*9*16*8) return;
  int layer = i / 4608;
  int j = i - layer*4608;
  int g = j / 1152;
  int r = j - g*1152;
  int khkw = r >> 7;
  int q = r & 127;
  int oc = q >> 3, p = q & 7;
  const float* src = layer ? w2 : w1;
  int base = g*(CG*CG*9) + oc*(CG*9) + (2*p)*9 + khkw;
  float w0 = src[base], w1v = src[base + 9];
  unsigned lo;
  g_wth[layer][j] = bfsplit(w0, w1v, lo);
  g_wtl[layer][j] = lo;
}

// ---------------- grouped 3x3 conv (R12, kept: 76.8us) -----------------------
#define PRST 136
#define ROWST (8*PRST)
#define CIN_U32 (6*ROWST)
#define CONV_SMEM (2*CIN_U32*4)

template<bool FIRST>
__global__ __launch_bounds__(256, 3) void conv3x3_kernel(
    const float* __restrict__ xL, const float* __restrict__ xR,
    float* __restrict__ t1, float* __restrict__ t2,
    const unsigned* __restrict__ wth, const unsigned* __restrict__ wtl,
    const float* __restrict__ bias) {
  extern __shared__ unsigned smu[];
  unsigned* in_hi = smu;
  unsigned* in_lo = smu + CIN_U32;
  int t = threadIdx.x;
  int img = blockIdx.z;
  int b = blockIdx.y >> 2, grp = blockIdx.y & 3;
  int h0 = blockIdx.x * 4;
  const float* xorig = img ? xR : xL;
  const float* xin = FIRST ? xorig : (t1 + (size_t)img*IMG);
  float* out = (FIRST ? t1 : t2) + (size_t)img*IMG;

  for (int i = t; i < CIN_U32; i += 256) {
    int col  = i % PRST;
    int rest = i / PRST;
    int pair = rest & 7;
    int row  = rest >> 3;
    int hh = h0 - 1 + row;
    int ww = col - 1;
    float v0 = 0.f, v1 = 0.f;
    if ((unsigned)hh < (unsigned)NH && (unsigned)ww < (unsigned)NW) {
      int ch = grp*CG + 2*pair;
      size_t gidx = ((size_t)(b*NC + ch)*NH + hh)*NW + ww;
      v0 = xin[gidx];
      v1 = xin[gidx + HW];
      if (FIRST) {
        v0 = g_bnA[img][ch]*v0 + g_bnB[img][ch];
        v1 = g_bnA[img][ch+1]*v1 + g_bnB[img][ch+1];
      }
    }
    unsigned lo;
    in_hi[i] = bfsplit(v0, v1, lo);
    in_lo[i] = lo;
  }
  __syncthreads();

  int warp = t >> 5, lane = t & 31;
  int gr = lane >> 2, tig = lane & 3;
  int hh = warp >> 1;
  int wbase = (warp & 1) * 64;

  const unsigned* whg = wth + grp*(9*128);
  const unsigned* wlg = wtl + grp*(9*128);

  float d[8][4];
  #pragma unroll
  for (int nt = 0; nt < 8; nt++)
    d[nt][0] = d[nt][1] = d[nt][2] = d[nt][3] = 0.f;

  #pragma unroll
  for (int khkw = 0; khkw < 9; khkw++) {
    const int kh = khkw / 3, kw = khkw % 3;
    const unsigned* wh = whg + khkw*128;
    const unsigned* wl = wlg + khkw*128;
    unsigned ah0 = __ldg(wh + gr*8 + tig);
    unsigned ah1 = __ldg(wh + gr*8 + tig + 64);
    unsigned ah2 = __ldg(wh + gr*8 + tig + 4);
    unsigned ah3 = __ldg(wh + gr*8 + tig + 68);
    unsigned al0 = __ldg(wl + gr*8 + tig);
    unsigned al1 = __ldg(wl + gr*8 + tig + 64);
    unsigned al2 = __ldg(wl + gr*8 + tig + 4);
    unsigned al3 = __ldg(wl + gr*8 + tig + 68);
    int base_in = (hh + kh)*ROWST + tig*PRST + wbase + kw + gr;
    #pragma unroll
    for (int nt = 0; nt < 8; nt++) {
      int coln = base_in + nt*8;
      unsigned bh0 = in_hi[coln];
      unsigned bh1 = in_hi[coln + 4*PRST];
      unsigned bl0 = in_lo[coln];
      unsigned bl1 = in_lo[coln + 4*PRST];
      mma_bf16(d[nt][0],d[nt][1],d[nt][2],d[nt][3], al0,al1,al2,al3, bh0,bh1);
      mma_bf16(d[nt][0],d[nt][1],d[nt][2],d[nt][3], ah0,ah1,ah2,ah3, bl0,bl1);
      mma_bf16(d[nt][0],d[nt][1],d[nt][2],d[nt][3], ah0,ah1,ah2,ah3, bh0,bh1);
    }
  }

  int hout = h0 + hh;
  int ch0 = grp*CG + gr;
  int ch1 = ch0 + 8;
  float bz0 = bias[ch0], bz1 = bias[ch1];
  float ra0 = 0.f, rb0 = 0.f, ra1 = 0.f, rb1 = 0.f;
  if (!FIRST) {
    ra0 = g_bnA[img][ch0]; rb0 = g_bnB[img][ch0];
    ra1 = g_bnA[img][ch1]; rb1 = g_bnB[img][ch1];
  }
  size_t base0 = ((size_t)(b*NC + ch0)*NH + hout)*NW;
  size_t base1 = ((size_t)(b*NC + ch1)*NH + hout)*NW;
  #pragma unroll
  for (int nt = 0; nt < 8; nt++) {
    int w2c = wbase + nt*8 + 2*tig;
    float v0 = d[nt][0] + bz0, v1 = d[nt][1] + bz0;
    float v2 = d[nt][2] + bz1, v3 = d[nt][3] + bz1;
    if (FIRST) {
      v0 = v0 > 0.f ? v0 : 0.1f*v0;
      v1 = v1 > 0.f ? v1 : 0.1f*v1;
      v2 = v2 > 0.f ? v2 : 0.1f*v2;
      v3 = v3 > 0.f ? v3 : 0.1f*v3;
    } else {
      float2 x0 = *(const float2*)&xorig[base0 + w2c];
      float2 x1 = *(const float2*)&xorig[base1 + w2c];
      v0 += ra0*x0.x + rb0;  v1 += ra0*x0.y + rb0;
      v2 += ra1*x1.x + rb1;  v3 += ra1*x1.y + rb1;
    }
    *(float2*)&out[base0 + w2c] = make_float2(v0, v1);
    *(float2*)&out[base1 + w2c] = make_float2(v2, v3);
  }
}

// ---------------- fused attention: all-mma, mma 1x1 conv ---------------------
#define SST 132
#define QKST 130
#define QPST 37
#define XST2 65
#define A2ST 66
#define ATST 66
#define XPST 66
#define OFF_XLP_H 0
#define OFF_XLP_L 4224
#define OFF_XRP_H 8448
#define OFF_XRP_L 12672
#define OFF_QKV   0
#define OFF_XP    16896
#define OFF_QPH   16896
#define OFF_QPL   21632
#define OFF_KPH   26368
#define OFF_KPL   31104
#define OFF_A2H   16896
#define OFF_A2L   25344
#define OFF_ATH   33792
#define OFF_ATL   42240
#define OFF_WS    50688
#define OFF_BS    52736
#define OFF_RMAX  52864
#define OFF_RSC   52992
#define OFF_CMAX  53120
#define OFF_GCC   53248
#define OFF_VL    53376
#define OFF_VR    53504
#define OFF_PART  53632
#define OFF_FR    55680
#define OFF_GC    55808
#define OFF_MG    55936
#define ATTN_SMEM ((55936 + 32)*4)   // 223872 B

__global__ __launch_bounds__(1024, 1) void attn_kernel(
    const float* __restrict__ t2, const float* __restrict__ xL,
    const float* __restrict__ xR,
    const float* __restrict__ qw, const float* __restrict__ qb,
    const float* __restrict__ kw_, const float* __restrict__ kb,
    float* __restrict__ outL, float* __restrict__ outR) {
  extern __shared__ float sm[];
  float* Sb    = sm;
  float* qkv   = sm + OFF_QKV;
  unsigned* Xph = (unsigned*)(sm + OFF_XP);
  unsigned* Xpl = Xph + 8320;
  unsigned* Qph = (unsigned*)(sm + OFF_QPH);
  unsigned* Qpl = (unsigned*)(sm + OFF_QPL);
  unsigned* Kph = (unsigned*)(sm + OFF_KPH);
  unsigned* Kpl = (unsigned*)(sm + OFF_KPL);
  unsigned* A2h = (unsigned*)(sm + OFF_A2H);
  unsigned* A2l = (unsigned*)(sm + OFF_A2L);
  unsigned* Ath = (unsigned*)(sm + OFF_ATH);
  unsigned* Atl = (unsigned*)(sm + OFF_ATL);
  unsigned* Wph = (unsigned*)(sm + OFF_WS);
  unsigned* Wpl = Wph + 1024;
  float* wsf   = sm + OFF_WS;
  float* bs    = sm + OFF_BS;
  float* rmax  = sm + OFF_RMAX;
  float* rsc   = sm + OFF_RSC;
  float* cmax  = sm + OFF_CMAX;
  float* gcc   = sm + OFF_GCC;
  float* Vl    = sm + OFF_VL;
  float* Vr    = sm + OFF_VR;
  float* part  = sm + OFF_PART;
  float* fr    = sm + OFF_FR;
  float* gc    = sm + OFF_GC;
  float* Mg    = sm + OFF_MG;
  int n = blockIdx.x, b = n >> 7, h = n & 127;
  int t = threadIdx.x, warp = t >> 5, lane = t & 31;
  int g = lane >> 2, tig = lane & 3;

  // 1. pack weights + bias + X stage/pack
  {
    int k = t >> 3, p = t & 7;
    const float* wsrc = (k < 64) ? qw : kw_;
    int kk = k & 63;
    float w0 = wsrc[kk*16 + 2*p], w1v = wsrc[kk*16 + 2*p + 1];
    unsigned lo;
    Wph[t] = bfsplit(w0, w1v, lo);
    Wpl[t] = lo;
  }
  if (t < 128) bs[t] = (t < 64) ? qb[t] : kb[t-64];
  for (int i = t; i < 8192; i += 1024) {
    int u = i & 127, cp = i >> 7;
    int c = 2*cp;
    size_t gi = ((c >= 64) ? (size_t)IMG : 0) +
                ((size_t)(b*NC + (c & 63))*NH + h)*NW + u;
    float v0 = t2[gi], v1 = t2[gi + HW];
    unsigned lo;
    Xph[u*XST2 + cp] = bfsplit(v0, v1, lo);
    Xpl[u*XST2 + cp] = lo;
  }
  __syncthreads();

  // 2. 1x1 grouped conv via bf16 mma: qkv[k][u] = W·X + bias
  {
    int gg = warp >> 3, sub = warp & 7;
    int mt = sub >> 2, n0 = (sub & 3)*32;
    int krow0 = mt*64 + gg*16;
    int pbase = mt*32 + gg*8;          // FIX: right-image pairs for K rows
    float d[4][4];
    #pragma unroll
    for (int j = 0; j < 4; j++)
      d[j][0] = d[j][1] = d[j][2] = d[j][3] = 0.f;
    int ra = (krow0+g)*8 + tig, rb = (krow0+g+8)*8 + tig;
    unsigned ah0 = Wph[ra],   ah1 = Wph[rb];
    unsigned ah2 = Wph[ra+4], ah3 = Wph[rb+4];
    unsigned al0 = Wpl[ra],   al1 = Wpl[rb];
    unsigned al2 = Wpl[ra+4], al3 = Wpl[rb+4];
    #pragma unroll
    for (int j = 0; j < 4; j++) {
      int u = n0 + j*8 + g;
      int ci = u*XST2 + pbase + tig;
      unsigned bh0 = Xph[ci], bh1 = Xph[ci+4];
      unsigned bl0 = Xpl[ci], bl1 = Xpl[ci+4];
      mma_bf16(d[j][0],d[j][1],d[j][2],d[j][3], al0,al1,al2,al3, bh0,bh1);
      mma_bf16(d[j][0],d[j][1],d[j][2],d[j][3], ah0,ah1,ah2,ah3, bl0,bl1);
      mma_bf16(d[j][0],d[j][1],d[j][2],d[j][3], ah0,ah1,ah2,ah3, bh0,bh1);
    }
    int ua = krow0 + g, ub = ua + 8;
    float ba = bs[ua], bb = bs[ub];
    #pragma unroll
    for (int j = 0; j < 4; j++) {
      int col = n0 + j*8 + 2*tig;
      *(float2*)&qkv[ua*QKST + col] = make_float2(d[j][0]+ba, d[j][1]+ba);
      *(float2*)&qkv[ub*QKST + col] = make_float2(d[j][2]+bb, d[j][3]+bb);
    }
  }
  __syncthreads();

  // 3. row-mean subtract
  for (int r = warp; r < 128; r += 32) {
    float s = 0.f;
    for (int u = lane; u < 128; u += 32) s += qkv[r*QKST + u];
    #pragma unroll
    for (int off = 16; off; off >>= 1) s += __shfl_xor_sync(0xffffffffu, s, off);
    float mean = s * (1.f/128.f);
    for (int u = lane; u < 128; u += 32) qkv[r*QKST + u] -= mean;
  }
  __syncthreads();

  // 3.5 pack Q/K k-pairs bf16 hi/lo (Xp dead)
  for (int loop = 0; loop < 8; loop++) {
    int u = t & 127;
    int kp = (t >> 7) + loop*8;
    float v0 = qkv[(2*kp)*QKST + u];
    float v1 = qkv[(2*kp+1)*QKST + u];
    unsigned lo;
    unsigned hi = bfsplit(v0, v1, lo);
    if (kp < 32) { Qph[u*QPST + kp] = hi;      Qpl[u*QPST + kp] = lo; }
    else         { Kph[u*QPST + kp-32] = hi;   Kpl[u*QPST + kp-32] = lo; }
  }
  __syncthreads();

  // 4. GEMM1 via bf16 mma: S -> Sb (qkv dead)
  {
    int u0 = (warp >> 2) * 16, v0 = (warp & 3) * 32;
    float d[4][4];
    #pragma unroll
    for (int j = 0; j < 4; j++)
      d[j][0] = d[j][1] = d[j][2] = d[j][3] = 0.f;
    #pragma unroll
    for (int ks = 0; ks < 4; ks++) {
      int kp = ks*8 + tig;
      int ra = (u0+g)*QPST + kp, rb = (u0+g+8)*QPST + kp;
      unsigned ah0 = Qph[ra],   ah1 = Qph[rb];
      unsigned ah2 = Qph[ra+4], ah3 = Qph[rb+4];
      unsigned al0 = Qpl[ra],   al1 = Qpl[rb];
      unsigned al2 = Qpl[ra+4], al3 = Qpl[rb+4];
      #pragma unroll
      for (int j = 0; j < 4; j++) {
        int ci = (v0 + j*8 + g)*QPST + kp;
        unsigned bh0 = Kph[ci], bh1 = Kph[ci+4];
        unsigned bl0 = Kpl[ci], bl1 = Kpl[ci+4];
        mma_bf16(d[j][0],d[j][1],d[j][2],d[j][3], al0,al1,al2,al3, bh0,bh1);
        mma_bf16(d[j][0],d[j][1],d[j][2],d[j][3], ah0,ah1,ah2,ah3, bl0,bl1);
        mma_bf16(d[j][0],d[j][1],d[j][2],d[j][3], ah0,ah1,ah2,ah3, bh0,bh1);
      }
    }
    #pragma unroll
    for (int j = 0; j < 4; j++) {
      int col = v0 + j*8 + 2*tig;
      *(float2*)&Sb[(u0+g)*SST + col]   = make_float2(d[j][0], d[j][1]);
      *(float2*)&Sb[(u0+g+8)*SST + col] = make_float2(d[j][2], d[j][3]);
    }
  }
  __syncthreads();

  // 5. max scans + combine + factors
  if (warp < 16) {
    for (int r = warp*8; r < warp*8 + 8; r++) {
      float m = -1e30f;
      #pragma unroll
      for (int j = 0; j < 4; j++) m = fmaxf(m, Sb[r*SST + lane + j*32]);
      #pragma unroll
      for (int off = 16; off; off >>= 1) m = fmaxf(m, __shfl_xor_sync(0xffffffffu, m, off));
      if (lane == 0) rmax[r] = m;
    }
  } else {
    int j = warp - 16;
    int c = (j & 3)*32 + lane;
    int r0 = (j >> 2)*32;
    float m = -1e30f;
    for (int r = r0; r < r0 + 32; r++) m = fmaxf(m, Sb[r*SST + c]);
    part[(j >> 2)*128 + c] = m;
  }
  __syncthreads();
  if (t < 128) {
    cmax[t] = fmaxf(fmaxf(part[t], part[128+t]), fmaxf(part[256+t], part[384+t]));
  } else if (t < 160) {
    int l = t - 128;
    float m = fmaxf(fmaxf(rmax[l], rmax[l+32]), fmaxf(rmax[l+64], rmax[l+96]));
    #pragma unroll
    for (int off = 16; off; off >>= 1) m = fmaxf(m, __shfl_xor_sync(0xffffffffu, m, off));
    if (l == 0) Mg[0] = m;
  }
  __syncthreads();
  if (t < 128) {
    float M = Mg[0];
    fr[t] = __expf(rmax[t] - M);
    gc[t] = __expf(M - cmax[t]);
  }
  __syncthreads();

  // 6. exp + A2/At packing + sums — all 32 warps
  {
    int r0 = warp*4;
    int cA = 2*lane, cB = cA + 64;
    float g0 = gc[cA], g1v = gc[cA+1], g2 = gc[cB], g3 = gc[cB+1];
    float cs0=0.f, cs1=0.f, cs2=0.f, cs3=0.f;
    float p0=0.f, p1=0.f, p2=0.f, p3=0.f;
    #pragma unroll
    for (int rr = 0; rr < 4; rr++) {
      int r = r0 + rr;
      float rm = rmax[r], frv = fr[r];
      float2 sA = *(const float2*)&Sb[r*SST + cA];
      float2 sB = *(const float2*)&Sb[r*SST + cB];
      float e0 = __expf(sA.x - rm), e1 = __expf(sA.y - rm);
      float e2 = __expf(sB.x - rm), e3 = __expf(sB.y - rm);
      float rs = e0 + e1 + e2 + e3;
      float a0 = e0*frv, a1 = e1*frv, a2 = e2*frv, a3 = e3*frv;
      cs0 += a0*g0; cs1 += a1*g1v; cs2 += a2*g2; cs3 += a3*g3;
      __nv_bfloat16 h0 = __float2bfloat16(a0), h1 = __float2bfloat16(a1);
      __nv_bfloat16 h2 = __float2bfloat16(a2), h3 = __float2bfloat16(a3);
      A2h[r*A2ST + lane]      = bfpk(h0, h1);
      A2l[r*A2ST + lane]      = bfpk(__float2bfloat16(a0 - __bfloat162float(h0)),
                                     __float2bfloat16(a1 - __bfloat162float(h1)));
      A2h[r*A2ST + lane + 32] = bfpk(h2, h3);
      A2l[r*A2ST + lane + 32] = bfpk(__float2bfloat16(a2 - __bfloat162float(h2)),
                                     __float2bfloat16(a3 - __bfloat162float(h3)));
      if (rr & 1) {
        int vp = warp*2 + (rr >> 1);
        __nv_bfloat16 q0 = __float2bfloat16(p0), q1 = __float2bfloat16(p1);
        __nv_bfloat16 q2 = __float2bfloat16(p2), q3 = __float2bfloat16(p3);
        Ath[cA*ATST + vp]     = bfpk(q0, h0);
        Atl[cA*ATST + vp]     = bfpk(__float2bfloat16(p0 - __bfloat162float(q0)),
                                     __float2bfloat16(a0 - __bfloat162float(h0)));
        Ath[(cA+1)*ATST + vp] = bfpk(q1, h1);
        Atl[(cA+1)*ATST + vp] = bfpk(__float2bfloat16(p1 - __bfloat162float(q1)),
                                     __float2bfloat16(a1 - __bfloat162float(h1)));
        Ath[cB*ATST + vp]     = bfpk(q2, h2);
        Atl[cB*ATST + vp]     = bfpk(__float2bfloat16(p2 - __bfloat162float(q2)),
                                     __float2bfloat16(a2 - __bfloat162float(h2)));
        Ath[(cB+1)*ATST + vp] = bfpk(q3, h3);
        Atl[(cB+1)*ATST + vp] = bfpk(__float2bfloat16(p3 - __bfloat162float(q3)),
                                     __float2bfloat16(a3 - __bfloat162float(h3)));
      } else { p0 = a0; p1 = a1; p2 = a2; p3 = a3; }
      #pragma unroll
      for (int off = 16; off; off >>= 1) rs += __shfl_xor_sync(0xffffffffu, rs, off);
      if (lane == 0) rsc[r] = 1.f / rs;
    }
    float* bank = (warp < 16) ? (part + warp*128) : (wsf + (warp-16)*128);
    bank[cA]   = cs0;
    bank[cA+1] = cs1;
    bank[cB]   = cs2;
    bank[cB+1] = cs3;
  }
  __syncthreads();
  if (t < 128) {
    float s = 0.f;
    #pragma unroll
    for (int w = 0; w < 16; w++) s += part[w*128 + t] + wsf[w*128 + t];
    gcc[t] = gc[t] / s;
    rsc[t] = __fdividef(rsc[t], fr[t]);
  }
  __syncthreads();

  // 7. banded Grams
  {
    bool isG = warp < 16;
    const unsigned* Ph = isG ? A2h : Ath;
    const unsigned* Pl = isG ? A2l : Atl;
    const float* wv = isG ? gcc : rsc;
    int stp = isG ? A2ST : ATST;
    int base = (warp & 15) * 8;
    float acc0[8], acc1[8], acc2g[8];
    #pragma unroll
    for (int i = 0; i < 8; i++) { acc0[i]=0.f; acc1[i]=0.f; acc2g[i]=0.f; }
    #pragma unroll
    for (int vj = 0; vj < 2; vj++) {
      int vp = vj*32 + lane;
      float w0 = wv[2*vp], w1 = wv[2*vp+1];
      float2 e0v = upk(Ph[base*stp + vp], Pl[base*stp + vp]);
      float2 e1v = upk(Ph[(base+1)*stp + vp], Pl[(base+1)*stp + vp]);
      #pragma unroll
      for (int i = 0; i < 8; i++) {
        int rn = base + i + 2;
        float2 e2v = (rn < 128) ? upk(Ph[rn*stp + vp], Pl[rn*stp + vp])
                                : make_float2(0.f, 0.f);
        acc0[i]  += e0v.x*w0*e0v.x + e0v.y*w1*e0v.y;
        acc1[i]  += e0v.x*w0*e1v.x + e0v.y*w1*e1v.y;
        acc2g[i] += e0v.x*w0*e2v.x + e0v.y*w1*e2v.y;
        e0v = e1v; e1v = e2v;
      }
    }
    int po = isG ? 0 : 384;
    #pragma unroll
    for (int i = 0; i < 8; i++) {
      #pragma unroll
      for (int off = 16; off; off >>= 1) {
        acc0[i]  += __shfl_xor_sync(0xffffffffu, acc0[i],  off);
        acc1[i]  += __shfl_xor_sync(0xffffffffu, acc1[i],  off);
        acc2g[i] += __shfl_xor_sync(0xffffffffu, acc2g[i], off);
      }
      if (lane == 0) {
        part[po + base+i]       = acc0[i];
        part[po + 128 + base+i] = acc1[i];
        part[po + 256 + base+i] = acc2g[i];
      }
    }
  }
  __syncthreads();

  // 8. x bf16 packing + V maps
  for (int i = t; i < 8192; i += 1024) {
    int img = i >> 12, j = i & 4095, c = j >> 6, vp = j & 63;
    const float* src = img ? xR : xL;
    float2 v = *(const float2*)&src[((size_t)(b*NC + c)*NH + h)*NW + 2*vp];
    unsigned* ph = (unsigned*)(sm + (img ? OFF_XRP_H : OFF_XLP_H));
    unsigned* pl = (unsigned*)(sm + (img ? OFF_XRP_L : OFF_XLP_L));
    unsigned lo;
    ph[c*XPST + vp] = bfsplit(v.x, v.y, lo);
    pl[c*XPST + vp] = lo;
  }
  if (t < 128) {
    int u = t;
    float accL = rsc[u]*part[u];
    if (u+1 < 128) accL += rsc[u+1]*part[128+u];
    if (u+2 < 128) accL += rsc[u+2]*part[256+u];
    if (u >= 1)    accL += rsc[u-1]*part[128+u-1];
    if (u >= 2)    accL += rsc[u-2]*part[256+u-2];
    Vl[u] = tanhf(5.f*accL);
  } else if (t < 256) {
    int u = t - 128;
    float accR = gcc[u]*part[384+u];
    if (u+1 < 128) accR += gcc[u+1]*part[512+u];
    if (u+2 < 128) accR += gcc[u+2]*part[640+u];
    if (u >= 1)    accR += gcc[u-1]*part[512+u-1];
    if (u >= 2)    accR += gcc[u-2]*part[640+u-2];
    Vr[u] = tanhf(5.f*accR);
  }
  __syncthreads();

  // 9. GEMM2/3 via bf16 mma + blend epilogue
  {
    bool left = warp < 16;
    int gw = warp & 15;
    int u0 = (gw >> 1) * 16, nb = (gw & 1) * 32;
    const unsigned* Ah = left ? A2h : Ath;
    const unsigned* Al = left ? A2l : Atl;
    const unsigned* Bh = (const unsigned*)(sm + (left ? OFF_XRP_H : OFF_XLP_H));
    const unsigned* Bl = (const unsigned*)(sm + (left ? OFF_XRP_L : OFF_XLP_L));
    float d[4][4];
    #pragma unroll
    for (int j = 0; j < 4; j++)
      d[j][0] = d[j][1] = d[j][2] = d[j][3] = 0.f;
    for (int ks = 0; ks < 8; ks++) {
      int vp = ks*8 + tig;
      int ra = (u0+g)*A2ST + vp, rb = (u0+g+8)*A2ST + vp;
      unsigned ah0 = Ah[ra],   ah1 = Ah[rb];
      unsigned ah2 = Ah[ra+4], ah3 = Ah[rb+4];
      unsigned al0 = Al[ra],   al1 = Al[rb];
      unsigned al2 = Al[ra+4], al3 = Al[rb+4];
      #pragma unroll
      for (int j = 0; j < 4; j++) {
        int ci = (nb + j*8 + g)*XPST + vp;
        unsigned bh0 = Bh[ci], bh1 = Bh[ci+4];
        unsigned bl0 = Bl[ci], bl1 = Bl[ci+4];
        mma_bf16(d[j][0],d[j][1],d[j][2],d[j][3], al0,al1,al2,al3, bh0,bh1);
        mma_bf16(d[j][0],d[j][1],d[j][2],d[j][3], ah0,ah1,ah2,ah3, bl0,bl1);
        mma_bf16(d[j][0],d[j][1],d[j][2],d[j][3], ah0,ah1,ah2,ah3, bh0,bh1);
      }
    }
    const float* xg = left ? xL : xR;
    float* og = left ? outL : outR;
    const float* Vv = left ? Vl : Vr;
    const float* scv = left ? rsc : gcc;
    int ua = u0 + g, ub = u0 + g + 8;
    float va = Vv[ua], vb = Vv[ub];
    float sa = scv[ua]*va, sb2 = scv[ub]*vb;
    float ia = 1.f - va, ib = 1.f - vb;
    #pragma unroll
    for (int j = 0; j < 4; j++) {
      int c = nb + j*8 + 2*tig;
      size_t b0i = ((size_t)(b*NC + c)*NH + h)*NW;
      size_t b1i = b0i + (size_t)HW;
      og[b0i + ua] = xg[b0i + ua]*ia + d[j][0]*sa;
      og[b1i + ua] = xg[b1i + ua]*ia + d[j][1]*sa;
      og[b0i + ub] = xg[b0i + ub]*ib + d[j][2]*sb2;
      og[b1i + ub] = xg[b1i + ub]*ib + d[j][3]*sb2;
    }
  }
}

// ---------------- host ------------------------------------------------------
extern "C" void kernel_launch(void* const* d_in, const int* in_sizes, int n_in,
                              void* d_out, int out_size) {
  const float* xL    = (const float*)d_in[0];
  const float* xR    = (const float*)d_in[1];
  const float* gamma = (const float*)d_in[2];
  const float* beta  = (const float*)d_in[3];
  const float* w1    = (const float*)d_in[4];
  const float* b1    = (const float*)d_in[5];
  const float* w2    = (const float*)d_in[6];
  const float* b2    = (const float*)d_in[7];
  const float* qw    = (const float*)d_in[8];
  const float* qb    = (const float*)d_in[9];
  const float* kw    = (const float*)d_in[10];
  const float* kb    = (const float*)d_in[11];
  float* outL = (float*)d_out;
  float* outR = outL + (size_t)IMG;

  float *t1, *t2;
  unsigned *wth, *wtl;
  cudaGetSymbolAddress((void**)&t1, g_t1);
  cudaGetSymbolAddress((void**)&t2, g_t2);
  cudaGetSymbolAddress((void**)&wth, g_wth);
  cudaGetSymbolAddress((void**)&wtl, g_wtl);

  cudaFuncSetAttribute(conv3x3_kernel<true>,  cudaFuncAttributeMaxDynamicSharedMemorySize, CONV_SMEM);
  cudaFuncSetAttribute(conv3x3_kernel<false>, cudaFuncAttributeMaxDynamicSharedMemorySize, CONV_SMEM);
  cudaFuncSetAttribute(attn_kernel, cudaFuncAttributeMaxDynamicSharedMemorySize, ATTN_SMEM);

  bn_stats_kernel<<<128, 256>>>(xL, xR, gamma, beta);
  wtrans_kernel<<<(2*NG*9*16*8 + 255)/256, 256>>>(w1, w2);

  dim3 cgrid(NH/4, NB*NG, 2);
  conv3x3_kernel<true ><<<cgrid, 256, CONV_SMEM>>>(
      xL, xR, t1, t2, wth, wtl, b1);
  conv3x3_kernel<false><<<cgrid, 256, CONV_SMEM>>>(
      xL, xR, t1, t2, wth + 4608, wtl + 4608, b2);

  attn_kernel<<<NROW, 1024, ATTN_SMEM>>>(t2, xL, xR, qw, qb, kw, kb, outL, outR);
}

// round 17
// speedup vs baseline: 1.6937x; 1.0182x over previous
#include <cuda_runtime.h>
#include <cuda_bf16.h>
#include <math.h>

#define NB 8
#define NC 64
#define NG 4
#define CG 16
#define NH 128
#define NW 128
#define HW (NH*NW)
#define IMG (NB*NC*HW)
#define NROW (NB*NH)

typedef unsigned long long u64;

__device__ __forceinline__ u64 f2dup(float v) {
  u64 r; asm("mov.b64 %0, {%1, %1};" : "=l"(r) : "f"(v)); return r;
}
__device__ __forceinline__ u64 f2pk(float a, float b) {
  u64 r; asm("mov.b64 %0, {%1, %2};" : "=l"(r) : "f"(a), "f"(b)); return r;
}
__device__ __forceinline__ void fma2(u64& d, u64 a, u64 b) {
  asm("fma.rn.f32x2 %0, %1, %2, %0;" : "+l"(d) : "l"(a), "l"(b));
}
__device__ __forceinline__ float2 f2up(u64 v) {
  float2 f; asm("mov.b64 {%0, %1}, %2;" : "=f"(f.x), "=f"(f.y) : "l"(v)); return f;
}
__device__ __forceinline__ void mma_bf16(
    float& d0, float& d1, float& d2, float& d3,
    unsigned a0, unsigned a1, unsigned a2, unsigned a3,
    unsigned b0, unsigned b1) {
  asm volatile(
    "mma.sync.aligned.m16n8k16.row.col.f32.bf16.bf16.f32 "
    "{%0,%1,%2,%3}, {%4,%5,%6,%7}, {%8,%9}, {%0,%1,%2,%3};"
    : "+f"(d0), "+f"(d1), "+f"(d2), "+f"(d3)
    : "r"(a0), "r"(a1), "r"(a2), "r"(a3), "r"(b0), "r"(b1));
}
__device__ __forceinline__ unsigned bfpk(__nv_bfloat16 a, __nv_bfloat16 b) {
  __nv_bfloat162 h = __halves2bfloat162(a, b);
  return *(unsigned*)&h;
}
// pack truncated hi16 of (a,b): low half <- hi16(a), high half <- hi16(b)
__device__ __forceinline__ unsigned prmt76(unsigned a, unsigned b) {
  unsigned d; asm("prmt.b32 %0, %1, %2, 0x7632;" : "=r"(d) : "r"(a), "r"(b));
  return d;
}
// pack bf16x2: {hiVal -> high half, loVal -> low half}
__device__ __forceinline__ unsigned cvtbf2(float hiVal, float loVal) {
  unsigned d;
  asm("cvt.rn.bf16x2.f32 %0, %1, %2;" : "=r"(d) : "f"(hiVal), "f"(loVal));
  return d;
}
// fast truncation-based hi/lo split (drop-in for rounded version)
__device__ __forceinline__ unsigned bfsplit(float a, float b, unsigned& lo) {
  unsigned ia = __float_as_uint(a), ib = __float_as_uint(b);
  float la = a - __uint_as_float(ia & 0xffff0000u);
  float lb = b - __uint_as_float(ib & 0xffff0000u);
  lo = cvtbf2(lb, la);
  return prmt76(ia, ib);
}
__device__ __forceinline__ float2 upk(unsigned h, unsigned l) {
  __nv_bfloat162 hb = *(__nv_bfloat162*)&h;
  __nv_bfloat162 lb = *(__nv_bfloat162*)&l;
  return make_float2(__low2float(hb) + __low2float(lb),
                     __high2float(hb) + __high2float(lb));
}

// ---------------- scratch ----------------------------------------------------
__device__ float g_t1[2*(size_t)IMG];
__device__ float g_t2[2*(size_t)IMG];
__device__ float g_bnA[2][NC];
__device__ float g_bnB[2][NC];
__device__ __align__(16) unsigned g_wth[2][NG*9*16*8];
__device__ __align__(16) unsigned g_wtl[2][NG*9*16*8];

// ---------------- BN statistics ----------------------------------------------
__global__ __launch_bounds__(256) void bn_stats_kernel(
    const float* __restrict__ xl, const float* __restrict__ xr,
    const float* __restrict__ gamma, const float* __restrict__ beta) {
  int c = blockIdx.x & 63;
  int img = blockIdx.x >> 6;
  const float4* x = (const float4*)(img ? xr : xl);
  int t = threadIdx.x;
  float s = 0.f, s2 = 0.f;
  for (int b = 0; b < NB; b++) {
    const float4* p = x + (size_t)(b*NC + c)*(HW/4);
    for (int i = t; i < HW/4; i += 256) {
      float4 v = p[i];
      s  += v.x + v.y + v.z + v.w;
      s2 += v.x*v.x + v.y*v.y + v.z*v.z + v.w*v.w;
    }
  }
  __shared__ float sh[256], sh2[256];
  sh[t] = s; sh2[t] = s2; __syncthreads();
  for (int off = 128; off; off >>= 1) {
    if (t < off) { sh[t] += sh[t+off]; sh2[t] += sh2[t+off]; }
    __syncthreads();
  }
  if (t == 0) {
    const float inv = 1.f / (float)(NB*HW);
    float mean = sh[0] * inv;
    float var  = sh2[0] * inv - mean*mean;
    float a = gamma[c] * rsqrtf(var + 1e-5f);
    g_bnA[img][c] = a;
    g_bnB[img][c] = beta[c] - mean * a;
  }
}

// ---------------- weight prep (kept) ------------------------------------------
__global__ __launch_bounds__(256) void wtrans_kernel(
    const float* __restrict__ w1, const float* __restrict__ w2) {
  int i = blockIdx.x * 256 + threadIdx.x;
  if (i >= 2*NG*9*16*8) return;
  int layer = i / 4608;
  int j = i - layer*4608;
  int g = j / 1152;
  int r = j - g*1152;
  int khkw = r >> 7;
  int q = r & 127;
  int oc = q >> 3, p = q & 7;
  const float* src = layer ? w2 : w1;
  int base = g*(CG*CG*9) + oc*(CG*9) + (2*p)*9 + khkw;
  float w0 = src[base], w1v = src[base + 9];
  unsigned lo;
  g_wth[layer][j] = bfsplit(w0, w1v, lo);
  g_wtl[layer][j] = lo;
}

// ---------------- grouped 3x3 conv (R12 structure, fast split) ---------------
#define PRST 136
#define ROWST (8*PRST)
#define CIN_U32 (6*ROWST)
#define CONV_SMEM (2*CIN_U32*4)

template<bool FIRST>
__global__ __launch_bounds__(256, 3) void conv3x3_kernel(
    const float* __restrict__ xL, const float* __restrict__ xR,
    float* __restrict__ t1, float* __restrict__ t2,
    const unsigned* __restrict__ wth, const unsigned* __restrict__ wtl,
    const float* __restrict__ bias) {
  extern __shared__ unsigned smu[];
  unsigned* in_hi = smu;
  unsigned* in_lo = smu + CIN_U32;
  int t = threadIdx.x;
  int img = blockIdx.z;
  int b = blockIdx.y >> 2, grp = blockIdx.y & 3;
  int h0 = blockIdx.x * 4;
  const float* xorig = img ? xR : xL;
  const float* xin = FIRST ? xorig : (t1 + (size_t)img*IMG);
  float* out = (FIRST ? t1 : t2) + (size_t)img*IMG;

  for (int i = t; i < CIN_U32; i += 256) {
    int col  = i % PRST;
    int rest = i / PRST;
    int pair = rest & 7;
    int row  = rest >> 3;
    int hh = h0 - 1 + row;
    int ww = col - 1;
    float v0 = 0.f, v1 = 0.f;
    if ((unsigned)hh < (unsigned)NH && (unsigned)ww < (unsigned)NW) {
      int ch = grp*CG + 2*pair;
      size_t gidx = ((size_t)(b*NC + ch)*NH + hh)*NW + ww;
      v0 = xin[gidx];
      v1 = xin[gidx + HW];
      if (FIRST) {
        v0 = g_bnA[img][ch]*v0 + g_bnB[img][ch];
        v1 = g_bnA[img][ch+1]*v1 + g_bnB[img][ch+1];
      }
    }
    unsigned lo;
    in_hi[i] = bfsplit(v0, v1, lo);
    in_lo[i] = lo;
  }
  __syncthreads();

  int warp = t >> 5, lane = t & 31;
  int gr = lane >> 2, tig = lane & 3;
  int hh = warp >> 1;
  int wbase = (warp & 1) * 64;

  const unsigned* whg = wth + grp*(9*128);
  const unsigned* wlg = wtl + grp*(9*128);

  float d[8][4];
  #pragma unroll
  for (int nt = 0; nt < 8; nt++)
    d[nt][0] = d[nt][1] = d[nt][2] = d[nt][3] = 0.f;

  #pragma unroll
  for (int khkw = 0; khkw < 9; khkw++) {
    const int kh = khkw / 3, kw = khkw % 3;
    const unsigned* wh = whg + khkw*128;
    const unsigned* wl = wlg + khkw*128;
    unsigned ah0 = __ldg(wh + gr*8 + tig);
    unsigned ah1 = __ldg(wh + gr*8 + tig + 64);
    unsigned ah2 = __ldg(wh + gr*8 + tig + 4);
    unsigned ah3 = __ldg(wh + gr*8 + tig + 68);
    unsigned al0 = __ldg(wl + gr*8 + tig);
    unsigned al1 = __ldg(wl + gr*8 + tig + 64);
    unsigned al2 = __ldg(wl + gr*8 + tig + 4);
    unsigned al3 = __ldg(wl + gr*8 + tig + 68);
    int base_in = (hh + kh)*ROWST + tig*PRST + wbase + kw + gr;
    #pragma unroll
    for (int nt = 0; nt < 8; nt++) {
      int coln = base_in + nt*8;
      unsigned bh0 = in_hi[coln];
      unsigned bh1 = in_hi[coln + 4*PRST];
      unsigned bl0 = in_lo[coln];
      unsigned bl1 = in_lo[coln + 4*PRST];
      mma_bf16(d[nt][0],d[nt][1],d[nt][2],d[nt][3], al0,al1,al2,al3, bh0,bh1);
      mma_bf16(d[nt][0],d[nt][1],d[nt][2],d[nt][3], ah0,ah1,ah2,ah3, bl0,bl1);
      mma_bf16(d[nt][0],d[nt][1],d[nt][2],d[nt][3], ah0,ah1,ah2,ah3, bh0,bh1);
    }
  }

  int hout = h0 + hh;
  int ch0 = grp*CG + gr;
  int ch1 = ch0 + 8;
  float bz0 = bias[ch0], bz1 = bias[ch1];
  float ra0 = 0.f, rb0 = 0.f, ra1 = 0.f, rb1 = 0.f;
  if (!FIRST) {
    ra0 = g_bnA[img][ch0]; rb0 = g_bnB[img][ch0];
    ra1 = g_bnA[img][ch1]; rb1 = g_bnB[img][ch1];
  }
  size_t base0 = ((size_t)(b*NC + ch0)*NH + hout)*NW;
  size_t base1 = ((size_t)(b*NC + ch1)*NH + hout)*NW;
  #pragma unroll
  for (int nt = 0; nt < 8; nt++) {
    int w2c = wbase + nt*8 + 2*tig;
    float v0 = d[nt][0] + bz0, v1 = d[nt][1] + bz0;
    float v2 = d[nt][2] + bz1, v3 = d[nt][3] + bz1;
    if (FIRST) {
      v0 = v0 > 0.f ? v0 : 0.1f*v0;
      v1 = v1 > 0.f ? v1 : 0.1f*v1;
      v2 = v2 > 0.f ? v2 : 0.1f*v2;
      v3 = v3 > 0.f ? v3 : 0.1f*v3;
    } else {
      float2 x0 = *(const float2*)&xorig[base0 + w2c];
      float2 x1 = *(const float2*)&xorig[base1 + w2c];
      v0 += ra0*x0.x + rb0;  v1 += ra0*x0.y + rb0;
      v2 += ra1*x1.x + rb1;  v3 += ra1*x1.y + rb1;
    }
    *(float2*)&out[base0 + w2c] = make_float2(v0, v1);
    *(float2*)&out[base1 + w2c] = make_float2(v2, v3);
  }
}

// ---------------- fused attention: all-mma, fast splits ----------------------
#define SST 132
#define QKST 130
#define QPST 37
#define XST2 65
#define A2ST 66
#define ATST 66
#define XPST 66
#define OFF_XLP_H 0
#define OFF_XLP_L 4224
#define OFF_XRP_H 8448
#define OFF_XRP_L 12672
#define OFF_QKV   0
#define OFF_XP    16896
#define OFF_QPH   16896
#define OFF_QPL   21632
#define OFF_KPH   26368
#define OFF_KPL   31104
#define OFF_A2H   16896
#define OFF_A2L   25344
#define OFF_ATH   33792
#define OFF_ATL   42240
#define OFF_WS    50688
#define OFF_BS    52736
#define OFF_RMAX  52864
#define OFF_RSC   52992
#define OFF_CMAX  53120
#define OFF_GCC   53248
#define OFF_VL    53376
#define OFF_VR    53504
#define OFF_PART  53632
#define OFF_FR    55680
#define OFF_GC    55808
#define OFF_MG    55936
#define ATTN_SMEM ((55936 + 32)*4)   // 223872 B

__global__ __launch_bounds__(1024, 1) void attn_kernel(
    const float* __restrict__ t2, const float* __restrict__ xL,
    const float* __restrict__ xR,
    const float* __restrict__ qw, const float* __restrict__ qb,
    const float* __restrict__ kw_, const float* __restrict__ kb,
    float* __restrict__ outL, float* __restrict__ outR) {
  extern __shared__ float sm[];
  float* Sb    = sm;
  float* qkv   = sm + OFF_QKV;
  unsigned* Xph = (unsigned*)(sm + OFF_XP);
  unsigned* Xpl = Xph + 8320;
  unsigned* Qph = (unsigned*)(sm + OFF_QPH);
  unsigned* Qpl = (unsigned*)(sm + OFF_QPL);
  unsigned* Kph = (unsigned*)(sm + OFF_KPH);
  unsigned* Kpl = (unsigned*)(sm + OFF_KPL);
  unsigned* A2h = (unsigned*)(sm + OFF_A2H);
  unsigned* A2l = (unsigned*)(sm + OFF_A2L);
  unsigned* Ath = (unsigned*)(sm + OFF_ATH);
  unsigned* Atl = (unsigned*)(sm + OFF_ATL);
  unsigned* Wph = (unsigned*)(sm + OFF_WS);
  unsigned* Wpl = Wph + 1024;
  float* wsf   = sm + OFF_WS;
  float* bs    = sm + OFF_BS;
  float* rmax  = sm + OFF_RMAX;
  float* rsc   = sm + OFF_RSC;
  float* cmax  = sm + OFF_CMAX;
  float* gcc   = sm + OFF_GCC;
  float* Vl    = sm + OFF_VL;
  float* Vr    = sm + OFF_VR;
  float* part  = sm + OFF_PART;
  float* fr    = sm + OFF_FR;
  float* gc    = sm + OFF_GC;
  float* Mg    = sm + OFF_MG;
  int n = blockIdx.x, b = n >> 7, h = n & 127;
  int t = threadIdx.x, warp = t >> 5, lane = t & 31;
  int g = lane >> 2, tig = lane & 3;

  // 1. pack weights + bias + X stage/pack
  {
    int k = t >> 3, p = t & 7;
    const float* wsrc = (k < 64) ? qw : kw_;
    int kk = k & 63;
    float w0 = wsrc[kk*16 + 2*p], w1v = wsrc[kk*16 + 2*p + 1];
    unsigned lo;
    Wph[t] = bfsplit(w0, w1v, lo);
    Wpl[t] = lo;
  }
  if (t < 128) bs[t] = (t < 64) ? qb[t] : kb[t-64];
  for (int i = t; i < 8192; i += 1024) {
    int u = i & 127, cp = i >> 7;
    int c = 2*cp;
    size_t gi = ((c >= 64) ? (size_t)IMG : 0) +
                ((size_t)(b*NC + (c & 63))*NH + h)*NW + u;
    float v0 = t2[gi], v1 = t2[gi + HW];
    unsigned lo;
    Xph[u*XST2 + cp] = bfsplit(v0, v1, lo);
    Xpl[u*XST2 + cp] = lo;
  }
  __syncthreads();

  // 2. 1x1 grouped conv via bf16 mma
  {
    int gg = warp >> 3, sub = warp & 7;
    int mt = sub >> 2, n0 = (sub & 3)*32;
    int krow0 = mt*64 + gg*16;
    int pbase = mt*32 + gg*8;
    float d[4][4];
    #pragma unroll
    for (int j = 0; j < 4; j++)
      d[j][0] = d[j][1] = d[j][2] = d[j][3] = 0.f;
    int ra = (krow0+g)*8 + tig, rb = (krow0+g+8)*8 + tig;
    unsigned ah0 = Wph[ra],   ah1 = Wph[rb];
    unsigned ah2 = Wph[ra+4], ah3 = Wph[rb+4];
    unsigned al0 = Wpl[ra],   al1 = Wpl[rb];
    unsigned al2 = Wpl[ra+4], al3 = Wpl[rb+4];
    #pragma unroll
    for (int j = 0; j < 4; j++) {
      int u = n0 + j*8 + g;
      int ci = u*XST2 + pbase + tig;
      unsigned bh0 = Xph[ci], bh1 = Xph[ci+4];
      unsigned bl0 = Xpl[ci], bl1 = Xpl[ci+4];
      mma_bf16(d[j][0],d[j][1],d[j][2],d[j][3], al0,al1,al2,al3, bh0,bh1);
      mma_bf16(d[j][0],d[j][1],d[j][2],d[j][3], ah0,ah1,ah2,ah3, bl0,bl1);
      mma_bf16(d[j][0],d[j][1],d[j][2],d[j][3], ah0,ah1,ah2,ah3, bh0,bh1);
    }
    int ua = krow0 + g, ub = ua + 8;
    float ba = bs[ua], bb = bs[ub];
    #pragma unroll
    for (int j = 0; j < 4; j++) {
      int col = n0 + j*8 + 2*tig;
      *(float2*)&qkv[ua*QKST + col] = make_float2(d[j][0]+ba, d[j][1]+ba);
      *(float2*)&qkv[ub*QKST + col] = make_float2(d[j][2]+bb, d[j][3]+bb);
    }
  }
  __syncthreads();

  // 3. row means only (into part[0..127], free until phase 5)
  for (int r = warp; r < 128; r += 32) {
    float s = 0.f;
    for (int u = lane; u < 128; u += 32) s += qkv[r*QKST + u];
    #pragma unroll
    for (int off = 16; off; off >>= 1) s += __shfl_xor_sync(0xffffffffu, s, off);
    if (lane == 0) part[r] = s * (1.f/128.f);
  }
  __syncthreads();

  // 3.5 pack Q/K k-pairs bf16 hi/lo, mean subtracted inline (Xp dead)
  for (int loop = 0; loop < 8; loop++) {
    int u = t & 127;
    int kp = (t >> 7) + loop*8;
    float v0 = qkv[(2*kp)*QKST + u]   - part[2*kp];
    float v1 = qkv[(2*kp+1)*QKST + u] - part[2*kp+1];
    unsigned lo;
    unsigned hi = bfsplit(v0, v1, lo);
    if (kp < 32) { Qph[u*QPST + kp] = hi;      Qpl[u*QPST + kp] = lo; }
    else         { Kph[u*QPST + kp-32] = hi;   Kpl[u*QPST + kp-32] = lo; }
  }
  __syncthreads();

  // 4. GEMM1 via bf16 mma: S -> Sb (qkv dead)
  {
    int u0 = (warp >> 2) * 16, v0 = (warp & 3) * 32;
    float d[4][4];
    #pragma unroll
    for (int j = 0; j < 4; j++)
      d[j][0] = d[j][1] = d[j][2] = d[j][3] = 0.f;
    #pragma unroll
    for (int ks = 0; ks < 4; ks++) {
      int kp = ks*8 + tig;
      int ra = (u0+g)*QPST + kp, rb = (u0+g+8)*QPST + kp;
      unsigned ah0 = Qph[ra],   ah1 = Qph[rb];
      unsigned ah2 = Qph[ra+4], ah3 = Qph[rb+4];
      unsigned al0 = Qpl[ra],   al1 = Qpl[rb];
      unsigned al2 = Qpl[ra+4], al3 = Qpl[rb+4];
      #pragma unroll
      for (int j = 0; j < 4; j++) {
        int ci = (v0 + j*8 + g)*QPST + kp;
        unsigned bh0 = Kph[ci], bh1 = Kph[ci+4];
        unsigned bl0 = Kpl[ci], bl1 = Kpl[ci+4];
        mma_bf16(d[j][0],d[j][1],d[j][2],d[j][3], al0,al1,al2,al3, bh0,bh1);
        mma_bf16(d[j][0],d[j][1],d[j][2],d[j][3], ah0,ah1,ah2,ah3, bl0,bl1);
        mma_bf16(d[j][0],d[j][1],d[j][2],d[j][3], ah0,ah1,ah2,ah3, bh0,bh1);
      }
    }
    #pragma unroll
    for (int j = 0; j < 4; j++) {
      int col = v0 + j*8 + 2*tig;
      *(float2*)&Sb[(u0+g)*SST + col]   = make_float2(d[j][0], d[j][1]);
      *(float2*)&Sb[(u0+g+8)*SST + col] = make_float2(d[j][2], d[j][3]);
    }
  }
  __syncthreads();

  // 5. max scans + combine + factors
  if (warp < 16) {
    for (int r = warp*8; r < warp*8 + 8; r++) {
      float m = -1e30f;
      #pragma unroll
      for (int j = 0; j < 4; j++) m = fmaxf(m, Sb[r*SST + lane + j*32]);
      #pragma unroll
      for (int off = 16; off; off >>= 1) m = fmaxf(m, __shfl_xor_sync(0xffffffffu, m, off));
      if (lane == 0) rmax[r] = m;
    }
  } else {
    int j = warp - 16;
    int c = (j & 3)*32 + lane;
    int r0 = (j >> 2)*32;
    float m = -1e30f;
    for (int r = r0; r < r0 + 32; r++) m = fmaxf(m, Sb[r*SST + c]);
    part[(j >> 2)*128 + c] = m;
  }
  __syncthreads();
  if (t < 128) {
    cmax[t] = fmaxf(fmaxf(part[t], part[128+t]), fmaxf(part[256+t], part[384+t]));
  } else if (t < 160) {
    int l = t - 128;
    float m = fmaxf(fmaxf(rmax[l], rmax[l+32]), fmaxf(rmax[l+64], rmax[l+96]));
    #pragma unroll
    for (int off = 16; off; off >>= 1) m = fmaxf(m, __shfl_xor_sync(0xffffffffu, m, off));
    if (l == 0) Mg[0] = m;
  }
  __syncthreads();
  if (t < 128) {
    float M = Mg[0];
    fr[t] = __expf(rmax[t] - M);
    gc[t] = __expf(M - cmax[t]);
  }
  __syncthreads();

  // 6. exp + A2/At packing (fast splits) + sums — all 32 warps
  {
    int r0 = warp*4;
    int cA = 2*lane, cB = cA + 64;
    float g0 = gc[cA], g1v = gc[cA+1], g2 = gc[cB], g3 = gc[cB+1];
    float cs0=0.f, cs1=0.f, cs2=0.f, cs3=0.f;
    unsigned ip0=0, ip1=0, ip2=0, ip3=0;
    float lp0=0.f, lp1=0.f, lp2=0.f, lp3=0.f;
    #pragma unroll
    for (int rr = 0; rr < 4; rr++) {
      int r = r0 + rr;
      float rm = rmax[r], frv = fr[r];
      float2 sA = *(const float2*)&Sb[r*SST + cA];
      float2 sB = *(const float2*)&Sb[r*SST + cB];
      float e0 = __expf(sA.x - rm), e1 = __expf(sA.y - rm);
      float e2 = __expf(sB.x - rm), e3 = __expf(sB.y - rm);
      float rs = e0 + e1 + e2 + e3;
      float a0 = e0*frv, a1 = e1*frv, a2 = e2*frv, a3 = e3*frv;
      cs0 += a0*g0; cs1 += a1*g1v; cs2 += a2*g2; cs3 += a3*g3;
      unsigned ia0 = __float_as_uint(a0), ia1 = __float_as_uint(a1);
      unsigned ia2 = __float_as_uint(a2), ia3 = __float_as_uint(a3);
      float la0 = a0 - __uint_as_float(ia0 & 0xffff0000u);
      float la1 = a1 - __uint_as_float(ia1 & 0xffff0000u);
      float la2 = a2 - __uint_as_float(ia2 & 0xffff0000u);
      float la3 = a3 - __uint_as_float(ia3 & 0xffff0000u);
      A2h[r*A2ST + lane]      = prmt76(ia0, ia1);
      A2l[r*A2ST + lane]      = cvtbf2(la1, la0);
      A2h[r*A2ST + lane + 32] = prmt76(ia2, ia3);
      A2l[r*A2ST + lane + 32] = cvtbf2(la3, la2);
      if (rr & 1) {
        int vp = warp*2 + (rr >> 1);
        Ath[cA*ATST + vp]     = prmt76(ip0, ia0);
        Atl[cA*ATST + vp]     = cvtbf2(la0, lp0);
        Ath[(cA+1)*ATST + vp] = prmt76(ip1, ia1);
        Atl[(cA+1)*ATST + vp] = cvtbf2(la1, lp1);
        Ath[cB*ATST + vp]     = prmt76(ip2, ia2);
        Atl[cB*ATST + vp]     = cvtbf2(la2, lp2);
        Ath[(cB+1)*ATST + vp] = prmt76(ip3, ia3);
        Atl[(cB+1)*ATST + vp] = cvtbf2(la3, lp3);
      } else {
        ip0 = ia0; ip1 = ia1; ip2 = ia2; ip3 = ia3;
        lp0 = la0; lp1 = la1; lp2 = la2; lp3 = la3;
      }
      #pragma unroll
      for (int off = 16; off; off >>= 1) rs += __shfl_xor_sync(0xffffffffu, rs, off);
      if (lane == 0) rsc[r] = 1.f / rs;
    }
    float* bank = (warp < 16) ? (part + warp*128) : (wsf + (warp-16)*128);
    bank[cA]   = cs0;
    bank[cA+1] = cs1;
    bank[cB]   = cs2;
    bank[cB+1] = cs3;
  }
  __syncthreads();
  if (t < 128) {
    float s = 0.f;
    #pragma unroll
    for (int w = 0; w < 16; w++) s += part[w*128 + t] + wsf[w*128 + t];
    gcc[t] = gc[t] / s;
    rsc[t] = __fdividef(rsc[t], fr[t]);
  }
  __syncthreads();

  // 7. banded Grams
  {
    bool isG = warp < 16;
    const unsigned* Ph = isG ? A2h : Ath;
    const unsigned* Pl = isG ? A2l : Atl;
    const float* wv = isG ? gcc : rsc;
    int stp = isG ? A2ST : ATST;
    int base = (warp & 15) * 8;
    float acc0[8], acc1[8], acc2g[8];
    #pragma unroll
    for (int i = 0; i < 8; i++) { acc0[i]=0.f; acc1[i]=0.f; acc2g[i]=0.f; }
    #pragma unroll
    for (int vj = 0; vj < 2; vj++) {
      int vp = vj*32 + lane;
      float w0 = wv[2*vp], w1 = wv[2*vp+1];
      float2 e0v = upk(Ph[base*stp + vp], Pl[base*stp + vp]);
      float2 e1v = upk(Ph[(base+1)*stp + vp], Pl[(base+1)*stp + vp]);
      #pragma unroll
      for (int i = 0; i < 8; i++) {
        int rn = base + i + 2;
        float2 e2v = (rn < 128) ? upk(Ph[rn*stp + vp], Pl[rn*stp + vp])
                                : make_float2(0.f, 0.f);
        acc0[i]  += e0v.x*w0*e0v.x + e0v.y*w1*e0v.y;
        acc1[i]  += e0v.x*w0*e1v.x + e0v.y*w1*e1v.y;
        acc2g[i] += e0v.x*w0*e2v.x + e0v.y*w1*e2v.y;
        e0v = e1v; e1v = e2v;
      }
    }
    int po = isG ? 0 : 384;
    #pragma unroll
    for (int i = 0; i < 8; i++) {
      #pragma unroll
      for (int off = 16; off; off >>= 1) {
        acc0[i]  += __shfl_xor_sync(0xffffffffu, acc0[i],  off);
        acc1[i]  += __shfl_xor_sync(0xffffffffu, acc1[i],  off);
        acc2g[i] += __shfl_xor_sync(0xffffffffu, acc2g[i], off);
      }
      if (lane == 0) {
        part[po + base+i]       = acc0[i];
        part[po + 128 + base+i] = acc1[i];
        part[po + 256 + base+i] = acc2g[i];
      }
    }
  }
  __syncthreads();

  // 8. x bf16 packing + V maps
  for (int i = t; i < 8192; i += 1024) {
    int img = i >> 12, j = i & 4095, c = j >> 6, vp = j & 63;
    const float* src = img ? xR : xL;
    float2 v = *(const float2*)&src[((size_t)(b*NC + c)*NH + h)*NW + 2*vp];
    unsigned* ph = (unsigned*)(sm + (img ? OFF_XRP_H : OFF_XLP_H));
    unsigned* pl = (unsigned*)(sm + (img ? OFF_XRP_L : OFF_XLP_L));
    unsigned lo;
    ph[c*XPST + vp] = bfsplit(v.x, v.y, lo);
    pl[c*XPST + vp] = lo;
  }
  if (t < 128) {
    int u = t;
    float accL = rsc[u]*part[u];
    if (u+1 < 128) accL += rsc[u+1]*part[128+u];
    if (u+2 < 128) accL += rsc[u+2]*part[256+u];
    if (u >= 1)    accL += rsc[u-1]*part[128+u-1];
    if (u >= 2)    accL += rsc[u-2]*part[256+u-2];
    Vl[u] = tanhf(5.f*accL);
  } else if (t < 256) {
    int u = t - 128;
    float accR = gcc[u]*part[384+u];
    if (u+1 < 128) accR += gcc[u+1]*part[512+u];
    if (u+2 < 128) accR += gcc[u+2]*part[640+u];
    if (u >= 1)    accR += gcc[u-1]*part[512+u-1];
    if (u >= 2)    accR += gcc[u-2]*part[640+u-2];
    Vr[u] = tanhf(5.f*accR);
  }
  __syncthreads();

  // 9. GEMM2/3 via bf16 mma + blend epilogue
  {
    bool left = warp < 16;
    int gw = warp & 15;
    int u0 = (gw >> 1) * 16, nb = (gw & 1) * 32;
    const unsigned* Ah = left ? A2h : Ath;
    const unsigned* Al = left ? A2l : Atl;
    const unsigned* Bh = (const unsigned*)(sm + (left ? OFF_XRP_H : OFF_XLP_H));
    const unsigned* Bl = (const unsigned*)(sm + (left ? OFF_XRP_L : OFF_XLP_L));
    float d[4][4];
    #pragma unroll
    for (int j = 0; j < 4; j++)
      d[j][0] = d[j][1] = d[j][2] = d[j][3] = 0.f;
    for (int ks = 0; ks < 8; ks++) {
      int vp = ks*8 + tig;
      int ra = (u0+g)*A2ST + vp, rb = (u0+g+8)*A2ST + vp;
      unsigned ah0 = Ah[ra],   ah1 = Ah[rb];
      unsigned ah2 = Ah[ra+4], ah3 = Ah[rb+4];
      unsigned al0 = Al[ra],   al1 = Al[rb];
      unsigned al2 = Al[ra+4], al3 = Al[rb+4];
      #pragma unroll
      for (int j = 0; j < 4; j++) {
        int ci = (nb + j*8 + g)*XPST + vp;
        unsigned bh0 = Bh[ci], bh1 = Bh[ci+4];
        unsigned bl0 = Bl[ci], bl1 = Bl[ci+4];
        mma_bf16(d[j][0],d[j][1],d[j][2],d[j][3], al0,al1,al2,al3, bh0,bh1);
        mma_bf16(d[j][0],d[j][1],d[j][2],d[j][3], ah0,ah1,ah2,ah3, bl0,bl1);
        mma_bf16(d[j][0],d[j][1],d[j][2],d[j][3], ah0,ah1,ah2,ah3, bh0,bh1);
      }
    }
    const float* xg = left ? xL : xR;
    float* og = left ? outL : outR;
    const float* Vv = left ? Vl : Vr;
    const float* scv = left ? rsc : gcc;
    int ua = u0 + g, ub = u0 + g + 8;
    float va = Vv[ua], vb = Vv[ub];
    float sa = scv[ua]*va, sb2 = scv[ub]*vb;
    float ia = 1.f - va, ib = 1.f - vb;
    #pragma unroll
    for (int j = 0; j < 4; j++) {
      int c = nb + j*8 + 2*tig;
      size_t b0i = ((size_t)(b*NC + c)*NH + h)*NW;
      size_t b1i = b0i + (size_t)HW;
      og[b0i + ua] = xg[b0i + ua]*ia + d[j][0]*sa;
      og[b1i + ua] = xg[b1i + ua]*ia + d[j][1]*sa;
      og[b0i + ub] = xg[b0i + ub]*ib + d[j][2]*sb2;
      og[b1i + ub] = xg[b1i + ub]*ib + d[j][3]*sb2;
    }
  }
}

// ---------------- host ------------------------------------------------------
extern "C" void kernel_launch(void* const* d_in, const int* in_sizes, int n_in,
                              void* d_out, int out_size) {
  const float* xL    = (const float*)d_in[0];
  const float* xR    = (const float*)d_in[1];
  const float* gamma = (const float*)d_in[2];
  const float* beta  = (const float*)d_in[3];
  const float* w1    = (const float*)d_in[4];
  const float* b1    = (const float*)d_in[5];
  const float* w2    = (const float*)d_in[6];
  const float* b2    = (const float*)d_in[7];
  const float* qw    = (const float*)d_in[8];
  const float* qb    = (const float*)d_in[9];
  const float* kw    = (const float*)d_in[10];
  const float* kb    = (const float*)d_in[11];
  float* outL = (float*)d_out;
  float* outR = outL + (size_t)IMG;

  float *t1, *t2;
  unsigned *wth, *wtl;
  cudaGetSymbolAddress((void**)&t1, g_t1);
  cudaGetSymbolAddress((void**)&t2, g_t2);
  cudaGetSymbolAddress((void**)&wth, g_wth);
  cudaGetSymbolAddress((void**)&wtl, g_wtl);

  cudaFuncSetAttribute(conv3x3_kernel<true>,  cudaFuncAttributeMaxDynamicSharedMemorySize, CONV_SMEM);
  cudaFuncSetAttribute(conv3x3_kernel<false>, cudaFuncAttributeMaxDynamicSharedMemorySize, CONV_SMEM);
  cudaFuncSetAttribute(attn_kernel, cudaFuncAttributeMaxDynamicSharedMemorySize, ATTN_SMEM);

  bn_stats_kernel<<<128, 256>>>(xL, xR, gamma, beta);
  wtrans_kernel<<<(2*NG*9*16*8 + 255)/256, 256>>>(w1, w2);

  dim3 cgrid(NH/4, NB*NG, 2);
  conv3x3_kernel<true ><<<cgrid, 256, CONV_SMEM>>>(
      xL, xR, t1, t2, wth, wtl, b1);
  conv3x3_kernel<false><<<cgrid, 256, CONV_SMEM>>>(
      xL, xR, t1, t2, wth + 4608, wtl + 4608, b2);

  attn_kernel<<<NROW, 1024, ATTN_SMEM>>>(t2, xL, xR, qw, qb, kw, kb, outL, outR);
}